// round 1
// baseline (speedup 1.0000x reference)
#include <cuda_runtime.h>
#include <cuda_bf16.h>
#include <math.h>

// ---------------- problem constants ----------------
#define BATCH   32
#define NTOK    196          // 14*14
#define DMODEL  128
#define ROWS    (BATCH*NTOK) // 6272
#define PDIM    768          // 3*16*16
#define DEPTH   7
#define KNN_LAYER 6
#define MKEYS   8192
#define TOPK    32
#define FFH     512
#define NCLS    1000
#define SCALE   0.08838834764831845f   // 128^-0.5
#define LNEPS   1e-5f

// ---------------- device scratch (no allocations allowed) ----------------
__device__ float g_p   [ (long)ROWS*PDIM ];          // 19.3 MB
__device__ float g_h   [ (long)ROWS*DMODEL ];
__device__ float g_y   [ (long)ROWS*DMODEL ];
__device__ float g_qkv [ (long)ROWS*3*DMODEL ];
__device__ float g_att [ (long)BATCH*NTOK*NTOK ];
__device__ float g_msim[ (long)BATCH*NTOK*MKEYS ];   // 205 MB
__device__ float g_o   [ (long)ROWS*DMODEL ];
__device__ float g_ff  [ (long)ROWS*FFH ];
__device__ float g_mv  [ (long)ROWS*TOPK ];
__device__ int   g_mi  [ (long)ROWS*TOPK ];
__device__ float g_feats[ BATCH*DMODEL ];

// ---------------- helpers ----------------
__device__ __forceinline__ float gelu_tanh(float v) {
    const float c = 0.7978845608028654f;
    float t = tanhf(c * (v + 0.044715f * v * v * v));
    return 0.5f * v * (1.f + t);
}

// ---------------- patchify: x(32,3,224,224) -> p(6272,768) ----------------
__global__ void patchify_k(const float* __restrict__ x, float* __restrict__ p) {
    long e = (long)blockIdx.x * 256 + threadIdx.x;
    if (e >= (long)ROWS * PDIM) return;
    int c   = (int)(e % PDIM);
    long row = e / PDIM;
    int b = (int)(row / NTOK), n = (int)(row % NTOK);
    int i = n / 14, j = n % 14;
    int ch = c / 256, r = c % 256, pi = r / 16, pj = r % 16;
    p[e] = x[(((long)b*3 + ch)*224 + (i*16 + pi))*224 + (j*16 + pj)];
}

// ---------------- generic tiled GEMM ----------------
// C[bz] = alpha * A[bz] (op B[bz]) (+bias) (+res) (opt gelu)
// A: Mr x K (lda), B: K x Nc (ldb) or (TB) Nc x K (ldb), C: Mr x Nc (ldc)
#define BM 64
#define BN 64
#define BKT 16
template<bool TB, bool DOGELU>
__global__ void gemm_k(const float* __restrict__ A, const float* __restrict__ Bm,
                       const float* __restrict__ bias, const float* __restrict__ Res,
                       float* __restrict__ C,
                       int Mr, int Nc, int K,
                       long sAb, int lda, long sBb, int ldb, long sCb, int ldc,
                       float alpha)
{
    __shared__ float As[BKT][BM + 1];
    __shared__ float Bs[BKT][BN + 1];
    int bz = blockIdx.z;
    const float* Ab = A + (long)bz * sAb;
    const float* Bb = Bm + (long)bz * sBb;
    float*       Cb = C + (long)bz * sCb;
    const float* Rb = Res ? (Res + (long)bz * sCb) : nullptr;

    int row0 = blockIdx.y * BM;
    int col0 = blockIdx.x * BN;
    int tid = threadIdx.x;
    int tx = tid & 15, ty = tid >> 4;

    float acc[4][4] = {};

    for (int k0 = 0; k0 < K; k0 += BKT) {
        // load A tile (coalesced along k)
        #pragma unroll
        for (int t = tid; t < BM * BKT; t += 256) {
            int m = t / BKT, k = t % BKT;
            int gr = row0 + m, gk = k0 + k;
            float v = 0.f;
            if (gr < Mr && gk < K) v = Ab[(long)gr * lda + gk];
            As[k][m] = v;
        }
        // load B tile
        if (TB) {
            #pragma unroll
            for (int t = tid; t < BKT * BN; t += 256) {
                int n = t / BKT, k = t % BKT;
                int gn = col0 + n, gk = k0 + k;
                float v = 0.f;
                if (gn < Nc && gk < K) v = Bb[(long)gn * ldb + gk];
                Bs[k][n] = v;
            }
        } else {
            #pragma unroll
            for (int t = tid; t < BKT * BN; t += 256) {
                int k = t / BN, n = t % BN;
                int gn = col0 + n, gk = k0 + k;
                float v = 0.f;
                if (gn < Nc && gk < K) v = Bb[(long)gk * ldb + gn];
                Bs[k][n] = v;
            }
        }
        __syncthreads();
        #pragma unroll
        for (int kk = 0; kk < BKT; kk++) {
            float a[4], b[4];
            #pragma unroll
            for (int i = 0; i < 4; i++) a[i] = As[kk][ty * 4 + i];
            #pragma unroll
            for (int j = 0; j < 4; j++) b[j] = Bs[kk][tx * 4 + j];
            #pragma unroll
            for (int i = 0; i < 4; i++)
                #pragma unroll
                for (int j = 0; j < 4; j++)
                    acc[i][j] += a[i] * b[j];
        }
        __syncthreads();
    }

    #pragma unroll
    for (int i = 0; i < 4; i++) {
        int gr = row0 + ty * 4 + i;
        if (gr >= Mr) continue;
        #pragma unroll
        for (int j = 0; j < 4; j++) {
            int gn = col0 + tx * 4 + j;
            if (gn >= Nc) continue;
            float v = acc[i][j] * alpha;
            if (bias) v += bias[gn];
            if (Rb)   v += Rb[(long)gr * ldc + gn];
            if (DOGELU) v = gelu_tanh(v);
            Cb[(long)gr * ldc + gn] = v;
        }
    }
}

// ---------------- layernorm over D=128 ----------------
__global__ void ln_k(const float* __restrict__ in, const float* __restrict__ g,
                     const float* __restrict__ b, float* __restrict__ out)
{
    long row = blockIdx.x;
    int t = threadIdx.x;                 // 128 threads
    float v = in[row * DMODEL + t];
    __shared__ float red[4];
    float s = v;
    #pragma unroll
    for (int o = 16; o > 0; o >>= 1) s += __shfl_xor_sync(0xffffffffu, s, o);
    if ((t & 31) == 0) red[t >> 5] = s;
    __syncthreads();
    float mu = (red[0] + red[1] + red[2] + red[3]) * (1.f / 128.f);
    float d = v - mu;
    __syncthreads();
    float s2 = d * d;
    #pragma unroll
    for (int o = 16; o > 0; o >>= 1) s2 += __shfl_xor_sync(0xffffffffu, s2, o);
    if ((t & 31) == 0) red[t >> 5] = s2;
    __syncthreads();
    float var = (red[0] + red[1] + red[2] + red[3]) * (1.f / 128.f);
    out[row * DMODEL + t] = d / sqrtf(var + LNEPS) * g[t] + b[t];
}

// ---------------- softmax over 196 logits (row in-place) ----------------
__global__ void softmax196_k(float* __restrict__ att)
{
    long row = blockIdx.x;
    int t = threadIdx.x;                 // 256 threads
    float* a = att + row * NTOK;
    float v = (t < NTOK) ? a[t] : -3.4e38f;
    __shared__ float red[8];
    float m = v;
    #pragma unroll
    for (int o = 16; o > 0; o >>= 1) m = fmaxf(m, __shfl_xor_sync(0xffffffffu, m, o));
    if ((t & 31) == 0) red[t >> 5] = m;
    __syncthreads();
    m = red[0];
    #pragma unroll
    for (int i = 1; i < 8; i++) m = fmaxf(m, red[i]);
    float e = (t < NTOK) ? expf(v - m) : 0.f;
    __syncthreads();
    float s = e;
    #pragma unroll
    for (int o = 16; o > 0; o >>= 1) s += __shfl_xor_sync(0xffffffffu, s, o);
    if ((t & 31) == 0) red[t >> 5] = s;
    __syncthreads();
    s = red[0];
    #pragma unroll
    for (int i = 1; i < 8; i++) s += red[i];
    if (t < NTOK) a[t] = e / s;
}

// ---------------- top-32 of an 8192-row (iterative block argmax) ----------------
__global__ void topk_k(const float* __restrict__ msim,
                       float* __restrict__ mvals, int* __restrict__ midx)
{
    long row = blockIdx.x;
    int tid = threadIdx.x;               // 256 threads
    __shared__ float sv[MKEYS];          // 32 KB
    __shared__ float rmax[256];
    __shared__ int   rloc[256];
    const float* src = msim + row * MKEYS;
    for (int i = tid; i < MKEYS; i += 256) sv[i] = src[i];
    __syncthreads();
    for (int it = 0; it < TOPK; it++) {
        float best = -3.4e38f; int bi = MKEYS;
        for (int i = tid; i < MKEYS; i += 256) {
            float v = sv[i];
            if (v > best) { best = v; bi = i; }
        }
        rmax[tid] = best; rloc[tid] = bi;
        __syncthreads();
        for (int s = 128; s > 0; s >>= 1) {
            if (tid < s) {
                float ov = rmax[tid + s]; int oi = rloc[tid + s];
                if (ov > rmax[tid] || (ov == rmax[tid] && oi < rloc[tid])) {
                    rmax[tid] = ov; rloc[tid] = oi;
                }
            }
            __syncthreads();
        }
        if (tid == 0) {
            mvals[row * TOPK + it] = rmax[0];
            midx [row * TOPK + it] = rloc[0];
            sv[rloc[0]] = -3.4e38f;
        }
        __syncthreads();
    }
}

// ---------------- kNN layer: softmax(concat[32 mem, 196 local]) + weighted sums ----------------
__global__ void knn_combine_k(const float* __restrict__ att,
                              const float* __restrict__ mvals, const int* __restrict__ midx,
                              const float* __restrict__ qkv, const float* __restrict__ knn_v,
                              float* __restrict__ out)
{
    long row = blockIdx.x;
    int b = (int)(row / NTOK);
    int tid = threadIdx.x;               // 128 threads (= D)
    __shared__ float w[TOPK + NTOK];     // 228 logits -> probs
    __shared__ int   sidx[TOPK];
    __shared__ float red[4];

    if (tid < TOPK) {
        w[tid]    = mvals[row * TOPK + tid];
        sidx[tid] = midx [row * TOPK + tid];
    }
    for (int m = tid; m < NTOK; m += 128) w[TOPK + m] = att[row * NTOK + m];
    __syncthreads();

    float l0 = w[tid];
    float l1 = (tid < (TOPK + NTOK - 128)) ? w[tid + 128] : -3.4e38f;
    float m = fmaxf(l0, l1);
    #pragma unroll
    for (int o = 16; o > 0; o >>= 1) m = fmaxf(m, __shfl_xor_sync(0xffffffffu, m, o));
    if ((tid & 31) == 0) red[tid >> 5] = m;
    __syncthreads();
    m = fmaxf(fmaxf(red[0], red[1]), fmaxf(red[2], red[3]));
    float e0 = expf(l0 - m);
    float e1 = (tid < (TOPK + NTOK - 128)) ? expf(l1 - m) : 0.f;
    float s = e0 + e1;
    __syncthreads();
    #pragma unroll
    for (int o = 16; o > 0; o >>= 1) s += __shfl_xor_sync(0xffffffffu, s, o);
    if ((tid & 31) == 0) red[tid >> 5] = s;
    __syncthreads();
    s = red[0] + red[1] + red[2] + red[3];
    float inv = 1.f / s;
    w[tid] = e0 * inv;
    if (tid < (TOPK + NTOK - 128)) w[tid + 128] = e1 * inv;
    __syncthreads();

    // out[d] = sum_j w[j]*knn_v[b,idx_j,d] + sum_m w[32+m]*v[b,m,d]
    float acc = 0.f;
    const float* kv = knn_v + (long)b * MKEYS * DMODEL;
    #pragma unroll 4
    for (int j = 0; j < TOPK; j++)
        acc += w[j] * kv[(long)sidx[j] * DMODEL + tid];
    const float* vbase = qkv + ((long)b * NTOK) * 384 + 256;
    for (int mm = 0; mm < NTOK; mm++)
        acc += w[TOPK + mm] * vbase[(long)mm * 384 + tid];
    out[row * DMODEL + tid] = acc;
}

// ---------------- mean pool over tokens ----------------
__global__ void mean_k(const float* __restrict__ y, float* __restrict__ feats)
{
    int b = blockIdx.x, d = threadIdx.x;
    float s = 0.f;
    for (int n = 0; n < NTOK; n++) s += y[((long)b * NTOK + n) * DMODEL + d];
    feats[b * DMODEL + d] = s * (1.f / 196.f);
}

// ---------------- launch ----------------
extern "C" void kernel_launch(void* const* d_in, const int* in_sizes, int n_in,
                              void* d_out, int out_size)
{
    const float* x       = (const float*)d_in[0];
    const float* patch_w = (const float*)d_in[1];
    const float* patch_b = (const float*)d_in[2];
    const float* ln1_g   = (const float*)d_in[3];
    const float* ln1_b   = (const float*)d_in[4];
    const float* qkv_w   = (const float*)d_in[5];
    const float* qkv_b   = (const float*)d_in[6];
    const float* out_w   = (const float*)d_in[7];
    const float* out_b   = (const float*)d_in[8];
    const float* ln2_g   = (const float*)d_in[9];
    const float* ln2_b   = (const float*)d_in[10];
    const float* ff1_w   = (const float*)d_in[11];
    const float* ff1_b   = (const float*)d_in[12];
    const float* ff2_w   = (const float*)d_in[13];
    const float* ff2_b   = (const float*)d_in[14];
    const float* lnf_g   = (const float*)d_in[15];
    const float* lnf_b   = (const float*)d_in[16];
    const float* knn_k   = (const float*)d_in[17];
    const float* knn_v   = (const float*)d_in[18];
    const float* head_w  = (const float*)d_in[19];
    const float* head_b  = (const float*)d_in[20];
    float* out = (float*)d_out;

    void* tp;
    cudaGetSymbolAddress(&tp, g_p);    float* pP    = (float*)tp;
    cudaGetSymbolAddress(&tp, g_h);    float* pH    = (float*)tp;
    cudaGetSymbolAddress(&tp, g_y);    float* pY    = (float*)tp;
    cudaGetSymbolAddress(&tp, g_qkv);  float* pQKV  = (float*)tp;
    cudaGetSymbolAddress(&tp, g_att);  float* pATT  = (float*)tp;
    cudaGetSymbolAddress(&tp, g_msim); float* pMSIM = (float*)tp;
    cudaGetSymbolAddress(&tp, g_o);    float* pO    = (float*)tp;
    cudaGetSymbolAddress(&tp, g_ff);   float* pFF   = (float*)tp;
    cudaGetSymbolAddress(&tp, g_mv);   float* pMV   = (float*)tp;
    cudaGetSymbolAddress(&tp, g_mi);   int*   pMI   = (int*)tp;
    cudaGetSymbolAddress(&tp, g_feats);float* pFeat = (float*)tp;

    // patch embed
    patchify_k<<<(int)(((long)ROWS * PDIM + 255) / 256), 256>>>(x, pP);
    gemm_k<false,false><<<dim3(2, 98, 1), 256>>>(pP, patch_w, patch_b, nullptr, pH,
        ROWS, DMODEL, PDIM, 0, PDIM, 0, DMODEL, 0, DMODEL, 1.f);

    for (int i = 0; i < DEPTH; i++) {
        ln_k<<<ROWS, 128>>>(pH, ln1_g + i * DMODEL, ln1_b + i * DMODEL, pY);
        gemm_k<false,false><<<dim3(6, 98, 1), 256>>>(pY, qkv_w + (long)i * DMODEL * 3 * DMODEL,
            qkv_b + i * 3 * DMODEL, nullptr, pQKV,
            ROWS, 3 * DMODEL, DMODEL, 0, DMODEL, 0, 3 * DMODEL, 0, 3 * DMODEL, 1.f);
        // sim = q @ k^T * scale   (batched NT)
        gemm_k<true,false><<<dim3(4, 4, BATCH), 256>>>(pQKV, pQKV + 128, nullptr, nullptr, pATT,
            NTOK, NTOK, DMODEL,
            (long)NTOK * 384, 384, (long)NTOK * 384, 384, (long)NTOK * NTOK, NTOK, SCALE);

        if (i == KNN_LAYER) {
            // msim = q @ knn_k^T * scale  (batched NT, N=8192)
            gemm_k<true,false><<<dim3(128, 4, BATCH), 256>>>(pQKV, knn_k, nullptr, nullptr, pMSIM,
                NTOK, MKEYS, DMODEL,
                (long)NTOK * 384, 384, (long)MKEYS * DMODEL, DMODEL, (long)NTOK * MKEYS, MKEYS, SCALE);
            topk_k<<<ROWS, 256>>>(pMSIM, pMV, pMI);
            knn_combine_k<<<ROWS, 128>>>(pATT, pMV, pMI, pQKV, knn_v, pO);
        } else {
            softmax196_k<<<ROWS, 256>>>(pATT);
            // o = attn @ v (batched NN, K=196)
            gemm_k<false,false><<<dim3(2, 4, BATCH), 256>>>(pATT, pQKV + 256, nullptr, nullptr, pO,
                NTOK, DMODEL, NTOK,
                (long)NTOK * NTOK, NTOK, (long)NTOK * 384, 384, (long)NTOK * DMODEL, DMODEL, 1.f);
        }

        // h = h + o @ out_w + out_b
        gemm_k<false,false><<<dim3(2, 98, 1), 256>>>(pO, out_w + (long)i * DMODEL * DMODEL,
            out_b + i * DMODEL, pH, pH,
            ROWS, DMODEL, DMODEL, 0, DMODEL, 0, DMODEL, 0, DMODEL, 1.f);

        ln_k<<<ROWS, 128>>>(pH, ln2_g + i * DMODEL, ln2_b + i * DMODEL, pY);
        // ff1 + gelu
        gemm_k<false,true><<<dim3(8, 98, 1), 256>>>(pY, ff1_w + (long)i * DMODEL * FFH,
            ff1_b + i * FFH, nullptr, pFF,
            ROWS, FFH, DMODEL, 0, DMODEL, 0, FFH, 0, FFH, 1.f);
        // h = h + ff @ ff2_w + ff2_b
        gemm_k<false,false><<<dim3(2, 98, 1), 256>>>(pFF, ff2_w + (long)i * FFH * DMODEL,
            ff2_b + i * DMODEL, pH, pH,
            ROWS, DMODEL, FFH, 0, FFH, 0, DMODEL, 0, DMODEL, 1.f);
    }

    ln_k<<<ROWS, 128>>>(pH, lnf_g, lnf_b, pY);
    mean_k<<<BATCH, 128>>>(pY, pFeat);
    gemm_k<false,false><<<dim3(16, 1, 1), 256>>>(pFeat, head_w, head_b, nullptr, out,
        BATCH, NCLS, DMODEL, 0, DMODEL, 0, NCLS, 0, NCLS, 1.f);
}

// round 2
// speedup vs baseline: 1.3634x; 1.3634x over previous
#include <cuda_runtime.h>
#include <cuda_bf16.h>
#include <math.h>

// ---------------- problem constants ----------------
#define BATCH   32
#define NTOK    196          // 14*14
#define DMODEL  128
#define ROWS    (BATCH*NTOK) // 6272
#define PDIM    768          // 3*16*16
#define DEPTH   7
#define KNN_LAYER 6
#define MKEYS   8192
#define TOPK    32
#define FFH     512
#define NCLS    1000
#define SCALE   0.08838834764831845f   // 128^-0.5
#define LNEPS   1e-5f

// ---------------- device scratch (no allocations allowed) ----------------
__device__ float g_p   [ (long)ROWS*PDIM ];
__device__ float g_h   [ (long)ROWS*DMODEL ];
__device__ float g_y   [ (long)ROWS*DMODEL ];
__device__ float g_qkv [ (long)ROWS*3*DMODEL ];
__device__ float g_att [ (long)BATCH*NTOK*NTOK ];
__device__ float g_msim[ (long)BATCH*NTOK*MKEYS ];
__device__ float g_o   [ (long)ROWS*DMODEL ];
__device__ float g_ff  [ (long)ROWS*FFH ];
__device__ float g_mv  [ (long)ROWS*TOPK ];
__device__ int   g_mi  [ (long)ROWS*TOPK ];
__device__ float g_feats[ BATCH*DMODEL ];

// ---------------- helpers ----------------
__device__ __forceinline__ float gelu_tanh(float v) {
    const float c = 0.7978845608028654f;
    float t = tanhf(c * (v + 0.044715f * v * v * v));
    return 0.5f * v * (1.f + t);
}
__device__ __forceinline__ unsigned f2tf32(float f) {
    unsigned u;
    asm("cvt.rna.tf32.f32 %0, %1;" : "=r"(u) : "f"(f));
    return u;
}

// ---------------- patchify: x(32,3,224,224) -> p(6272,768) ----------------
__global__ void patchify_k(const float* __restrict__ x, float* __restrict__ p) {
    long e = (long)blockIdx.x * 256 + threadIdx.x;
    if (e >= (long)ROWS * PDIM) return;
    int c   = (int)(e % PDIM);
    long row = e / PDIM;
    int b = (int)(row / NTOK), n = (int)(row % NTOK);
    int i = n / 14, j = n % 14;
    int ch = c / 256, r = c % 256, pi = r / 16, pj = r % 16;
    p[e] = x[(((long)b*3 + ch)*224 + (i*16 + pi))*224 + (j*16 + pj)];
}

// ---------------- SIMT GEMM v2: 128x128 tile, BK=8, 8x8 microtile ----------------
// C[bz] = alpha * A[bz] (op B[bz]) (+bias) (+res) (opt gelu)
template<bool TB, bool DOGELU>
__global__ void gemm2_k(const float* __restrict__ A, const float* __restrict__ Bm,
                        const float* __restrict__ bias, const float* __restrict__ Res,
                        float* __restrict__ C,
                        int Mr, int Nc, int K,
                        long sAb, int lda, long sBb, int ldb, long sCb, int ldc,
                        float alpha)
{
    __shared__ float As[8][132];
    __shared__ float Bs[8][132];
    int bz = blockIdx.z;
    const float* Ab = A + (long)bz * sAb;
    const float* Bb = Bm + (long)bz * sBb;
    float*       Cb = C + (long)bz * sCb;
    const float* Rb = Res ? (Res + (long)bz * sCb) : nullptr;

    int row0 = blockIdx.y * 128;
    int col0 = blockIdx.x * 128;
    int tid = threadIdx.x;
    int tx = tid & 15, ty = tid >> 4;

    // load-index precompute
    int m_a = tid >> 1, ka = (tid & 1) * 4;           // A tile: 128 rows x 8 (two float4 cols halves)
    int kb = tid >> 5, nb = (tid & 31) * 4;           // B tile (NN): 8 rows x 128
    int n_b = tid >> 1, kb2 = (tid & 1) * 4;          // B tile (TB): 128 rows x 8

    float acc[8][8];
    #pragma unroll
    for (int i = 0; i < 8; i++)
        #pragma unroll
        for (int j = 0; j < 8; j++) acc[i][j] = 0.f;

    for (int k0 = 0; k0 < K; k0 += 8) {
        // ---- load A tile -> As[k][m]
        {
            int gr = row0 + m_a, gk = k0 + ka;
            float4 v = make_float4(0.f, 0.f, 0.f, 0.f);
            if (gr < Mr) {
                if (gk + 3 < K) {
                    v = *(const float4*)&Ab[(long)gr * lda + gk];
                } else {
                    float t0 = (gk + 0 < K) ? Ab[(long)gr * lda + gk + 0] : 0.f;
                    float t1 = (gk + 1 < K) ? Ab[(long)gr * lda + gk + 1] : 0.f;
                    float t2 = (gk + 2 < K) ? Ab[(long)gr * lda + gk + 2] : 0.f;
                    float t3 = (gk + 3 < K) ? Ab[(long)gr * lda + gk + 3] : 0.f;
                    v = make_float4(t0, t1, t2, t3);
                }
            }
            As[ka + 0][m_a] = v.x; As[ka + 1][m_a] = v.y;
            As[ka + 2][m_a] = v.z; As[ka + 3][m_a] = v.w;
        }
        // ---- load B tile -> Bs[k][n]
        if (TB) {
            int gn = col0 + n_b, gk = k0 + kb2;
            float4 v = make_float4(0.f, 0.f, 0.f, 0.f);
            if (gn < Nc) {
                if (gk + 3 < K) {
                    v = *(const float4*)&Bb[(long)gn * ldb + gk];
                } else {
                    float t0 = (gk + 0 < K) ? Bb[(long)gn * ldb + gk + 0] : 0.f;
                    float t1 = (gk + 1 < K) ? Bb[(long)gn * ldb + gk + 1] : 0.f;
                    float t2 = (gk + 2 < K) ? Bb[(long)gn * ldb + gk + 2] : 0.f;
                    float t3 = (gk + 3 < K) ? Bb[(long)gn * ldb + gk + 3] : 0.f;
                    v = make_float4(t0, t1, t2, t3);
                }
            }
            Bs[kb2 + 0][n_b] = v.x; Bs[kb2 + 1][n_b] = v.y;
            Bs[kb2 + 2][n_b] = v.z; Bs[kb2 + 3][n_b] = v.w;
        } else {
            int gk = k0 + kb, gn = col0 + nb;
            float4 v = make_float4(0.f, 0.f, 0.f, 0.f);
            if (gk < K) {
                if (gn + 3 < Nc) {
                    v = *(const float4*)&Bb[(long)gk * ldb + gn];
                } else {
                    float t0 = (gn + 0 < Nc) ? Bb[(long)gk * ldb + gn + 0] : 0.f;
                    float t1 = (gn + 1 < Nc) ? Bb[(long)gk * ldb + gn + 1] : 0.f;
                    float t2 = (gn + 2 < Nc) ? Bb[(long)gk * ldb + gn + 2] : 0.f;
                    float t3 = (gn + 3 < Nc) ? Bb[(long)gk * ldb + gn + 3] : 0.f;
                    v = make_float4(t0, t1, t2, t3);
                }
            }
            *(float4*)&Bs[kb][nb] = v;
        }
        __syncthreads();

        #pragma unroll
        for (int kk = 0; kk < 8; kk++) {
            float4 a0 = *(float4*)&As[kk][ty * 4];
            float4 a1 = *(float4*)&As[kk][64 + ty * 4];
            float4 b0 = *(float4*)&Bs[kk][tx * 4];
            float4 b1 = *(float4*)&Bs[kk][64 + tx * 4];
            float a[8] = {a0.x, a0.y, a0.z, a0.w, a1.x, a1.y, a1.z, a1.w};
            float b[8] = {b0.x, b0.y, b0.z, b0.w, b1.x, b1.y, b1.z, b1.w};
            #pragma unroll
            for (int i = 0; i < 8; i++)
                #pragma unroll
                for (int j = 0; j < 8; j++)
                    acc[i][j] += a[i] * b[j];
        }
        __syncthreads();
    }

    #pragma unroll
    for (int i = 0; i < 8; i++) {
        int gr = row0 + ((i < 4) ? (ty * 4 + i) : (64 + ty * 4 + i - 4));
        if (gr >= Mr) continue;
        #pragma unroll
        for (int j = 0; j < 8; j++) {
            int gn = col0 + ((j < 4) ? (tx * 4 + j) : (64 + tx * 4 + j - 4));
            if (gn >= Nc) continue;
            float v = acc[i][j] * alpha;
            if (bias) v += bias[gn];
            if (Rb)   v += Rb[(long)gr * ldc + gn];
            if (DOGELU) v = gelu_tanh(v);
            Cb[(long)gr * ldc + gn] = v;
        }
    }
}

// ---------------- msim = q @ knn_k^T * SCALE via tf32 mma.sync ----------------
// grid: (MKEYS/128, ceil(196/64)=4, BATCH), 256 threads (8 warps, 2x4 of 32x32)
__global__ void msim_mma_k(const float* __restrict__ qkv, const float* __restrict__ knnk,
                           float* __restrict__ msim)
{
    __shared__ unsigned As[64][36];
    __shared__ unsigned Bs[128][36];
    int b = blockIdx.z;
    int row0 = blockIdx.y * 64;
    int n0 = blockIdx.x * 128;
    int tid = threadIdx.x;
    int lane = tid & 31, warp = tid >> 5;
    int wm = warp >> 2, wn = warp & 3;   // 2 x 4 warps, each 32x32
    const float* Aq = qkv + (long)b * NTOK * 384;          // q at offset 0, stride 384
    const float* Bk = knnk + (long)b * MKEYS * DMODEL;

    float acc[2][4][4];
    #pragma unroll
    for (int im = 0; im < 2; im++)
        #pragma unroll
        for (int jn = 0; jn < 4; jn++)
            #pragma unroll
            for (int c = 0; c < 4; c++) acc[im][jn][c] = 0.f;

    for (int k0 = 0; k0 < 128; k0 += 32) {
        // A: 64 rows x 32 cols
        #pragma unroll
        for (int p = 0; p < 2; p++) {
            int r = tid >> 2;
            int kk4 = ((tid & 3) + p * 4) * 4;
            float4 v = make_float4(0.f, 0.f, 0.f, 0.f);
            int gr = row0 + r;
            if (gr < NTOK) v = *(const float4*)&Aq[(long)gr * 384 + k0 + kk4];
            As[r][kk4 + 0] = f2tf32(v.x); As[r][kk4 + 1] = f2tf32(v.y);
            As[r][kk4 + 2] = f2tf32(v.z); As[r][kk4 + 3] = f2tf32(v.w);
        }
        // B: 128 rows x 32 cols
        #pragma unroll
        for (int p = 0; p < 4; p++) {
            int n = (tid >> 3) + p * 32;
            int kk4 = (tid & 7) * 4;
            float4 v = *(const float4*)&Bk[(long)(n0 + n) * DMODEL + k0 + kk4];
            Bs[n][kk4 + 0] = f2tf32(v.x); Bs[n][kk4 + 1] = f2tf32(v.y);
            Bs[n][kk4 + 2] = f2tf32(v.z); Bs[n][kk4 + 3] = f2tf32(v.w);
        }
        __syncthreads();

        #pragma unroll
        for (int ks = 0; ks < 32; ks += 8) {
            unsigned afr[2][4], bfr[4][2];
            #pragma unroll
            for (int im = 0; im < 2; im++) {
                int mb = wm * 32 + im * 16;
                afr[im][0] = As[mb + (lane >> 2)    ][ks +     (lane & 3)];
                afr[im][1] = As[mb + (lane >> 2) + 8][ks +     (lane & 3)];
                afr[im][2] = As[mb + (lane >> 2)    ][ks + 4 + (lane & 3)];
                afr[im][3] = As[mb + (lane >> 2) + 8][ks + 4 + (lane & 3)];
            }
            #pragma unroll
            for (int jn = 0; jn < 4; jn++) {
                int nb = wn * 32 + jn * 8;
                bfr[jn][0] = Bs[nb + (lane >> 2)][ks +     (lane & 3)];
                bfr[jn][1] = Bs[nb + (lane >> 2)][ks + 4 + (lane & 3)];
            }
            #pragma unroll
            for (int im = 0; im < 2; im++)
                #pragma unroll
                for (int jn = 0; jn < 4; jn++) {
                    asm volatile(
                        "mma.sync.aligned.m16n8k8.row.col.f32.tf32.tf32.f32 "
                        "{%0,%1,%2,%3}, {%4,%5,%6,%7}, {%8,%9}, {%0,%1,%2,%3};"
                        : "+f"(acc[im][jn][0]), "+f"(acc[im][jn][1]),
                          "+f"(acc[im][jn][2]), "+f"(acc[im][jn][3])
                        : "r"(afr[im][0]), "r"(afr[im][1]), "r"(afr[im][2]), "r"(afr[im][3]),
                          "r"(bfr[jn][0]), "r"(bfr[jn][1]));
                }
        }
        __syncthreads();
    }

    // epilogue: write acc * SCALE
    float* out = msim + (long)b * NTOK * MKEYS;
    #pragma unroll
    for (int im = 0; im < 2; im++) {
        #pragma unroll
        for (int jn = 0; jn < 4; jn++) {
            int r0 = row0 + wm * 32 + im * 16 + (lane >> 2);
            int c0 = n0 + wn * 32 + jn * 8 + 2 * (lane & 3);
            if (r0 < NTOK) {
                out[(long)r0 * MKEYS + c0    ] = acc[im][jn][0] * SCALE;
                out[(long)r0 * MKEYS + c0 + 1] = acc[im][jn][1] * SCALE;
            }
            int r1 = r0 + 8;
            if (r1 < NTOK) {
                out[(long)r1 * MKEYS + c0    ] = acc[im][jn][2] * SCALE;
                out[(long)r1 * MKEYS + c0 + 1] = acc[im][jn][3] * SCALE;
            }
        }
    }
}

// ---------------- layernorm over D=128 ----------------
__global__ void ln_k(const float* __restrict__ in, const float* __restrict__ g,
                     const float* __restrict__ b, float* __restrict__ out)
{
    long row = blockIdx.x;
    int t = threadIdx.x;                 // 128 threads
    float v = in[row * DMODEL + t];
    __shared__ float red[4];
    float s = v;
    #pragma unroll
    for (int o = 16; o > 0; o >>= 1) s += __shfl_xor_sync(0xffffffffu, s, o);
    if ((t & 31) == 0) red[t >> 5] = s;
    __syncthreads();
    float mu = (red[0] + red[1] + red[2] + red[3]) * (1.f / 128.f);
    float d = v - mu;
    __syncthreads();
    float s2 = d * d;
    #pragma unroll
    for (int o = 16; o > 0; o >>= 1) s2 += __shfl_xor_sync(0xffffffffu, s2, o);
    if ((t & 31) == 0) red[t >> 5] = s2;
    __syncthreads();
    float var = (red[0] + red[1] + red[2] + red[3]) * (1.f / 128.f);
    out[row * DMODEL + t] = d / sqrtf(var + LNEPS) * g[t] + b[t];
}

// ---------------- softmax over 196 logits (row in-place) ----------------
__global__ void softmax196_k(float* __restrict__ att)
{
    long row = blockIdx.x;
    int t = threadIdx.x;                 // 256 threads
    float* a = att + row * NTOK;
    float v = (t < NTOK) ? a[t] : -3.4e38f;
    __shared__ float red[8];
    float m = v;
    #pragma unroll
    for (int o = 16; o > 0; o >>= 1) m = fmaxf(m, __shfl_xor_sync(0xffffffffu, m, o));
    if ((t & 31) == 0) red[t >> 5] = m;
    __syncthreads();
    m = red[0];
    #pragma unroll
    for (int i = 1; i < 8; i++) m = fmaxf(m, red[i]);
    float e = (t < NTOK) ? expf(v - m) : 0.f;
    __syncthreads();
    float s = e;
    #pragma unroll
    for (int o = 16; o > 0; o >>= 1) s += __shfl_xor_sync(0xffffffffu, s, o);
    if ((t & 31) == 0) red[t >> 5] = s;
    __syncthreads();
    s = red[0];
    #pragma unroll
    for (int i = 1; i < 8; i++) s += red[i];
    if (t < NTOK) a[t] = e / s;
}

// ---------------- top-32 of an 8192-row (iterative block argmax) ----------------
__global__ void topk_k(const float* __restrict__ msim,
                       float* __restrict__ mvals, int* __restrict__ midx)
{
    long row = blockIdx.x;
    int tid = threadIdx.x;               // 256 threads
    __shared__ float sv[MKEYS];          // 32 KB
    __shared__ float rmax[256];
    __shared__ int   rloc[256];
    const float* src = msim + row * MKEYS;
    for (int i = tid; i < MKEYS; i += 256) sv[i] = src[i];
    __syncthreads();
    for (int it = 0; it < TOPK; it++) {
        float best = -3.4e38f; int bi = MKEYS;
        for (int i = tid; i < MKEYS; i += 256) {
            float v = sv[i];
            if (v > best) { best = v; bi = i; }
        }
        rmax[tid] = best; rloc[tid] = bi;
        __syncthreads();
        for (int s = 128; s > 0; s >>= 1) {
            if (tid < s) {
                float ov = rmax[tid + s]; int oi = rloc[tid + s];
                if (ov > rmax[tid] || (ov == rmax[tid] && oi < rloc[tid])) {
                    rmax[tid] = ov; rloc[tid] = oi;
                }
            }
            __syncthreads();
        }
        if (tid == 0) {
            mvals[row * TOPK + it] = rmax[0];
            midx [row * TOPK + it] = rloc[0];
            sv[rloc[0]] = -3.4e38f;
        }
        __syncthreads();
    }
}

// ---------------- kNN layer: softmax(concat[32 mem, 196 local]) + weighted sums ----------------
__global__ void knn_combine_k(const float* __restrict__ att,
                              const float* __restrict__ mvals, const int* __restrict__ midx,
                              const float* __restrict__ qkv, const float* __restrict__ knn_v,
                              float* __restrict__ out)
{
    long row = blockIdx.x;
    int b = (int)(row / NTOK);
    int tid = threadIdx.x;               // 128 threads (= D)
    __shared__ float w[TOPK + NTOK];     // 228 logits -> probs
    __shared__ int   sidx[TOPK];
    __shared__ float red[4];

    if (tid < TOPK) {
        w[tid]    = mvals[row * TOPK + tid];
        sidx[tid] = midx [row * TOPK + tid];
    }
    for (int m = tid; m < NTOK; m += 128) w[TOPK + m] = att[row * NTOK + m];
    __syncthreads();

    float l0 = w[tid];
    float l1 = (tid < (TOPK + NTOK - 128)) ? w[tid + 128] : -3.4e38f;
    float m = fmaxf(l0, l1);
    #pragma unroll
    for (int o = 16; o > 0; o >>= 1) m = fmaxf(m, __shfl_xor_sync(0xffffffffu, m, o));
    if ((tid & 31) == 0) red[tid >> 5] = m;
    __syncthreads();
    m = fmaxf(fmaxf(red[0], red[1]), fmaxf(red[2], red[3]));
    float e0 = expf(l0 - m);
    float e1 = (tid < (TOPK + NTOK - 128)) ? expf(l1 - m) : 0.f;
    float s = e0 + e1;
    __syncthreads();
    #pragma unroll
    for (int o = 16; o > 0; o >>= 1) s += __shfl_xor_sync(0xffffffffu, s, o);
    if ((tid & 31) == 0) red[tid >> 5] = s;
    __syncthreads();
    s = red[0] + red[1] + red[2] + red[3];
    float inv = 1.f / s;
    w[tid] = e0 * inv;
    if (tid < (TOPK + NTOK - 128)) w[tid + 128] = e1 * inv;
    __syncthreads();

    float acc = 0.f;
    const float* kv = knn_v + (long)b * MKEYS * DMODEL;
    #pragma unroll 4
    for (int j = 0; j < TOPK; j++)
        acc += w[j] * kv[(long)sidx[j] * DMODEL + tid];
    const float* vbase = qkv + ((long)b * NTOK) * 384 + 256;
    for (int mm = 0; mm < NTOK; mm++)
        acc += w[TOPK + mm] * vbase[(long)mm * 384 + tid];
    out[row * DMODEL + tid] = acc;
}

// ---------------- mean pool over tokens ----------------
__global__ void mean_k(const float* __restrict__ y, float* __restrict__ feats)
{
    int b = blockIdx.x, d = threadIdx.x;
    float s = 0.f;
    for (int n = 0; n < NTOK; n++) s += y[((long)b * NTOK + n) * DMODEL + d];
    feats[b * DMODEL + d] = s * (1.f / 196.f);
}

// ---------------- launch ----------------
extern "C" void kernel_launch(void* const* d_in, const int* in_sizes, int n_in,
                              void* d_out, int out_size)
{
    const float* x       = (const float*)d_in[0];
    const float* patch_w = (const float*)d_in[1];
    const float* patch_b = (const float*)d_in[2];
    const float* ln1_g   = (const float*)d_in[3];
    const float* ln1_b   = (const float*)d_in[4];
    const float* qkv_w   = (const float*)d_in[5];
    const float* qkv_b   = (const float*)d_in[6];
    const float* out_w   = (const float*)d_in[7];
    const float* out_b   = (const float*)d_in[8];
    const float* ln2_g   = (const float*)d_in[9];
    const float* ln2_b   = (const float*)d_in[10];
    const float* ff1_w   = (const float*)d_in[11];
    const float* ff1_b   = (const float*)d_in[12];
    const float* ff2_w   = (const float*)d_in[13];
    const float* ff2_b   = (const float*)d_in[14];
    const float* lnf_g   = (const float*)d_in[15];
    const float* lnf_b   = (const float*)d_in[16];
    const float* knn_k   = (const float*)d_in[17];
    const float* knn_v   = (const float*)d_in[18];
    const float* head_w  = (const float*)d_in[19];
    const float* head_b  = (const float*)d_in[20];
    float* out = (float*)d_out;

    void* tp;
    cudaGetSymbolAddress(&tp, g_p);    float* pP    = (float*)tp;
    cudaGetSymbolAddress(&tp, g_h);    float* pH    = (float*)tp;
    cudaGetSymbolAddress(&tp, g_y);    float* pY    = (float*)tp;
    cudaGetSymbolAddress(&tp, g_qkv);  float* pQKV  = (float*)tp;
    cudaGetSymbolAddress(&tp, g_att);  float* pATT  = (float*)tp;
    cudaGetSymbolAddress(&tp, g_msim); float* pMSIM = (float*)tp;
    cudaGetSymbolAddress(&tp, g_o);    float* pO    = (float*)tp;
    cudaGetSymbolAddress(&tp, g_ff);   float* pFF   = (float*)tp;
    cudaGetSymbolAddress(&tp, g_mv);   float* pMV   = (float*)tp;
    cudaGetSymbolAddress(&tp, g_mi);   int*   pMI   = (int*)tp;
    cudaGetSymbolAddress(&tp, g_feats);float* pFeat = (float*)tp;

    // patch embed
    patchify_k<<<(int)(((long)ROWS * PDIM + 255) / 256), 256>>>(x, pP);
    gemm2_k<false,false><<<dim3(1, 49, 1), 256>>>(pP, patch_w, patch_b, nullptr, pH,
        ROWS, DMODEL, PDIM, 0, PDIM, 0, DMODEL, 0, DMODEL, 1.f);

    for (int i = 0; i < DEPTH; i++) {
        ln_k<<<ROWS, 128>>>(pH, ln1_g + i * DMODEL, ln1_b + i * DMODEL, pY);
        gemm2_k<false,false><<<dim3(3, 49, 1), 256>>>(pY, qkv_w + (long)i * DMODEL * 3 * DMODEL,
            qkv_b + i * 3 * DMODEL, nullptr, pQKV,
            ROWS, 3 * DMODEL, DMODEL, 0, DMODEL, 0, 3 * DMODEL, 0, 3 * DMODEL, 1.f);
        // sim = q @ k^T * scale   (batched NT)
        gemm2_k<true,false><<<dim3(2, 2, BATCH), 256>>>(pQKV, pQKV + 128, nullptr, nullptr, pATT,
            NTOK, NTOK, DMODEL,
            (long)NTOK * 384, 384, (long)NTOK * 384, 384, (long)NTOK * NTOK, NTOK, SCALE);

        if (i == KNN_LAYER) {
            msim_mma_k<<<dim3(MKEYS / 128, 4, BATCH), 256>>>(pQKV, knn_k, pMSIM);
            topk_k<<<ROWS, 256>>>(pMSIM, pMV, pMI);
            knn_combine_k<<<ROWS, 128>>>(pATT, pMV, pMI, pQKV, knn_v, pO);
        } else {
            softmax196_k<<<ROWS, 256>>>(pATT);
            // o = attn @ v (batched NN, K=196)
            gemm2_k<false,false><<<dim3(1, 2, BATCH), 256>>>(pATT, pQKV + 256, nullptr, nullptr, pO,
                NTOK, DMODEL, NTOK,
                (long)NTOK * NTOK, NTOK, (long)NTOK * 384, 384, (long)NTOK * DMODEL, DMODEL, 1.f);
        }

        // h = h + o @ out_w + out_b
        gemm2_k<false,false><<<dim3(1, 49, 1), 256>>>(pO, out_w + (long)i * DMODEL * DMODEL,
            out_b + i * DMODEL, pH, pH,
            ROWS, DMODEL, DMODEL, 0, DMODEL, 0, DMODEL, 0, DMODEL, 1.f);

        ln_k<<<ROWS, 128>>>(pH, ln2_g + i * DMODEL, ln2_b + i * DMODEL, pY);
        // ff1 + gelu
        gemm2_k<false,true><<<dim3(4, 49, 1), 256>>>(pY, ff1_w + (long)i * DMODEL * FFH,
            ff1_b + i * FFH, nullptr, pFF,
            ROWS, FFH, DMODEL, 0, DMODEL, 0, FFH, 0, FFH, 1.f);
        // h = h + ff @ ff2_w + ff2_b
        gemm2_k<false,false><<<dim3(1, 49, 1), 256>>>(pFF, ff2_w + (long)i * FFH * DMODEL,
            ff2_b + i * DMODEL, pH, pH,
            ROWS, DMODEL, FFH, 0, FFH, 0, DMODEL, 0, DMODEL, 1.f);
    }

    ln_k<<<ROWS, 128>>>(pH, lnf_g, lnf_b, pY);
    mean_k<<<BATCH, 128>>>(pY, pFeat);
    gemm2_k<false,false><<<dim3(8, 1, 1), 256>>>(pFeat, head_w, head_b, nullptr, out,
        BATCH, NCLS, DMODEL, 0, DMODEL, 0, NCLS, 0, NCLS, 1.f);
}

// round 3
// speedup vs baseline: 1.4984x; 1.0990x over previous
#include <cuda_runtime.h>
#include <cuda_bf16.h>
#include <math.h>

// ---------------- problem constants ----------------
#define BATCH   32
#define NTOK    196
#define DMODEL  128
#define ROWS    (BATCH*NTOK) // 6272
#define PDIM    768
#define DEPTH   7
#define KNN_LAYER 6
#define MKEYS   8192
#define TOPK    32
#define FFH     512
#define NCLS    1000
#define SCALE   0.08838834764831845f
#define LNEPS   1e-5f

// ---------------- device scratch ----------------
__device__ float g_p   [ (long)ROWS*PDIM ];
__device__ float g_h   [ (long)ROWS*DMODEL ];
__device__ float g_y   [ (long)ROWS*DMODEL ];
__device__ float g_qkv [ (long)ROWS*3*DMODEL ];
__device__ float g_att [ (long)BATCH*NTOK*NTOK ];
__device__ float g_msim[ (long)BATCH*NTOK*MKEYS ];
__device__ float g_o   [ (long)ROWS*DMODEL ];
__device__ float g_ff  [ (long)ROWS*FFH ];
__device__ float g_mv  [ (long)ROWS*TOPK ];
__device__ int   g_mi  [ (long)ROWS*TOPK ];
__device__ float g_feats[ BATCH*DMODEL ];

// ---------------- helpers ----------------
__device__ __forceinline__ float gelu_tanh(float v) {
    const float c = 0.7978845608028654f;
    float t = tanhf(c * (v + 0.044715f * v * v * v));
    return 0.5f * v * (1.f + t);
}
__device__ __forceinline__ unsigned f2tf32(float f) {
    unsigned u;
    asm("cvt.rna.tf32.f32 %0, %1;" : "=r"(u) : "f"(f));
    return u;
}
__device__ __forceinline__ void split_tf32(float v, unsigned& h, unsigned& l) {
    h = f2tf32(v);
    l = f2tf32(v - __uint_as_float(h));
}
#define MMA_TF32(ACC, AF, BF)                                              \
    asm volatile(                                                          \
        "mma.sync.aligned.m16n8k8.row.col.f32.tf32.tf32.f32 "              \
        "{%0,%1,%2,%3}, {%4,%5,%6,%7}, {%8,%9}, {%0,%1,%2,%3};"            \
        : "+f"((ACC)[0]), "+f"((ACC)[1]), "+f"((ACC)[2]), "+f"((ACC)[3])   \
        : "r"((AF)[0]), "r"((AF)[1]), "r"((AF)[2]), "r"((AF)[3]),          \
          "r"((BF)[0]), "r"((BF)[1]))

// ---------------- patchify ----------------
__global__ void patchify_k(const float* __restrict__ x, float* __restrict__ p) {
    long e = (long)blockIdx.x * 256 + threadIdx.x;
    if (e >= (long)ROWS * PDIM) return;
    int c   = (int)(e % PDIM);
    long row = e / PDIM;
    int b = (int)(row / NTOK), n = (int)(row % NTOK);
    int i = n / 14, j = n % 14;
    int ch = c / 256, r = c % 256, pi = r / 16, pj = r % 16;
    p[e] = x[(((long)b*3 + ch)*224 + (i*16 + pi))*224 + (j*16 + pj)];
}

// ---------------- unified 3xTF32 mma GEMM ----------------
// Block tile 64(M) x 128(N), k-chunk 16. 8 warps as 2x4, warp tile 32x32.
// C[bz] = alpha * A[bz] (op B[bz]) (+bias) (+res) (opt gelu)
template<bool TB, bool DOGELU>
__global__ void __launch_bounds__(256, 2)
mma3_k(const float* __restrict__ A, const float* __restrict__ Bm,
       const float* __restrict__ bias, const float* __restrict__ Res,
       float* __restrict__ C,
       int Mr, int Nc, int K,
       long sAb, int lda, long sBb, int ldb, long sCb, int ldc,
       float alpha)
{
    __shared__ unsigned Ah[64][20], Al[64][20];
    __shared__ unsigned Bh[16][136], Bl[16][136];

    int bz = blockIdx.z;
    const float* Ab = A + (long)bz * sAb;
    const float* Bb = Bm + (long)bz * sBb;
    float*       Cb = C + (long)bz * sCb;
    const float* Rb = Res ? (Res + (long)bz * sCb) : nullptr;

    int row0 = blockIdx.y * 64;
    int col0 = blockIdx.x * 128;
    int tid = threadIdx.x;
    int lane = tid & 31, warp = tid >> 5;
    int wm = warp >> 2, wn = warp & 3;    // 2 x 4 warps
    int g = lane >> 2, tg = lane & 3;

    // load index precompute
    int arow = tid >> 2, ak = (tid & 3) * 4;         // A: 64 x 16
    int bkNN = tid >> 5, bnNN = (tid & 31) * 4;      // B NN: 16 x 128 (two passes k+=8)
    int bnTB = tid >> 2, bkTB = (tid & 3) * 4;       // B TB: 128 n x 16 k (two passes n+=64)

    float acc[2][4][4];
    #pragma unroll
    for (int im = 0; im < 2; im++)
        #pragma unroll
        for (int jn = 0; jn < 4; jn++)
            #pragma unroll
            for (int c = 0; c < 4; c++) acc[im][jn][c] = 0.f;

    for (int k0 = 0; k0 < K; k0 += 16) {
        // ---- A tile -> Ah/Al[m][k]
        {
            int gr = row0 + arow, gk = k0 + ak;
            float4 v = make_float4(0.f, 0.f, 0.f, 0.f);
            if (gr < Mr) {
                if (gk + 3 < K) v = *(const float4*)&Ab[(long)gr * lda + gk];
                else {
                    if (gk + 0 < K) v.x = Ab[(long)gr * lda + gk + 0];
                    if (gk + 1 < K) v.y = Ab[(long)gr * lda + gk + 1];
                    if (gk + 2 < K) v.z = Ab[(long)gr * lda + gk + 2];
                    if (gk + 3 < K) v.w = Ab[(long)gr * lda + gk + 3];
                }
            }
            split_tf32(v.x, Ah[arow][ak + 0], Al[arow][ak + 0]);
            split_tf32(v.y, Ah[arow][ak + 1], Al[arow][ak + 1]);
            split_tf32(v.z, Ah[arow][ak + 2], Al[arow][ak + 2]);
            split_tf32(v.w, Ah[arow][ak + 3], Al[arow][ak + 3]);
        }
        // ---- B tile -> Bh/Bl[k][n]
        if (TB) {
            #pragma unroll
            for (int p = 0; p < 2; p++) {
                int n = bnTB + p * 64;
                int gn = col0 + n, gk = k0 + bkTB;
                float4 v = make_float4(0.f, 0.f, 0.f, 0.f);
                if (gn < Nc) {
                    if (gk + 3 < K) v = *(const float4*)&Bb[(long)gn * ldb + gk];
                    else {
                        if (gk + 0 < K) v.x = Bb[(long)gn * ldb + gk + 0];
                        if (gk + 1 < K) v.y = Bb[(long)gn * ldb + gk + 1];
                        if (gk + 2 < K) v.z = Bb[(long)gn * ldb + gk + 2];
                        if (gk + 3 < K) v.w = Bb[(long)gn * ldb + gk + 3];
                    }
                }
                split_tf32(v.x, Bh[bkTB + 0][n], Bl[bkTB + 0][n]);
                split_tf32(v.y, Bh[bkTB + 1][n], Bl[bkTB + 1][n]);
                split_tf32(v.z, Bh[bkTB + 2][n], Bl[bkTB + 2][n]);
                split_tf32(v.w, Bh[bkTB + 3][n], Bl[bkTB + 3][n]);
            }
        } else {
            #pragma unroll
            for (int p = 0; p < 2; p++) {
                int k = bkNN + p * 8;
                int gk = k0 + k, gn = col0 + bnNN;
                float4 v = make_float4(0.f, 0.f, 0.f, 0.f);
                if (gk < K) {
                    if (gn + 3 < Nc) v = *(const float4*)&Bb[(long)gk * ldb + gn];
                    else {
                        if (gn + 0 < Nc) v.x = Bb[(long)gk * ldb + gn + 0];
                        if (gn + 1 < Nc) v.y = Bb[(long)gk * ldb + gn + 1];
                        if (gn + 2 < Nc) v.z = Bb[(long)gk * ldb + gn + 2];
                        if (gn + 3 < Nc) v.w = Bb[(long)gk * ldb + gn + 3];
                    }
                }
                split_tf32(v.x, Bh[k][bnNN + 0], Bl[k][bnNN + 0]);
                split_tf32(v.y, Bh[k][bnNN + 1], Bl[k][bnNN + 1]);
                split_tf32(v.z, Bh[k][bnNN + 2], Bl[k][bnNN + 2]);
                split_tf32(v.w, Bh[k][bnNN + 3], Bl[k][bnNN + 3]);
            }
        }
        __syncthreads();

        #pragma unroll
        for (int ks = 0; ks < 16; ks += 8) {
            unsigned ah[2][4], al_[2][4], bh[4][2], bl_[4][2];
            #pragma unroll
            for (int im = 0; im < 2; im++) {
                int mb = wm * 32 + im * 16;
                ah[im][0] = Ah[mb + g    ][ks +     tg];
                ah[im][1] = Ah[mb + g + 8][ks +     tg];
                ah[im][2] = Ah[mb + g    ][ks + 4 + tg];
                ah[im][3] = Ah[mb + g + 8][ks + 4 + tg];
                al_[im][0] = Al[mb + g    ][ks +     tg];
                al_[im][1] = Al[mb + g + 8][ks +     tg];
                al_[im][2] = Al[mb + g    ][ks + 4 + tg];
                al_[im][3] = Al[mb + g + 8][ks + 4 + tg];
            }
            #pragma unroll
            for (int jn = 0; jn < 4; jn++) {
                int nb = wn * 32 + jn * 8;
                bh[jn][0] = Bh[ks +     tg][nb + g];
                bh[jn][1] = Bh[ks + 4 + tg][nb + g];
                bl_[jn][0] = Bl[ks +     tg][nb + g];
                bl_[jn][1] = Bl[ks + 4 + tg][nb + g];
            }
            #pragma unroll
            for (int im = 0; im < 2; im++)
                #pragma unroll
                for (int jn = 0; jn < 4; jn++) {
                    MMA_TF32(acc[im][jn], ah[im], bl_[jn]);
                    MMA_TF32(acc[im][jn], al_[im], bh[jn]);
                    MMA_TF32(acc[im][jn], ah[im], bh[jn]);
                }
        }
        __syncthreads();
    }

    // ---- epilogue
    #pragma unroll
    for (int im = 0; im < 2; im++) {
        #pragma unroll
        for (int jn = 0; jn < 4; jn++) {
            int r0 = row0 + wm * 32 + im * 16 + g;
            int c0 = col0 + wn * 32 + jn * 8 + 2 * tg;
            #pragma unroll
            for (int half = 0; half < 2; half++) {
                int gr = r0 + half * 8;
                if (gr >= Mr) continue;
                #pragma unroll
                for (int cc = 0; cc < 2; cc++) {
                    int gn = c0 + cc;
                    if (gn >= Nc) continue;
                    float v = acc[im][jn][half * 2 + cc] * alpha;
                    if (bias) v += bias[gn];
                    if (Rb)   v += Rb[(long)gr * ldc + gn];
                    if (DOGELU) v = gelu_tanh(v);
                    Cb[(long)gr * ldc + gn] = v;
                }
            }
        }
    }
}

// ---------------- layernorm over D=128 ----------------
__global__ void ln_k(const float* __restrict__ in, const float* __restrict__ g,
                     const float* __restrict__ b, float* __restrict__ out)
{
    long row = blockIdx.x;
    int t = threadIdx.x;
    float v = in[row * DMODEL + t];
    __shared__ float red[4];
    float s = v;
    #pragma unroll
    for (int o = 16; o > 0; o >>= 1) s += __shfl_xor_sync(0xffffffffu, s, o);
    if ((t & 31) == 0) red[t >> 5] = s;
    __syncthreads();
    float mu = (red[0] + red[1] + red[2] + red[3]) * (1.f / 128.f);
    float d = v - mu;
    __syncthreads();
    float s2 = d * d;
    #pragma unroll
    for (int o = 16; o > 0; o >>= 1) s2 += __shfl_xor_sync(0xffffffffu, s2, o);
    if ((t & 31) == 0) red[t >> 5] = s2;
    __syncthreads();
    float var = (red[0] + red[1] + red[2] + red[3]) * (1.f / 128.f);
    out[row * DMODEL + t] = d / sqrtf(var + LNEPS) * g[t] + b[t];
}

// ---------------- softmax over 196 ----------------
__global__ void softmax196_k(float* __restrict__ att)
{
    long row = blockIdx.x;
    int t = threadIdx.x;
    float* a = att + row * NTOK;
    float v = (t < NTOK) ? a[t] : -3.4e38f;
    __shared__ float red[8];
    float m = v;
    #pragma unroll
    for (int o = 16; o > 0; o >>= 1) m = fmaxf(m, __shfl_xor_sync(0xffffffffu, m, o));
    if ((t & 31) == 0) red[t >> 5] = m;
    __syncthreads();
    m = red[0];
    #pragma unroll
    for (int i = 1; i < 8; i++) m = fmaxf(m, red[i]);
    float e = (t < NTOK) ? expf(v - m) : 0.f;
    __syncthreads();
    float s = e;
    #pragma unroll
    for (int o = 16; o > 0; o >>= 1) s += __shfl_xor_sync(0xffffffffu, s, o);
    if ((t & 31) == 0) red[t >> 5] = s;
    __syncthreads();
    s = red[0];
    #pragma unroll
    for (int i = 1; i < 8; i++) s += red[i];
    if (t < NTOK) a[t] = e / s;
}

// ---------------- top-32 of an 8192-row ----------------
__global__ void topk_k(const float* __restrict__ msim,
                       float* __restrict__ mvals, int* __restrict__ midx)
{
    long row = blockIdx.x;
    int tid = threadIdx.x;
    __shared__ float sv[MKEYS];
    __shared__ float rmax[256];
    __shared__ int   rloc[256];
    const float* src = msim + row * MKEYS;
    for (int i = tid; i < MKEYS; i += 256) sv[i] = src[i];
    __syncthreads();
    for (int it = 0; it < TOPK; it++) {
        float best = -3.4e38f; int bi = MKEYS;
        for (int i = tid; i < MKEYS; i += 256) {
            float v = sv[i];
            if (v > best) { best = v; bi = i; }
        }
        rmax[tid] = best; rloc[tid] = bi;
        __syncthreads();
        for (int s = 128; s > 0; s >>= 1) {
            if (tid < s) {
                float ov = rmax[tid + s]; int oi = rloc[tid + s];
                if (ov > rmax[tid] || (ov == rmax[tid] && oi < rloc[tid])) {
                    rmax[tid] = ov; rloc[tid] = oi;
                }
            }
            __syncthreads();
        }
        if (tid == 0) {
            mvals[row * TOPK + it] = rmax[0];
            midx [row * TOPK + it] = rloc[0];
            sv[rloc[0]] = -3.4e38f;
        }
        __syncthreads();
    }
}

// ---------------- kNN combine ----------------
__global__ void knn_combine_k(const float* __restrict__ att,
                              const float* __restrict__ mvals, const int* __restrict__ midx,
                              const float* __restrict__ qkv, const float* __restrict__ knn_v,
                              float* __restrict__ out)
{
    long row = blockIdx.x;
    int b = (int)(row / NTOK);
    int tid = threadIdx.x;
    __shared__ float w[TOPK + NTOK];
    __shared__ int   sidx[TOPK];
    __shared__ float red[4];

    if (tid < TOPK) {
        w[tid]    = mvals[row * TOPK + tid];
        sidx[tid] = midx [row * TOPK + tid];
    }
    for (int m = tid; m < NTOK; m += 128) w[TOPK + m] = att[row * NTOK + m];
    __syncthreads();

    float l0 = w[tid];
    float l1 = (tid < (TOPK + NTOK - 128)) ? w[tid + 128] : -3.4e38f;
    float m = fmaxf(l0, l1);
    #pragma unroll
    for (int o = 16; o > 0; o >>= 1) m = fmaxf(m, __shfl_xor_sync(0xffffffffu, m, o));
    if ((tid & 31) == 0) red[tid >> 5] = m;
    __syncthreads();
    m = fmaxf(fmaxf(red[0], red[1]), fmaxf(red[2], red[3]));
    float e0 = expf(l0 - m);
    float e1 = (tid < (TOPK + NTOK - 128)) ? expf(l1 - m) : 0.f;
    float s = e0 + e1;
    __syncthreads();
    #pragma unroll
    for (int o = 16; o > 0; o >>= 1) s += __shfl_xor_sync(0xffffffffu, s, o);
    if ((tid & 31) == 0) red[tid >> 5] = s;
    __syncthreads();
    s = red[0] + red[1] + red[2] + red[3];
    float inv = 1.f / s;
    w[tid] = e0 * inv;
    if (tid < (TOPK + NTOK - 128)) w[tid + 128] = e1 * inv;
    __syncthreads();

    float acc = 0.f;
    const float* kv = knn_v + (long)b * MKEYS * DMODEL;
    #pragma unroll 4
    for (int j = 0; j < TOPK; j++)
        acc += w[j] * kv[(long)sidx[j] * DMODEL + tid];
    const float* vbase = qkv + ((long)b * NTOK) * 384 + 256;
    for (int mm = 0; mm < NTOK; mm++)
        acc += w[TOPK + mm] * vbase[(long)mm * 384 + tid];
    out[row * DMODEL + tid] = acc;
}

// ---------------- mean pool ----------------
__global__ void mean_k(const float* __restrict__ y, float* __restrict__ feats)
{
    int b = blockIdx.x, d = threadIdx.x;
    float s = 0.f;
    for (int n = 0; n < NTOK; n++) s += y[((long)b * NTOK + n) * DMODEL + d];
    feats[b * DMODEL + d] = s * (1.f / 196.f);
}

// ---------------- launch ----------------
extern "C" void kernel_launch(void* const* d_in, const int* in_sizes, int n_in,
                              void* d_out, int out_size)
{
    const float* x       = (const float*)d_in[0];
    const float* patch_w = (const float*)d_in[1];
    const float* patch_b = (const float*)d_in[2];
    const float* ln1_g   = (const float*)d_in[3];
    const float* ln1_b   = (const float*)d_in[4];
    const float* qkv_w   = (const float*)d_in[5];
    const float* qkv_b   = (const float*)d_in[6];
    const float* out_w   = (const float*)d_in[7];
    const float* out_b   = (const float*)d_in[8];
    const float* ln2_g   = (const float*)d_in[9];
    const float* ln2_b   = (const float*)d_in[10];
    const float* ff1_w   = (const float*)d_in[11];
    const float* ff1_b   = (const float*)d_in[12];
    const float* ff2_w   = (const float*)d_in[13];
    const float* ff2_b   = (const float*)d_in[14];
    const float* lnf_g   = (const float*)d_in[15];
    const float* lnf_b   = (const float*)d_in[16];
    const float* knn_k   = (const float*)d_in[17];
    const float* knn_v   = (const float*)d_in[18];
    const float* head_w  = (const float*)d_in[19];
    const float* head_b  = (const float*)d_in[20];
    float* out = (float*)d_out;

    void* tp;
    cudaGetSymbolAddress(&tp, g_p);    float* pP    = (float*)tp;
    cudaGetSymbolAddress(&tp, g_h);    float* pH    = (float*)tp;
    cudaGetSymbolAddress(&tp, g_y);    float* pY    = (float*)tp;
    cudaGetSymbolAddress(&tp, g_qkv);  float* pQKV  = (float*)tp;
    cudaGetSymbolAddress(&tp, g_att);  float* pATT  = (float*)tp;
    cudaGetSymbolAddress(&tp, g_msim); float* pMSIM = (float*)tp;
    cudaGetSymbolAddress(&tp, g_o);    float* pO    = (float*)tp;
    cudaGetSymbolAddress(&tp, g_ff);   float* pFF   = (float*)tp;
    cudaGetSymbolAddress(&tp, g_mv);   float* pMV   = (float*)tp;
    cudaGetSymbolAddress(&tp, g_mi);   int*   pMI   = (int*)tp;
    cudaGetSymbolAddress(&tp, g_feats);float* pFeat = (float*)tp;

    // patch embed
    patchify_k<<<(int)(((long)ROWS * PDIM + 255) / 256), 256>>>(x, pP);
    mma3_k<false,false><<<dim3(1, 98, 1), 256>>>(pP, patch_w, patch_b, nullptr, pH,
        ROWS, DMODEL, PDIM, 0, PDIM, 0, DMODEL, 0, DMODEL, 1.f);

    for (int i = 0; i < DEPTH; i++) {
        ln_k<<<ROWS, 128>>>(pH, ln1_g + i * DMODEL, ln1_b + i * DMODEL, pY);
        mma3_k<false,false><<<dim3(3, 98, 1), 256>>>(pY, qkv_w + (long)i * DMODEL * 3 * DMODEL,
            qkv_b + i * 3 * DMODEL, nullptr, pQKV,
            ROWS, 3 * DMODEL, DMODEL, 0, DMODEL, 0, 3 * DMODEL, 0, 3 * DMODEL, 1.f);
        // sim = q @ k^T * scale  (batched TB)
        mma3_k<true,false><<<dim3(2, 4, BATCH), 256>>>(pQKV, pQKV + 128, nullptr, nullptr, pATT,
            NTOK, NTOK, DMODEL,
            (long)NTOK * 384, 384, (long)NTOK * 384, 384, (long)NTOK * NTOK, NTOK, SCALE);

        if (i == KNN_LAYER) {
            // msim = q @ knn_k^T * scale  (batched TB, N=8192)
            mma3_k<true,false><<<dim3(64, 4, BATCH), 256>>>(pQKV, knn_k, nullptr, nullptr, pMSIM,
                NTOK, MKEYS, DMODEL,
                (long)NTOK * 384, 384, (long)MKEYS * DMODEL, DMODEL, (long)NTOK * MKEYS, MKEYS, SCALE);
            topk_k<<<ROWS, 256>>>(pMSIM, pMV, pMI);
            knn_combine_k<<<ROWS, 128>>>(pATT, pMV, pMI, pQKV, knn_v, pO);
        } else {
            softmax196_k<<<ROWS, 256>>>(pATT);
            // o = attn @ v  (batched NN, K=196)
            mma3_k<false,false><<<dim3(1, 4, BATCH), 256>>>(pATT, pQKV + 256, nullptr, nullptr, pO,
                NTOK, DMODEL, NTOK,
                (long)NTOK * NTOK, NTOK, (long)NTOK * 384, 384, (long)NTOK * DMODEL, DMODEL, 1.f);
        }

        // h = h + o @ out_w + out_b
        mma3_k<false,false><<<dim3(1, 98, 1), 256>>>(pO, out_w + (long)i * DMODEL * DMODEL,
            out_b + i * DMODEL, pH, pH,
            ROWS, DMODEL, DMODEL, 0, DMODEL, 0, DMODEL, 0, DMODEL, 1.f);

        ln_k<<<ROWS, 128>>>(pH, ln2_g + i * DMODEL, ln2_b + i * DMODEL, pY);
        // ff1 + gelu
        mma3_k<false,true><<<dim3(4, 98, 1), 256>>>(pY, ff1_w + (long)i * DMODEL * FFH,
            ff1_b + i * FFH, nullptr, pFF,
            ROWS, FFH, DMODEL, 0, DMODEL, 0, FFH, 0, FFH, 1.f);
        // h = h + ff @ ff2_w + ff2_b
        mma3_k<false,false><<<dim3(1, 98, 1), 256>>>(pFF, ff2_w + (long)i * FFH * DMODEL,
            ff2_b + i * DMODEL, pH, pH,
            ROWS, DMODEL, FFH, 0, FFH, 0, DMODEL, 0, DMODEL, 1.f);
    }

    ln_k<<<ROWS, 128>>>(pH, lnf_g, lnf_b, pY);
    mean_k<<<BATCH, 128>>>(pY, pFeat);
    mma3_k<false,false><<<dim3(8, 1, 1), 256>>>(pFeat, head_w, head_b, nullptr, out,
        BATCH, NCLS, DMODEL, 0, DMODEL, 0, NCLS, 0, NCLS, 1.f);
}

// round 4
// speedup vs baseline: 2.1003x; 1.4017x over previous
#include <cuda_runtime.h>
#include <cuda_bf16.h>
#include <math.h>

// ---------------- problem constants ----------------
#define BATCH   32
#define NTOK    196
#define DMODEL  128
#define ROWS    (BATCH*NTOK) // 6272
#define PDIM    768
#define DEPTH   7
#define KNN_LAYER 6
#define MKEYS   8192
#define TOPK    32
#define FFH     512
#define NCLS    1000
#define SCALE   0.08838834764831845f
#define LNEPS   1e-5f

// ---------------- device scratch ----------------
__device__ float g_p   [ (long)ROWS*PDIM ];
__device__ float g_h   [ (long)ROWS*DMODEL ];
__device__ float g_y   [ (long)ROWS*DMODEL ];
__device__ float g_qkv [ (long)ROWS*3*DMODEL ];
__device__ float g_att [ (long)BATCH*NTOK*NTOK ];
__device__ float g_msim[ (long)BATCH*NTOK*MKEYS ];
__device__ float g_o   [ (long)ROWS*DMODEL ];
__device__ float g_ff  [ (long)ROWS*FFH ];
__device__ float g_mv  [ (long)ROWS*TOPK ];
__device__ int   g_mi  [ (long)ROWS*TOPK ];
__device__ float g_feats[ BATCH*DMODEL ];

// ---------------- helpers ----------------
__device__ __forceinline__ float gelu_tanh(float v) {
    const float c = 0.7978845608028654f;
    float t = tanhf(c * (v + 0.044715f * v * v * v));
    return 0.5f * v * (1.f + t);
}
__device__ __forceinline__ unsigned f2tf32(float f) {
    unsigned u;
    asm("cvt.rna.tf32.f32 %0, %1;" : "=r"(u) : "f"(f));
    return u;
}
#define MMA_TF32(ACC, AF, BF)                                              \
    asm volatile(                                                          \
        "mma.sync.aligned.m16n8k8.row.col.f32.tf32.tf32.f32 "              \
        "{%0,%1,%2,%3}, {%4,%5,%6,%7}, {%8,%9}, {%0,%1,%2,%3};"            \
        : "+f"((ACC)[0]), "+f"((ACC)[1]), "+f"((ACC)[2]), "+f"((ACC)[3])   \
        : "r"((AF)[0]), "r"((AF)[1]), "r"((AF)[2]), "r"((AF)[3]),          \
          "r"((BF)[0]), "r"((BF)[1]))

// ---------------- patchify ----------------
__global__ void patchify_k(const float* __restrict__ x, float* __restrict__ p) {
    long e = (long)blockIdx.x * 256 + threadIdx.x;
    if (e >= (long)ROWS * PDIM) return;
    int c   = (int)(e % PDIM);
    long row = e / PDIM;
    int b = (int)(row / NTOK), n = (int)(row % NTOK);
    int i = n / 14, j = n % 14;
    int ch = c / 256, r = c % 256, pi = r / 16, pj = r % 16;
    p[e] = x[(((long)b*3 + ch)*224 + (i*16 + pi))*224 + (j*16 + pj)];
}

// ---------------- unified TF32 mma GEMM (SPLIT=3: ~fp32, SPLIT=1: tf32) ------
// Block tile 64(M) x 128(N), K-chunk 32, reg-prefetch pipeline.
// 8 warps as 2x4, warp tile 32x32.
// smem layout: Ah[64*36] (+Al), Bh[32*136] (+Bl). Fragment LDS is conflict-free:
//   A bank = (4g+tg) mod 32 (all distinct), B bank = (8tg+g) mod 32 (all distinct).
#define APAD 36
#define BPAD 136
template<bool TB, bool DOGELU, int SPLIT>
__global__ void __launch_bounds__(256, 2)
mma3_k(const float* __restrict__ A, const float* __restrict__ Bm,
       const float* __restrict__ bias, const float* __restrict__ Res,
       float* __restrict__ C,
       int Mr, int Nc, int K,
       long sAb, int lda, long sBb, int ldb, long sCb, int ldc,
       float alpha)
{
    extern __shared__ unsigned smem_u[];
    unsigned* Ah = smem_u;
    unsigned* Al;
    unsigned* Bh;
    unsigned* Bl;
    if (SPLIT == 3) {
        Al = Ah + 64 * APAD;
        Bh = Al + 64 * APAD;
        Bl = Bh + 32 * BPAD;
    } else {
        Al = nullptr;
        Bh = Ah + 64 * APAD;
        Bl = nullptr;
    }

    int bz = blockIdx.z;
    const float* Ab = A + (long)bz * sAb;
    const float* Bb = Bm + (long)bz * sBb;
    float*       Cb = C + (long)bz * sCb;
    const float* Rb = Res ? (Res + (long)bz * sCb) : nullptr;

    int row0 = blockIdx.y * 64;
    int col0 = blockIdx.x * 128;
    int tid = threadIdx.x;
    int lane = tid & 31, warp = tid >> 5;
    int wm = warp >> 2, wn = warp & 3;
    int g = lane >> 2, tg = lane & 3;

    // global-load index precompute (K-chunk 32)
    int ar = tid >> 3, ak = (tid & 7) * 4;        // A: rows ar, ar+32; k ak..ak+3
    int bkNN = tid >> 5, bnNN = (tid & 31) * 4;   // B NN: k rows bkNN+8p; n bnNN..+3
    int bnTB = tid >> 3, bkTB = (tid & 7) * 4;    // B TB: n rows bnTB+32p; k bkTB..+3

    float4 pa[2], pb[4];

    // ---- load helpers
    auto loadA = [&](int k0) {
        #pragma unroll
        for (int p = 0; p < 2; p++) {
            int gr = row0 + ar + p * 32, gk = k0 + ak;
            float4 v = make_float4(0.f, 0.f, 0.f, 0.f);
            if (gr < Mr) {
                if (gk + 3 < K) v = *(const float4*)&Ab[(long)gr * lda + gk];
                else {
                    if (gk + 0 < K) v.x = Ab[(long)gr * lda + gk + 0];
                    if (gk + 1 < K) v.y = Ab[(long)gr * lda + gk + 1];
                    if (gk + 2 < K) v.z = Ab[(long)gr * lda + gk + 2];
                    if (gk + 3 < K) v.w = Ab[(long)gr * lda + gk + 3];
                }
            }
            pa[p] = v;
        }
    };
    auto loadB = [&](int k0) {
        if (TB) {
            #pragma unroll
            for (int p = 0; p < 4; p++) {
                int gn = col0 + bnTB + p * 32, gk = k0 + bkTB;
                float4 v = make_float4(0.f, 0.f, 0.f, 0.f);
                if (gn < Nc) {
                    if (gk + 3 < K) v = *(const float4*)&Bb[(long)gn * ldb + gk];
                    else {
                        if (gk + 0 < K) v.x = Bb[(long)gn * ldb + gk + 0];
                        if (gk + 1 < K) v.y = Bb[(long)gn * ldb + gk + 1];
                        if (gk + 2 < K) v.z = Bb[(long)gn * ldb + gk + 2];
                        if (gk + 3 < K) v.w = Bb[(long)gn * ldb + gk + 3];
                    }
                }
                pb[p] = v;
            }
        } else {
            #pragma unroll
            for (int p = 0; p < 4; p++) {
                int gk = k0 + bkNN + p * 8, gn = col0 + bnNN;
                float4 v = make_float4(0.f, 0.f, 0.f, 0.f);
                if (gk < K) {
                    if (gn + 3 < Nc) v = *(const float4*)&Bb[(long)gk * ldb + gn];
                    else {
                        if (gn + 0 < Nc) v.x = Bb[(long)gk * ldb + gn + 0];
                        if (gn + 1 < Nc) v.y = Bb[(long)gk * ldb + gn + 1];
                        if (gn + 2 < Nc) v.z = Bb[(long)gk * ldb + gn + 2];
                        if (gn + 3 < Nc) v.w = Bb[(long)gk * ldb + gn + 3];
                    }
                }
                pb[p] = v;
            }
        }
    };
    auto storeTiles = [&]() {
        #pragma unroll
        for (int p = 0; p < 2; p++) {
            int r = ar + p * 32;
            float vv[4] = {pa[p].x, pa[p].y, pa[p].z, pa[p].w};
            #pragma unroll
            for (int j = 0; j < 4; j++) {
                unsigned h = f2tf32(vv[j]);
                Ah[r * APAD + ak + j] = h;
                if (SPLIT == 3) Al[r * APAD + ak + j] = f2tf32(vv[j] - __uint_as_float(h));
            }
        }
        if (TB) {
            #pragma unroll
            for (int p = 0; p < 4; p++) {
                int n = bnTB + p * 32;
                float vv[4] = {pb[p].x, pb[p].y, pb[p].z, pb[p].w};
                #pragma unroll
                for (int j = 0; j < 4; j++) {
                    unsigned h = f2tf32(vv[j]);
                    Bh[(bkTB + j) * BPAD + n] = h;
                    if (SPLIT == 3) Bl[(bkTB + j) * BPAD + n] = f2tf32(vv[j] - __uint_as_float(h));
                }
            }
        } else {
            #pragma unroll
            for (int p = 0; p < 4; p++) {
                int k = bkNN + p * 8;
                float vv[4] = {pb[p].x, pb[p].y, pb[p].z, pb[p].w};
                #pragma unroll
                for (int j = 0; j < 4; j++) {
                    unsigned h = f2tf32(vv[j]);
                    Bh[k * BPAD + bnNN + j] = h;
                    if (SPLIT == 3) Bl[k * BPAD + bnNN + j] = f2tf32(vv[j] - __uint_as_float(h));
                }
            }
        }
    };

    float acc[2][4][4];
    #pragma unroll
    for (int im = 0; im < 2; im++)
        #pragma unroll
        for (int jn = 0; jn < 4; jn++)
            #pragma unroll
            for (int c = 0; c < 4; c++) acc[im][jn][c] = 0.f;

    loadA(0); loadB(0);

    for (int k0 = 0; k0 < K; k0 += 32) {
        storeTiles();
        __syncthreads();
        if (k0 + 32 < K) { loadA(k0 + 32); loadB(k0 + 32); }

        #pragma unroll
        for (int ks = 0; ks < 32; ks += 8) {
            unsigned ah[2][4], al_[2][4], bh[4][2], bl_[4][2];
            #pragma unroll
            for (int im = 0; im < 2; im++) {
                int mb = wm * 32 + im * 16;
                ah[im][0] = Ah[(mb + g    ) * APAD + ks +     tg];
                ah[im][1] = Ah[(mb + g + 8) * APAD + ks +     tg];
                ah[im][2] = Ah[(mb + g    ) * APAD + ks + 4 + tg];
                ah[im][3] = Ah[(mb + g + 8) * APAD + ks + 4 + tg];
                if (SPLIT == 3) {
                    al_[im][0] = Al[(mb + g    ) * APAD + ks +     tg];
                    al_[im][1] = Al[(mb + g + 8) * APAD + ks +     tg];
                    al_[im][2] = Al[(mb + g    ) * APAD + ks + 4 + tg];
                    al_[im][3] = Al[(mb + g + 8) * APAD + ks + 4 + tg];
                }
            }
            #pragma unroll
            for (int jn = 0; jn < 4; jn++) {
                int nb = wn * 32 + jn * 8;
                bh[jn][0] = Bh[(ks +     tg) * BPAD + nb + g];
                bh[jn][1] = Bh[(ks + 4 + tg) * BPAD + nb + g];
                if (SPLIT == 3) {
                    bl_[jn][0] = Bl[(ks +     tg) * BPAD + nb + g];
                    bl_[jn][1] = Bl[(ks + 4 + tg) * BPAD + nb + g];
                }
            }
            #pragma unroll
            for (int im = 0; im < 2; im++)
                #pragma unroll
                for (int jn = 0; jn < 4; jn++) {
                    if (SPLIT == 3) {
                        MMA_TF32(acc[im][jn], ah[im], bl_[jn]);
                        MMA_TF32(acc[im][jn], al_[im], bh[jn]);
                    }
                    MMA_TF32(acc[im][jn], ah[im], bh[jn]);
                }
        }
        __syncthreads();
    }

    // ---- epilogue
    #pragma unroll
    for (int im = 0; im < 2; im++) {
        #pragma unroll
        for (int jn = 0; jn < 4; jn++) {
            int r0 = row0 + wm * 32 + im * 16 + g;
            int c0 = col0 + wn * 32 + jn * 8 + 2 * tg;
            #pragma unroll
            for (int half = 0; half < 2; half++) {
                int gr = r0 + half * 8;
                if (gr >= Mr) continue;
                #pragma unroll
                for (int cc = 0; cc < 2; cc++) {
                    int gn = c0 + cc;
                    if (gn >= Nc) continue;
                    float v = acc[im][jn][half * 2 + cc] * alpha;
                    if (bias) v += bias[gn];
                    if (Rb)   v += Rb[(long)gr * ldc + gn];
                    if (DOGELU) v = gelu_tanh(v);
                    Cb[(long)gr * ldc + gn] = v;
                }
            }
        }
    }
}

#define SMEM3 ((64*APAD*2 + 32*BPAD*2) * 4)
#define SMEM1 ((64*APAD + 32*BPAD) * 4)

// ---------------- layernorm over D=128 ----------------
__global__ void ln_k(const float* __restrict__ in, const float* __restrict__ g,
                     const float* __restrict__ b, float* __restrict__ out)
{
    long row = blockIdx.x;
    int t = threadIdx.x;
    float v = in[row * DMODEL + t];
    __shared__ float red[4];
    float s = v;
    #pragma unroll
    for (int o = 16; o > 0; o >>= 1) s += __shfl_xor_sync(0xffffffffu, s, o);
    if ((t & 31) == 0) red[t >> 5] = s;
    __syncthreads();
    float mu = (red[0] + red[1] + red[2] + red[3]) * (1.f / 128.f);
    float d = v - mu;
    __syncthreads();
    float s2 = d * d;
    #pragma unroll
    for (int o = 16; o > 0; o >>= 1) s2 += __shfl_xor_sync(0xffffffffu, s2, o);
    if ((t & 31) == 0) red[t >> 5] = s2;
    __syncthreads();
    float var = (red[0] + red[1] + red[2] + red[3]) * (1.f / 128.f);
    out[row * DMODEL + t] = d / sqrtf(var + LNEPS) * g[t] + b[t];
}

// ---------------- softmax over 196 ----------------
__global__ void softmax196_k(float* __restrict__ att)
{
    long row = blockIdx.x;
    int t = threadIdx.x;
    float* a = att + row * NTOK;
    float v = (t < NTOK) ? a[t] : -3.4e38f;
    __shared__ float red[8];
    float m = v;
    #pragma unroll
    for (int o = 16; o > 0; o >>= 1) m = fmaxf(m, __shfl_xor_sync(0xffffffffu, m, o));
    if ((t & 31) == 0) red[t >> 5] = m;
    __syncthreads();
    m = red[0];
    #pragma unroll
    for (int i = 1; i < 8; i++) m = fmaxf(m, red[i]);
    float e = (t < NTOK) ? expf(v - m) : 0.f;
    __syncthreads();
    float s = e;
    #pragma unroll
    for (int o = 16; o > 0; o >>= 1) s += __shfl_xor_sync(0xffffffffu, s, o);
    if ((t & 31) == 0) red[t >> 5] = s;
    __syncthreads();
    s = red[0];
    #pragma unroll
    for (int i = 1; i < 8; i++) s += red[i];
    if (t < NTOK) a[t] = e / s;
}

// ---------------- top-32 of an 8192-row ----------------
__global__ void topk_k(const float* __restrict__ msim,
                       float* __restrict__ mvals, int* __restrict__ midx)
{
    long row = blockIdx.x;
    int tid = threadIdx.x;
    __shared__ float sv[MKEYS];
    __shared__ float rmax[256];
    __shared__ int   rloc[256];
    const float* src = msim + row * MKEYS;
    for (int i = tid; i < MKEYS; i += 256) sv[i] = src[i];
    __syncthreads();
    for (int it = 0; it < TOPK; it++) {
        float best = -3.4e38f; int bi = MKEYS;
        for (int i = tid; i < MKEYS; i += 256) {
            float v = sv[i];
            if (v > best) { best = v; bi = i; }
        }
        rmax[tid] = best; rloc[tid] = bi;
        __syncthreads();
        for (int s = 128; s > 0; s >>= 1) {
            if (tid < s) {
                float ov = rmax[tid + s]; int oi = rloc[tid + s];
                if (ov > rmax[tid] || (ov == rmax[tid] && oi < rloc[tid])) {
                    rmax[tid] = ov; rloc[tid] = oi;
                }
            }
            __syncthreads();
        }
        if (tid == 0) {
            mvals[row * TOPK + it] = rmax[0];
            midx [row * TOPK + it] = rloc[0];
            sv[rloc[0]] = -3.4e38f;
        }
        __syncthreads();
    }
}

// ---------------- kNN combine ----------------
__global__ void knn_combine_k(const float* __restrict__ att,
                              const float* __restrict__ mvals, const int* __restrict__ midx,
                              const float* __restrict__ qkv, const float* __restrict__ knn_v,
                              float* __restrict__ out)
{
    long row = blockIdx.x;
    int b = (int)(row / NTOK);
    int tid = threadIdx.x;
    __shared__ float w[TOPK + NTOK];
    __shared__ int   sidx[TOPK];
    __shared__ float red[4];

    if (tid < TOPK) {
        w[tid]    = mvals[row * TOPK + tid];
        sidx[tid] = midx [row * TOPK + tid];
    }
    for (int m = tid; m < NTOK; m += 128) w[TOPK + m] = att[row * NTOK + m];
    __syncthreads();

    float l0 = w[tid];
    float l1 = (tid < (TOPK + NTOK - 128)) ? w[tid + 128] : -3.4e38f;
    float m = fmaxf(l0, l1);
    #pragma unroll
    for (int o = 16; o > 0; o >>= 1) m = fmaxf(m, __shfl_xor_sync(0xffffffffu, m, o));
    if ((tid & 31) == 0) red[tid >> 5] = m;
    __syncthreads();
    m = fmaxf(fmaxf(red[0], red[1]), fmaxf(red[2], red[3]));
    float e0 = expf(l0 - m);
    float e1 = (tid < (TOPK + NTOK - 128)) ? expf(l1 - m) : 0.f;
    float s = e0 + e1;
    __syncthreads();
    #pragma unroll
    for (int o = 16; o > 0; o >>= 1) s += __shfl_xor_sync(0xffffffffu, s, o);
    if ((tid & 31) == 0) red[tid >> 5] = s;
    __syncthreads();
    s = red[0] + red[1] + red[2] + red[3];
    float inv = 1.f / s;
    w[tid] = e0 * inv;
    if (tid < (TOPK + NTOK - 128)) w[tid + 128] = e1 * inv;
    __syncthreads();

    float acc = 0.f;
    const float* kv = knn_v + (long)b * MKEYS * DMODEL;
    #pragma unroll 4
    for (int j = 0; j < TOPK; j++)
        acc += w[j] * kv[(long)sidx[j] * DMODEL + tid];
    const float* vbase = qkv + ((long)b * NTOK) * 384 + 256;
    for (int mm = 0; mm < NTOK; mm++)
        acc += w[TOPK + mm] * vbase[(long)mm * 384 + tid];
    out[row * DMODEL + tid] = acc;
}

// ---------------- mean pool ----------------
__global__ void mean_k(const float* __restrict__ y, float* __restrict__ feats)
{
    int b = blockIdx.x, d = threadIdx.x;
    float s = 0.f;
    for (int n = 0; n < NTOK; n++) s += y[((long)b * NTOK + n) * DMODEL + d];
    feats[b * DMODEL + d] = s * (1.f / 196.f);
}

// ---------------- launch ----------------
extern "C" void kernel_launch(void* const* d_in, const int* in_sizes, int n_in,
                              void* d_out, int out_size)
{
    const float* x       = (const float*)d_in[0];
    const float* patch_w = (const float*)d_in[1];
    const float* patch_b = (const float*)d_in[2];
    const float* ln1_g   = (const float*)d_in[3];
    const float* ln1_b   = (const float*)d_in[4];
    const float* qkv_w   = (const float*)d_in[5];
    const float* qkv_b   = (const float*)d_in[6];
    const float* out_w   = (const float*)d_in[7];
    const float* out_b   = (const float*)d_in[8];
    const float* ln2_g   = (const float*)d_in[9];
    const float* ln2_b   = (const float*)d_in[10];
    const float* ff1_w   = (const float*)d_in[11];
    const float* ff1_b   = (const float*)d_in[12];
    const float* ff2_w   = (const float*)d_in[13];
    const float* ff2_b   = (const float*)d_in[14];
    const float* lnf_g   = (const float*)d_in[15];
    const float* lnf_b   = (const float*)d_in[16];
    const float* knn_k   = (const float*)d_in[17];
    const float* knn_v   = (const float*)d_in[18];
    const float* head_w  = (const float*)d_in[19];
    const float* head_b  = (const float*)d_in[20];
    float* out = (float*)d_out;

    void* tp;
    cudaGetSymbolAddress(&tp, g_p);    float* pP    = (float*)tp;
    cudaGetSymbolAddress(&tp, g_h);    float* pH    = (float*)tp;
    cudaGetSymbolAddress(&tp, g_y);    float* pY    = (float*)tp;
    cudaGetSymbolAddress(&tp, g_qkv);  float* pQKV  = (float*)tp;
    cudaGetSymbolAddress(&tp, g_att);  float* pATT  = (float*)tp;
    cudaGetSymbolAddress(&tp, g_msim); float* pMSIM = (float*)tp;
    cudaGetSymbolAddress(&tp, g_o);    float* pO    = (float*)tp;
    cudaGetSymbolAddress(&tp, g_ff);   float* pFF   = (float*)tp;
    cudaGetSymbolAddress(&tp, g_mv);   float* pMV   = (float*)tp;
    cudaGetSymbolAddress(&tp, g_mi);   int*   pMI   = (int*)tp;
    cudaGetSymbolAddress(&tp, g_feats);float* pFeat = (float*)tp;

    // raise dynamic smem limit for the 3x-split instantiations (53.2 KB)
    cudaFuncSetAttribute(mma3_k<false,false,3>, cudaFuncAttributeMaxDynamicSharedMemorySize, SMEM3);
    cudaFuncSetAttribute(mma3_k<true, false,3>, cudaFuncAttributeMaxDynamicSharedMemorySize, SMEM3);
    cudaFuncSetAttribute(mma3_k<false,true, 3>, cudaFuncAttributeMaxDynamicSharedMemorySize, SMEM3);
    cudaFuncSetAttribute(mma3_k<true, false,1>, cudaFuncAttributeMaxDynamicSharedMemorySize, SMEM1);

    // patch embed
    patchify_k<<<(int)(((long)ROWS * PDIM + 255) / 256), 256>>>(x, pP);
    mma3_k<false,false,3><<<dim3(1, 98, 1), 256, SMEM3>>>(pP, patch_w, patch_b, nullptr, pH,
        ROWS, DMODEL, PDIM, 0, PDIM, 0, DMODEL, 0, DMODEL, 1.f);

    for (int i = 0; i < DEPTH; i++) {
        ln_k<<<ROWS, 128>>>(pH, ln1_g + i * DMODEL, ln1_b + i * DMODEL, pY);
        mma3_k<false,false,3><<<dim3(3, 98, 1), 256, SMEM3>>>(pY, qkv_w + (long)i * DMODEL * 3 * DMODEL,
            qkv_b + i * 3 * DMODEL, nullptr, pQKV,
            ROWS, 3 * DMODEL, DMODEL, 0, DMODEL, 0, 3 * DMODEL, 0, 3 * DMODEL, 1.f);
        // sim = q @ k^T * scale  (batched TB)
        mma3_k<true,false,3><<<dim3(2, 4, BATCH), 256, SMEM3>>>(pQKV, pQKV + 128, nullptr, nullptr, pATT,
            NTOK, NTOK, DMODEL,
            (long)NTOK * 384, 384, (long)NTOK * 384, 384, (long)NTOK * NTOK, NTOK, SCALE);

        if (i == KNN_LAYER) {
            // msim = q @ knn_k^T * scale  (batched TB, N=8192) — 1xTF32
            mma3_k<true,false,1><<<dim3(64, 4, BATCH), 256, SMEM1>>>(pQKV, knn_k, nullptr, nullptr, pMSIM,
                NTOK, MKEYS, DMODEL,
                (long)NTOK * 384, 384, (long)MKEYS * DMODEL, DMODEL, (long)NTOK * MKEYS, MKEYS, SCALE);
            topk_k<<<ROWS, 256>>>(pMSIM, pMV, pMI);
            knn_combine_k<<<ROWS, 128>>>(pATT, pMV, pMI, pQKV, knn_v, pO);
        } else {
            softmax196_k<<<ROWS, 256>>>(pATT);
            // o = attn @ v  (batched NN, K=196)
            mma3_k<false,false,3><<<dim3(1, 4, BATCH), 256, SMEM3>>>(pATT, pQKV + 256, nullptr, nullptr, pO,
                NTOK, DMODEL, NTOK,
                (long)NTOK * NTOK, NTOK, (long)NTOK * 384, 384, (long)NTOK * DMODEL, DMODEL, 1.f);
        }

        // h = h + o @ out_w + out_b
        mma3_k<false,false,3><<<dim3(1, 98, 1), 256, SMEM3>>>(pO, out_w + (long)i * DMODEL * DMODEL,
            out_b + i * DMODEL, pH, pH,
            ROWS, DMODEL, DMODEL, 0, DMODEL, 0, DMODEL, 0, DMODEL, 1.f);

        ln_k<<<ROWS, 128>>>(pH, ln2_g + i * DMODEL, ln2_b + i * DMODEL, pY);
        // ff1 + gelu
        mma3_k<false,true,3><<<dim3(4, 98, 1), 256, SMEM3>>>(pY, ff1_w + (long)i * DMODEL * FFH,
            ff1_b + i * FFH, nullptr, pFF,
            ROWS, FFH, DMODEL, 0, DMODEL, 0, FFH, 0, FFH, 1.f);
        // h = h + ff @ ff2_w + ff2_b
        mma3_k<false,false,3><<<dim3(1, 98, 1), 256, SMEM3>>>(pFF, ff2_w + (long)i * FFH * DMODEL,
            ff2_b + i * DMODEL, pH, pH,
            ROWS, DMODEL, FFH, 0, FFH, 0, DMODEL, 0, DMODEL, 1.f);
    }

    ln_k<<<ROWS, 128>>>(pH, lnf_g, lnf_b, pY);
    mean_k<<<BATCH, 128>>>(pY, pFeat);
    mma3_k<false,false,3><<<dim3(8, 1, 1), 256, SMEM3>>>(pFeat, head_w, head_b, nullptr, out,
        BATCH, NCLS, DMODEL, 0, DMODEL, 0, NCLS, 0, NCLS, 1.f);
}

// round 5
// speedup vs baseline: 2.1100x; 1.0046x over previous
#include <cuda_runtime.h>
#include <cuda_bf16.h>
#include <math.h>

// ---------------- problem constants ----------------
#define BATCH   32
#define NTOK    196
#define DMODEL  128
#define ROWS    (BATCH*NTOK) // 6272
#define PDIM    768
#define DEPTH   7
#define KNN_LAYER 6
#define MKEYS   8192
#define TOPK    32
#define FFH     512
#define NCLS    1000
#define SCALE   0.08838834764831845f
#define LNEPS   1e-5f

// ---------------- device scratch ----------------
__device__ float g_p   [ (long)ROWS*PDIM ];
__device__ float g_h   [ (long)ROWS*DMODEL ];
__device__ float g_y   [ (long)ROWS*DMODEL ];
__device__ float g_qkv [ (long)ROWS*3*DMODEL ];
__device__ float g_att [ (long)BATCH*NTOK*NTOK ];
__device__ float g_msim[ (long)BATCH*NTOK*MKEYS ];
__device__ float g_o   [ (long)ROWS*DMODEL ];
__device__ float g_ff  [ (long)ROWS*FFH ];
__device__ float g_mv  [ (long)ROWS*TOPK ];
__device__ int   g_mi  [ (long)ROWS*TOPK ];
__device__ float g_feats[ BATCH*DMODEL ];

// ---------------- helpers ----------------
__device__ __forceinline__ float gelu_tanh(float v) {
    const float c = 0.7978845608028654f;
    float t = tanhf(c * (v + 0.044715f * v * v * v));
    return 0.5f * v * (1.f + t);
}
__device__ __forceinline__ unsigned f2tf32(float f) {
    unsigned u;
    asm("cvt.rna.tf32.f32 %0, %1;" : "=r"(u) : "f"(f));
    return u;
}
#define MMA_TF32(ACC, AF, BF)                                              \
    asm volatile(                                                          \
        "mma.sync.aligned.m16n8k8.row.col.f32.tf32.tf32.f32 "              \
        "{%0,%1,%2,%3}, {%4,%5,%6,%7}, {%8,%9}, {%0,%1,%2,%3};"            \
        : "+f"((ACC)[0]), "+f"((ACC)[1]), "+f"((ACC)[2]), "+f"((ACC)[3])   \
        : "r"((AF)[0]), "r"((AF)[1]), "r"((AF)[2]), "r"((AF)[3]),          \
          "r"((BF)[0]), "r"((BF)[1]))

// ---------------- patchify ----------------
__global__ void patchify_k(const float* __restrict__ x, float* __restrict__ p) {
    long e = (long)blockIdx.x * 256 + threadIdx.x;
    if (e >= (long)ROWS * PDIM) return;
    int c   = (int)(e % PDIM);
    long row = e / PDIM;
    int b = (int)(row / NTOK), n = (int)(row % NTOK);
    int i = n / 14, j = n % 14;
    int ch = c / 256, r = c % 256, pi = r / 16, pj = r % 16;
    p[e] = x[(((long)b*3 + ch)*224 + (i*16 + pi))*224 + (j*16 + pj)];
}

// ---------------- unified TF32 mma GEMM (SPLIT=3: ~fp32, SPLIT=1: tf32) ------
#define APAD 36
#define BPAD 136
template<bool TB, bool DOGELU, int SPLIT>
__global__ void __launch_bounds__(256, 2)
mma3_k(const float* __restrict__ A, const float* __restrict__ Bm,
       const float* __restrict__ bias, const float* __restrict__ Res,
       float* __restrict__ C,
       int Mr, int Nc, int K,
       long sAb, int lda, long sBb, int ldb, long sCb, int ldc,
       float alpha)
{
    extern __shared__ unsigned smem_u[];
    unsigned* Ah = smem_u;
    unsigned* Al;
    unsigned* Bh;
    unsigned* Bl;
    if (SPLIT == 3) {
        Al = Ah + 64 * APAD;
        Bh = Al + 64 * APAD;
        Bl = Bh + 32 * BPAD;
    } else {
        Al = nullptr;
        Bh = Ah + 64 * APAD;
        Bl = nullptr;
    }

    int bz = blockIdx.z;
    const float* Ab = A + (long)bz * sAb;
    const float* Bb = Bm + (long)bz * sBb;
    float*       Cb = C + (long)bz * sCb;
    const float* Rb = Res ? (Res + (long)bz * sCb) : nullptr;

    int row0 = blockIdx.y * 64;
    int col0 = blockIdx.x * 128;
    int tid = threadIdx.x;
    int lane = tid & 31, warp = tid >> 5;
    int wm = warp >> 2, wn = warp & 3;
    int g = lane >> 2, tg = lane & 3;

    int ar = tid >> 3, ak = (tid & 7) * 4;
    int bkNN = tid >> 5, bnNN = (tid & 31) * 4;
    int bnTB = tid >> 3, bkTB = (tid & 7) * 4;

    float4 pa[2], pb[4];

    auto loadA = [&](int k0) {
        #pragma unroll
        for (int p = 0; p < 2; p++) {
            int gr = row0 + ar + p * 32, gk = k0 + ak;
            float4 v = make_float4(0.f, 0.f, 0.f, 0.f);
            if (gr < Mr) {
                if (gk + 3 < K) v = *(const float4*)&Ab[(long)gr * lda + gk];
                else {
                    if (gk + 0 < K) v.x = Ab[(long)gr * lda + gk + 0];
                    if (gk + 1 < K) v.y = Ab[(long)gr * lda + gk + 1];
                    if (gk + 2 < K) v.z = Ab[(long)gr * lda + gk + 2];
                    if (gk + 3 < K) v.w = Ab[(long)gr * lda + gk + 3];
                }
            }
            pa[p] = v;
        }
    };
    auto loadB = [&](int k0) {
        if (TB) {
            #pragma unroll
            for (int p = 0; p < 4; p++) {
                int gn = col0 + bnTB + p * 32, gk = k0 + bkTB;
                float4 v = make_float4(0.f, 0.f, 0.f, 0.f);
                if (gn < Nc) {
                    if (gk + 3 < K) v = *(const float4*)&Bb[(long)gn * ldb + gk];
                    else {
                        if (gk + 0 < K) v.x = Bb[(long)gn * ldb + gk + 0];
                        if (gk + 1 < K) v.y = Bb[(long)gn * ldb + gk + 1];
                        if (gk + 2 < K) v.z = Bb[(long)gn * ldb + gk + 2];
                        if (gk + 3 < K) v.w = Bb[(long)gn * ldb + gk + 3];
                    }
                }
                pb[p] = v;
            }
        } else {
            #pragma unroll
            for (int p = 0; p < 4; p++) {
                int gk = k0 + bkNN + p * 8, gn = col0 + bnNN;
                float4 v = make_float4(0.f, 0.f, 0.f, 0.f);
                if (gk < K) {
                    if (gn + 3 < Nc) v = *(const float4*)&Bb[(long)gk * ldb + gn];
                    else {
                        if (gn + 0 < Nc) v.x = Bb[(long)gk * ldb + gn + 0];
                        if (gn + 1 < Nc) v.y = Bb[(long)gk * ldb + gn + 1];
                        if (gn + 2 < Nc) v.z = Bb[(long)gk * ldb + gn + 2];
                        if (gn + 3 < Nc) v.w = Bb[(long)gk * ldb + gn + 3];
                    }
                }
                pb[p] = v;
            }
        }
    };
    auto storeTiles = [&]() {
        #pragma unroll
        for (int p = 0; p < 2; p++) {
            int r = ar + p * 32;
            float vv[4] = {pa[p].x, pa[p].y, pa[p].z, pa[p].w};
            #pragma unroll
            for (int j = 0; j < 4; j++) {
                unsigned h = f2tf32(vv[j]);
                Ah[r * APAD + ak + j] = h;
                if (SPLIT == 3) Al[r * APAD + ak + j] = f2tf32(vv[j] - __uint_as_float(h));
            }
        }
        if (TB) {
            #pragma unroll
            for (int p = 0; p < 4; p++) {
                int n = bnTB + p * 32;
                float vv[4] = {pb[p].x, pb[p].y, pb[p].z, pb[p].w};
                #pragma unroll
                for (int j = 0; j < 4; j++) {
                    unsigned h = f2tf32(vv[j]);
                    Bh[(bkTB + j) * BPAD + n] = h;
                    if (SPLIT == 3) Bl[(bkTB + j) * BPAD + n] = f2tf32(vv[j] - __uint_as_float(h));
                }
            }
        } else {
            #pragma unroll
            for (int p = 0; p < 4; p++) {
                int k = bkNN + p * 8;
                float vv[4] = {pb[p].x, pb[p].y, pb[p].z, pb[p].w};
                #pragma unroll
                for (int j = 0; j < 4; j++) {
                    unsigned h = f2tf32(vv[j]);
                    Bh[k * BPAD + bnNN + j] = h;
                    if (SPLIT == 3) Bl[k * BPAD + bnNN + j] = f2tf32(vv[j] - __uint_as_float(h));
                }
            }
        }
    };

    float acc[2][4][4];
    #pragma unroll
    for (int im = 0; im < 2; im++)
        #pragma unroll
        for (int jn = 0; jn < 4; jn++)
            #pragma unroll
            for (int c = 0; c < 4; c++) acc[im][jn][c] = 0.f;

    loadA(0); loadB(0);

    for (int k0 = 0; k0 < K; k0 += 32) {
        storeTiles();
        __syncthreads();
        if (k0 + 32 < K) { loadA(k0 + 32); loadB(k0 + 32); }

        #pragma unroll
        for (int ks = 0; ks < 32; ks += 8) {
            unsigned ah[2][4], al_[2][4], bh[4][2], bl_[4][2];
            #pragma unroll
            for (int im = 0; im < 2; im++) {
                int mb = wm * 32 + im * 16;
                ah[im][0] = Ah[(mb + g    ) * APAD + ks +     tg];
                ah[im][1] = Ah[(mb + g + 8) * APAD + ks +     tg];
                ah[im][2] = Ah[(mb + g    ) * APAD + ks + 4 + tg];
                ah[im][3] = Ah[(mb + g + 8) * APAD + ks + 4 + tg];
                if (SPLIT == 3) {
                    al_[im][0] = Al[(mb + g    ) * APAD + ks +     tg];
                    al_[im][1] = Al[(mb + g + 8) * APAD + ks +     tg];
                    al_[im][2] = Al[(mb + g    ) * APAD + ks + 4 + tg];
                    al_[im][3] = Al[(mb + g + 8) * APAD + ks + 4 + tg];
                }
            }
            #pragma unroll
            for (int jn = 0; jn < 4; jn++) {
                int nb = wn * 32 + jn * 8;
                bh[jn][0] = Bh[(ks +     tg) * BPAD + nb + g];
                bh[jn][1] = Bh[(ks + 4 + tg) * BPAD + nb + g];
                if (SPLIT == 3) {
                    bl_[jn][0] = Bl[(ks +     tg) * BPAD + nb + g];
                    bl_[jn][1] = Bl[(ks + 4 + tg) * BPAD + nb + g];
                }
            }
            #pragma unroll
            for (int im = 0; im < 2; im++)
                #pragma unroll
                for (int jn = 0; jn < 4; jn++) {
                    if (SPLIT == 3) {
                        MMA_TF32(acc[im][jn], ah[im], bl_[jn]);
                        MMA_TF32(acc[im][jn], al_[im], bh[jn]);
                    }
                    MMA_TF32(acc[im][jn], ah[im], bh[jn]);
                }
        }
        __syncthreads();
    }

    #pragma unroll
    for (int im = 0; im < 2; im++) {
        #pragma unroll
        for (int jn = 0; jn < 4; jn++) {
            int r0 = row0 + wm * 32 + im * 16 + g;
            int c0 = col0 + wn * 32 + jn * 8 + 2 * tg;
            #pragma unroll
            for (int half = 0; half < 2; half++) {
                int gr = r0 + half * 8;
                if (gr >= Mr) continue;
                #pragma unroll
                for (int cc = 0; cc < 2; cc++) {
                    int gn = c0 + cc;
                    if (gn >= Nc) continue;
                    float v = acc[im][jn][half * 2 + cc] * alpha;
                    if (bias) v += bias[gn];
                    if (Rb)   v += Rb[(long)gr * ldc + gn];
                    if (DOGELU) v = gelu_tanh(v);
                    Cb[(long)gr * ldc + gn] = v;
                }
            }
        }
    }
}

#define SMEM3 ((64*APAD*2 + 32*BPAD*2) * 4)
#define SMEM1 ((64*APAD + 32*BPAD) * 4)

// ---------------- layernorm over D=128 ----------------
__global__ void ln_k(const float* __restrict__ in, const float* __restrict__ g,
                     const float* __restrict__ b, float* __restrict__ out)
{
    long row = blockIdx.x;
    int t = threadIdx.x;
    float v = in[row * DMODEL + t];
    __shared__ float red[4];
    float s = v;
    #pragma unroll
    for (int o = 16; o > 0; o >>= 1) s += __shfl_xor_sync(0xffffffffu, s, o);
    if ((t & 31) == 0) red[t >> 5] = s;
    __syncthreads();
    float mu = (red[0] + red[1] + red[2] + red[3]) * (1.f / 128.f);
    float d = v - mu;
    __syncthreads();
    float s2 = d * d;
    #pragma unroll
    for (int o = 16; o > 0; o >>= 1) s2 += __shfl_xor_sync(0xffffffffu, s2, o);
    if ((t & 31) == 0) red[t >> 5] = s2;
    __syncthreads();
    float var = (red[0] + red[1] + red[2] + red[3]) * (1.f / 128.f);
    out[row * DMODEL + t] = d / sqrtf(var + LNEPS) * g[t] + b[t];
}

// ---------------- softmax over 196 ----------------
__global__ void softmax196_k(float* __restrict__ att)
{
    long row = blockIdx.x;
    int t = threadIdx.x;
    float* a = att + row * NTOK;
    float v = (t < NTOK) ? a[t] : -3.4e38f;
    __shared__ float red[8];
    float m = v;
    #pragma unroll
    for (int o = 16; o > 0; o >>= 1) m = fmaxf(m, __shfl_xor_sync(0xffffffffu, m, o));
    if ((t & 31) == 0) red[t >> 5] = m;
    __syncthreads();
    m = red[0];
    #pragma unroll
    for (int i = 1; i < 8; i++) m = fmaxf(m, red[i]);
    float e = (t < NTOK) ? expf(v - m) : 0.f;
    __syncthreads();
    float s = e;
    #pragma unroll
    for (int o = 16; o > 0; o >>= 1) s += __shfl_xor_sync(0xffffffffu, s, o);
    if ((t & 31) == 0) red[t >> 5] = s;
    __syncthreads();
    s = red[0];
    #pragma unroll
    for (int i = 1; i < 8; i++) s += red[i];
    if (t < NTOK) a[t] = e / s;
}

// ---------------- top-32: register-resident incremental argmax ----------------
// Each thread owns 32 contiguous elements in registers. Extract global max 32x;
// only the winning thread recomputes its local max. 1 barrier per round.
__global__ void __launch_bounds__(256) topk_k(const float* __restrict__ msim,
                       float* __restrict__ mvals, int* __restrict__ midx)
{
    long row = blockIdx.x;
    int tid = threadIdx.x;
    int lane = tid & 31, wid = tid >> 5;
    const float* src = msim + row * MKEYS;

    float v[32];
    const float4* s4 = (const float4*)(src + tid * 32);
    #pragma unroll
    for (int i = 0; i < 8; i++) {
        float4 t = s4[i];
        v[i*4+0] = t.x; v[i*4+1] = t.y; v[i*4+2] = t.z; v[i*4+3] = t.w;
    }

    // packed key: ordered float bits << 32 | (MKEYS-1 - global_idx)  (max => larger value, then smaller idx)
    unsigned long long p = 0ull;
    #pragma unroll
    for (int i = 0; i < 32; i++) {
        unsigned u = __float_as_uint(v[i]);
        u = (u & 0x80000000u) ? ~u : (u | 0x80000000u);
        unsigned long long key = ((unsigned long long)u << 32) | (unsigned)(MKEYS - 1 - (tid * 32 + i));
        if (key > p) p = key;
    }

    __shared__ unsigned long long wmax[2][8];

    for (int it = 0; it < TOPK; it++) {
        unsigned long long q = p;
        #pragma unroll
        for (int o = 16; o > 0; o >>= 1) {
            unsigned long long other = __shfl_xor_sync(0xffffffffu, q, o);
            if (other > q) q = other;
        }
        if (lane == 0) wmax[it & 1][wid] = q;
        __syncthreads();
        unsigned long long best = wmax[it & 1][0];
        #pragma unroll
        for (int w = 1; w < 8; w++) {
            unsigned long long o2 = wmax[it & 1][w];
            if (o2 > best) best = o2;
        }
        int gidx = MKEYS - 1 - (int)(best & 0xffffffffu);
        if (tid == (gidx >> 5)) {
            int sub = gidx & 31;
            float bv = 0.f;
            #pragma unroll
            for (int i = 0; i < 32; i++)
                if (i == sub) { bv = v[i]; v[i] = -3.4e38f; }
            mvals[row * TOPK + it] = bv;
            midx [row * TOPK + it] = gidx;
            unsigned long long np = 0ull;
            #pragma unroll
            for (int i = 0; i < 32; i++) {
                unsigned u = __float_as_uint(v[i]);
                u = (u & 0x80000000u) ? ~u : (u | 0x80000000u);
                unsigned long long key = ((unsigned long long)u << 32) | (unsigned)(MKEYS - 1 - (tid * 32 + i));
                if (key > np) np = key;
            }
            p = np;
        }
    }
}

// ---------------- kNN combine ----------------
__global__ void knn_combine_k(const float* __restrict__ att,
                              const float* __restrict__ mvals, const int* __restrict__ midx,
                              const float* __restrict__ qkv, const float* __restrict__ knn_v,
                              float* __restrict__ out)
{
    long row = blockIdx.x;
    int b = (int)(row / NTOK);
    int tid = threadIdx.x;
    __shared__ float w[TOPK + NTOK];
    __shared__ int   sidx[TOPK];
    __shared__ float red[4];

    if (tid < TOPK) {
        w[tid]    = mvals[row * TOPK + tid];
        sidx[tid] = midx [row * TOPK + tid];
    }
    for (int m = tid; m < NTOK; m += 128) w[TOPK + m] = att[row * NTOK + m];
    __syncthreads();

    float l0 = w[tid];
    float l1 = (tid < (TOPK + NTOK - 128)) ? w[tid + 128] : -3.4e38f;
    float m = fmaxf(l0, l1);
    #pragma unroll
    for (int o = 16; o > 0; o >>= 1) m = fmaxf(m, __shfl_xor_sync(0xffffffffu, m, o));
    if ((tid & 31) == 0) red[tid >> 5] = m;
    __syncthreads();
    m = fmaxf(fmaxf(red[0], red[1]), fmaxf(red[2], red[3]));
    float e0 = expf(l0 - m);
    float e1 = (tid < (TOPK + NTOK - 128)) ? expf(l1 - m) : 0.f;
    float s = e0 + e1;
    __syncthreads();
    #pragma unroll
    for (int o = 16; o > 0; o >>= 1) s += __shfl_xor_sync(0xffffffffu, s, o);
    if ((tid & 31) == 0) red[tid >> 5] = s;
    __syncthreads();
    s = red[0] + red[1] + red[2] + red[3];
    float inv = 1.f / s;
    w[tid] = e0 * inv;
    if (tid < (TOPK + NTOK - 128)) w[tid + 128] = e1 * inv;
    __syncthreads();

    float acc = 0.f;
    const float* kv = knn_v + (long)b * MKEYS * DMODEL;
    #pragma unroll 4
    for (int j = 0; j < TOPK; j++)
        acc += w[j] * kv[(long)sidx[j] * DMODEL + tid];
    const float* vbase = qkv + ((long)b * NTOK) * 384 + 256;
    for (int mm = 0; mm < NTOK; mm++)
        acc += w[TOPK + mm] * vbase[(long)mm * 384 + tid];
    out[row * DMODEL + tid] = acc;
}

// ---------------- mean pool ----------------
__global__ void mean_k(const float* __restrict__ y, float* __restrict__ feats)
{
    int b = blockIdx.x, d = threadIdx.x;
    float s = 0.f;
    for (int n = 0; n < NTOK; n++) s += y[((long)b * NTOK + n) * DMODEL + d];
    feats[b * DMODEL + d] = s * (1.f / 196.f);
}

// ---------------- launch ----------------
extern "C" void kernel_launch(void* const* d_in, const int* in_sizes, int n_in,
                              void* d_out, int out_size)
{
    const float* x       = (const float*)d_in[0];
    const float* patch_w = (const float*)d_in[1];
    const float* patch_b = (const float*)d_in[2];
    const float* ln1_g   = (const float*)d_in[3];
    const float* ln1_b   = (const float*)d_in[4];
    const float* qkv_w   = (const float*)d_in[5];
    const float* qkv_b   = (const float*)d_in[6];
    const float* out_w   = (const float*)d_in[7];
    const float* out_b   = (const float*)d_in[8];
    const float* ln2_g   = (const float*)d_in[9];
    const float* ln2_b   = (const float*)d_in[10];
    const float* ff1_w   = (const float*)d_in[11];
    const float* ff1_b   = (const float*)d_in[12];
    const float* ff2_w   = (const float*)d_in[13];
    const float* ff2_b   = (const float*)d_in[14];
    const float* lnf_g   = (const float*)d_in[15];
    const float* lnf_b   = (const float*)d_in[16];
    const float* knn_k   = (const float*)d_in[17];
    const float* knn_v   = (const float*)d_in[18];
    const float* head_w  = (const float*)d_in[19];
    const float* head_b  = (const float*)d_in[20];
    float* out = (float*)d_out;

    void* tp;
    cudaGetSymbolAddress(&tp, g_p);    float* pP    = (float*)tp;
    cudaGetSymbolAddress(&tp, g_h);    float* pH    = (float*)tp;
    cudaGetSymbolAddress(&tp, g_y);    float* pY    = (float*)tp;
    cudaGetSymbolAddress(&tp, g_qkv);  float* pQKV  = (float*)tp;
    cudaGetSymbolAddress(&tp, g_att);  float* pATT  = (float*)tp;
    cudaGetSymbolAddress(&tp, g_msim); float* pMSIM = (float*)tp;
    cudaGetSymbolAddress(&tp, g_o);    float* pO    = (float*)tp;
    cudaGetSymbolAddress(&tp, g_ff);   float* pFF   = (float*)tp;
    cudaGetSymbolAddress(&tp, g_mv);   float* pMV   = (float*)tp;
    cudaGetSymbolAddress(&tp, g_mi);   int*   pMI   = (int*)tp;
    cudaGetSymbolAddress(&tp, g_feats);float* pFeat = (float*)tp;

    cudaFuncSetAttribute(mma3_k<false,false,3>, cudaFuncAttributeMaxDynamicSharedMemorySize, SMEM3);
    cudaFuncSetAttribute(mma3_k<true, false,3>, cudaFuncAttributeMaxDynamicSharedMemorySize, SMEM3);
    cudaFuncSetAttribute(mma3_k<false,true, 3>, cudaFuncAttributeMaxDynamicSharedMemorySize, SMEM3);
    cudaFuncSetAttribute(mma3_k<true, false,1>, cudaFuncAttributeMaxDynamicSharedMemorySize, SMEM1);

    // patch embed
    patchify_k<<<(int)(((long)ROWS * PDIM + 255) / 256), 256>>>(x, pP);
    mma3_k<false,false,3><<<dim3(1, 98, 1), 256, SMEM3>>>(pP, patch_w, patch_b, nullptr, pH,
        ROWS, DMODEL, PDIM, 0, PDIM, 0, DMODEL, 0, DMODEL, 1.f);

    for (int i = 0; i < DEPTH; i++) {
        ln_k<<<ROWS, 128>>>(pH, ln1_g + i * DMODEL, ln1_b + i * DMODEL, pY);
        mma3_k<false,false,3><<<dim3(3, 98, 1), 256, SMEM3>>>(pY, qkv_w + (long)i * DMODEL * 3 * DMODEL,
            qkv_b + i * 3 * DMODEL, nullptr, pQKV,
            ROWS, 3 * DMODEL, DMODEL, 0, DMODEL, 0, 3 * DMODEL, 0, 3 * DMODEL, 1.f);
        // sim = q @ k^T * scale  (batched TB)
        mma3_k<true,false,3><<<dim3(2, 4, BATCH), 256, SMEM3>>>(pQKV, pQKV + 128, nullptr, nullptr, pATT,
            NTOK, NTOK, DMODEL,
            (long)NTOK * 384, 384, (long)NTOK * 384, 384, (long)NTOK * NTOK, NTOK, SCALE);

        if (i == KNN_LAYER) {
            // msim = q @ knn_k^T * scale  (batched TB, N=8192) — 1xTF32
            mma3_k<true,false,1><<<dim3(64, 4, BATCH), 256, SMEM1>>>(pQKV, knn_k, nullptr, nullptr, pMSIM,
                NTOK, MKEYS, DMODEL,
                (long)NTOK * 384, 384, (long)MKEYS * DMODEL, DMODEL, (long)NTOK * MKEYS, MKEYS, SCALE);
            topk_k<<<ROWS, 256>>>(pMSIM, pMV, pMI);
            knn_combine_k<<<ROWS, 128>>>(pATT, pMV, pMI, pQKV, knn_v, pO);
        } else {
            softmax196_k<<<ROWS, 256>>>(pATT);
            // o = attn @ v  (batched NN, K=196)
            mma3_k<false,false,3><<<dim3(1, 4, BATCH), 256, SMEM3>>>(pATT, pQKV + 256, nullptr, nullptr, pO,
                NTOK, DMODEL, NTOK,
                (long)NTOK * NTOK, NTOK, (long)NTOK * 384, 384, (long)NTOK * DMODEL, DMODEL, 1.f);
        }

        // h = h + o @ out_w + out_b
        mma3_k<false,false,3><<<dim3(1, 98, 1), 256, SMEM3>>>(pO, out_w + (long)i * DMODEL * DMODEL,
            out_b + i * DMODEL, pH, pH,
            ROWS, DMODEL, DMODEL, 0, DMODEL, 0, DMODEL, 0, DMODEL, 1.f);

        ln_k<<<ROWS, 128>>>(pH, ln2_g + i * DMODEL, ln2_b + i * DMODEL, pY);
        // ff1 + gelu
        mma3_k<false,true,3><<<dim3(4, 98, 1), 256, SMEM3>>>(pY, ff1_w + (long)i * DMODEL * FFH,
            ff1_b + i * FFH, nullptr, pFF,
            ROWS, FFH, DMODEL, 0, DMODEL, 0, FFH, 0, FFH, 1.f);
        // h = h + ff @ ff2_w + ff2_b
        mma3_k<false,false,3><<<dim3(1, 98, 1), 256, SMEM3>>>(pFF, ff2_w + (long)i * FFH * DMODEL,
            ff2_b + i * DMODEL, pH, pH,
            ROWS, DMODEL, FFH, 0, FFH, 0, DMODEL, 0, DMODEL, 1.f);
    }

    ln_k<<<ROWS, 128>>>(pH, lnf_g, lnf_b, pY);
    mean_k<<<BATCH, 128>>>(pY, pFeat);
    mma3_k<false,false,3><<<dim3(8, 1, 1), 256, SMEM3>>>(pFeat, head_w, head_b, nullptr, out,
        BATCH, NCLS, DMODEL, 0, DMODEL, 0, NCLS, 0, NCLS, 1.f);
}

// round 7
// speedup vs baseline: 2.1397x; 1.0140x over previous
#include <cuda_runtime.h>
#include <cuda_bf16.h>
#include <math.h>

// ---------------- problem constants ----------------
#define BATCH   32
#define NTOK    196
#define DMODEL  128
#define ROWS    (BATCH*NTOK) // 6272
#define PDIM    768
#define DEPTH   7
#define KNN_LAYER 6
#define MKEYS   8192
#define TOPK    32
#define FFH     512
#define NCLS    1000
#define SCALE   0.08838834764831845f
#define LNEPS   1e-5f

// ---------------- device scratch ----------------
__device__ float g_p   [ (long)ROWS*PDIM ];
__device__ float g_h   [ (long)ROWS*DMODEL ];
__device__ float g_y   [ (long)ROWS*DMODEL ];
__device__ float g_qkv [ (long)ROWS*3*DMODEL ];
__device__ float g_att [ (long)BATCH*NTOK*NTOK ];
__device__ float g_msim[ (long)BATCH*NTOK*MKEYS ];
__device__ float g_o   [ (long)ROWS*DMODEL ];
__device__ float g_ff  [ (long)ROWS*FFH ];
__device__ float g_part[ (long)6*ROWS*DMODEL ];   // split-K partials
__device__ float g_mv  [ (long)ROWS*TOPK ];
__device__ int   g_mi  [ (long)ROWS*TOPK ];
__device__ float g_feats[ BATCH*DMODEL ];

// ---------------- helpers ----------------
__device__ __forceinline__ float gelu_tanh(float v) {
    const float c = 0.7978845608028654f;
    float t = tanhf(c * (v + 0.044715f * v * v * v));
    return 0.5f * v * (1.f + t);
}
__device__ __forceinline__ unsigned f2tf32(float f) {
    unsigned u;
    asm("cvt.rna.tf32.f32 %0, %1;" : "=r"(u) : "f"(f));
    return u;
}
#define MMA_TF32(ACC, AF, BF)                                              \
    asm volatile(                                                          \
        "mma.sync.aligned.m16n8k8.row.col.f32.tf32.tf32.f32 "              \
        "{%0,%1,%2,%3}, {%4,%5,%6,%7}, {%8,%9}, {%0,%1,%2,%3};"            \
        : "+f"((ACC)[0]), "+f"((ACC)[1]), "+f"((ACC)[2]), "+f"((ACC)[3])   \
        : "r"((AF)[0]), "r"((AF)[1]), "r"((AF)[2]), "r"((AF)[3]),          \
          "r"((BF)[0]), "r"((BF)[1]))

// ---------------- patchify ----------------
__global__ void patchify_k(const float* __restrict__ x, float* __restrict__ p) {
    long e = (long)blockIdx.x * 256 + threadIdx.x;
    if (e >= (long)ROWS * PDIM) return;
    int c   = (int)(e % PDIM);
    long row = e / PDIM;
    int b = (int)(row / NTOK), n = (int)(row % NTOK);
    int i = n / 14, j = n % 14;
    int ch = c / 256, r = c % 256, pi = r / 16, pj = r % 16;
    p[e] = x[(((long)b*3 + ch)*224 + (i*16 + pi))*224 + (j*16 + pj)];
}

// ---------------- unified TF32 mma GEMM (SPLIT=3: ~fp32, SPLIT=1: tf32) ------
// Block tile 64(M) x 128(N), K-chunk 32, 2-stage double-buffered smem.
// grid.z = nbatch * kslices (kslices>1 => write raw partials, no bias/res/gelu).
#define APAD 36
#define BPAD 136
#define WORDS3 (64*APAD*2 + 32*BPAD*2)
#define WORDS1 (64*APAD + 32*BPAD)
#define SMEM3 (WORDS3 * 8)   // x2 stages x4 bytes
#define SMEM1 (WORDS1 * 8)

template<bool TB, bool DOGELU, int SPLIT>
__global__ void __launch_bounds__(256, 2)
mma3_k(const float* __restrict__ A, const float* __restrict__ Bm,
       const float* __restrict__ bias, const float* __restrict__ Res,
       float* __restrict__ C,
       int Mr, int Nc, int K,
       long sAb, int lda, long sBb, int ldb, long sCb, int ldc,
       float alpha, int nbatch, int kslices, long sPart)
{
    extern __shared__ unsigned smem_u[];
    const int WORDS = (SPLIT == 3) ? WORDS3 : WORDS1;

    int bz = blockIdx.z;
    int batch = bz % nbatch;
    int ksl   = bz / nbatch;
    int Kslice = K / kslices;
    int Klo = ksl * Kslice;
    int Khi = (ksl == kslices - 1) ? K : Klo + Kslice;

    const float* Ab = A + (long)batch * sAb;
    const float* Bb = Bm + (long)batch * sBb;
    float*       Cb;
    const float* Rb;
    if (kslices > 1) {
        Cb = C + (long)ksl * sPart + (long)batch * sCb;
        Rb = nullptr;
    } else {
        Cb = C + (long)batch * sCb;
        Rb = Res ? (Res + (long)batch * sCb) : nullptr;
    }

    int row0 = blockIdx.y * 64;
    int col0 = blockIdx.x * 128;
    int tid = threadIdx.x;
    int lane = tid & 31, warp = tid >> 5;
    int wm = warp >> 2, wn = warp & 3;
    int g = lane >> 2, tg = lane & 3;

    int ar = tid >> 3, ak = (tid & 7) * 4;
    int bkNN = tid >> 5, bnNN = (tid & 31) * 4;
    int bnTB = tid >> 3, bkTB = (tid & 7) * 4;

    float4 pa[2], pb[4];

    auto loadA = [&](int k0) {
        #pragma unroll
        for (int p = 0; p < 2; p++) {
            int gr = row0 + ar + p * 32, gk = k0 + ak;
            float4 v = make_float4(0.f, 0.f, 0.f, 0.f);
            if (gr < Mr) {
                if (gk + 3 < Khi) v = *(const float4*)&Ab[(long)gr * lda + gk];
                else {
                    if (gk + 0 < Khi) v.x = Ab[(long)gr * lda + gk + 0];
                    if (gk + 1 < Khi) v.y = Ab[(long)gr * lda + gk + 1];
                    if (gk + 2 < Khi) v.z = Ab[(long)gr * lda + gk + 2];
                    if (gk + 3 < Khi) v.w = Ab[(long)gr * lda + gk + 3];
                }
            }
            pa[p] = v;
        }
    };
    auto loadB = [&](int k0) {
        if (TB) {
            #pragma unroll
            for (int p = 0; p < 4; p++) {
                int gn = col0 + bnTB + p * 32, gk = k0 + bkTB;
                float4 v = make_float4(0.f, 0.f, 0.f, 0.f);
                if (gn < Nc) {
                    if (gk + 3 < Khi) v = *(const float4*)&Bb[(long)gn * ldb + gk];
                    else {
                        if (gk + 0 < Khi) v.x = Bb[(long)gn * ldb + gk + 0];
                        if (gk + 1 < Khi) v.y = Bb[(long)gn * ldb + gk + 1];
                        if (gk + 2 < Khi) v.z = Bb[(long)gn * ldb + gk + 2];
                        if (gk + 3 < Khi) v.w = Bb[(long)gn * ldb + gk + 3];
                    }
                }
                pb[p] = v;
            }
        } else {
            #pragma unroll
            for (int p = 0; p < 4; p++) {
                int gk = k0 + bkNN + p * 8, gn = col0 + bnNN;
                float4 v = make_float4(0.f, 0.f, 0.f, 0.f);
                if (gk < Khi) {
                    if (gn + 3 < Nc) v = *(const float4*)&Bb[(long)gk * ldb + gn];
                    else {
                        if (gn + 0 < Nc) v.x = Bb[(long)gk * ldb + gn + 0];
                        if (gn + 1 < Nc) v.y = Bb[(long)gk * ldb + gn + 1];
                        if (gn + 2 < Nc) v.z = Bb[(long)gk * ldb + gn + 2];
                        if (gn + 3 < Nc) v.w = Bb[(long)gk * ldb + gn + 3];
                    }
                }
                pb[p] = v;
            }
        }
    };
    auto storeTiles = [&](int st) {
        unsigned* Ah = smem_u + st * WORDS;
        unsigned* Al = (SPLIT == 3) ? Ah + 64 * APAD : nullptr;
        unsigned* Bh = (SPLIT == 3) ? Al + 64 * APAD : Ah + 64 * APAD;
        unsigned* Bl = (SPLIT == 3) ? Bh + 32 * BPAD : nullptr;
        #pragma unroll
        for (int p = 0; p < 2; p++) {
            int r = ar + p * 32;
            float vv[4] = {pa[p].x, pa[p].y, pa[p].z, pa[p].w};
            #pragma unroll
            for (int j = 0; j < 4; j++) {
                unsigned h = f2tf32(vv[j]);
                Ah[r * APAD + ak + j] = h;
                if (SPLIT == 3) Al[r * APAD + ak + j] = f2tf32(vv[j] - __uint_as_float(h));
            }
        }
        if (TB) {
            #pragma unroll
            for (int p = 0; p < 4; p++) {
                int n = bnTB + p * 32;
                float vv[4] = {pb[p].x, pb[p].y, pb[p].z, pb[p].w};
                #pragma unroll
                for (int j = 0; j < 4; j++) {
                    unsigned h = f2tf32(vv[j]);
                    Bh[(bkTB + j) * BPAD + n] = h;
                    if (SPLIT == 3) Bl[(bkTB + j) * BPAD + n] = f2tf32(vv[j] - __uint_as_float(h));
                }
            }
        } else {
            #pragma unroll
            for (int p = 0; p < 4; p++) {
                int k = bkNN + p * 8;
                float vv[4] = {pb[p].x, pb[p].y, pb[p].z, pb[p].w};
                #pragma unroll
                for (int j = 0; j < 4; j++) {
                    unsigned h = f2tf32(vv[j]);
                    Bh[k * BPAD + bnNN + j] = h;
                    if (SPLIT == 3) Bl[k * BPAD + bnNN + j] = f2tf32(vv[j] - __uint_as_float(h));
                }
            }
        }
    };

    float acc[2][4][4];
    #pragma unroll
    for (int im = 0; im < 2; im++)
        #pragma unroll
        for (int jn = 0; jn < 4; jn++)
            #pragma unroll
            for (int c = 0; c < 4; c++) acc[im][jn][c] = 0.f;

    int nch = (Khi - Klo + 31) / 32;
    int stage = 0;

    loadA(Klo); loadB(Klo);
    storeTiles(0);
    __syncthreads();

    for (int c = 0; c < nch; c++) {
        if (c + 1 < nch) { loadA(Klo + (c + 1) * 32); loadB(Klo + (c + 1) * 32); }

        {
            unsigned* Ah = smem_u + stage * WORDS;
            unsigned* Al = (SPLIT == 3) ? Ah + 64 * APAD : nullptr;
            unsigned* Bh = (SPLIT == 3) ? Al + 64 * APAD : Ah + 64 * APAD;
            unsigned* Bl = (SPLIT == 3) ? Bh + 32 * BPAD : nullptr;
            #pragma unroll
            for (int ks = 0; ks < 32; ks += 8) {
                unsigned ah[2][4], al_[2][4], bh[4][2], bl_[4][2];
                #pragma unroll
                for (int im = 0; im < 2; im++) {
                    int mb = wm * 32 + im * 16;
                    ah[im][0] = Ah[(mb + g    ) * APAD + ks +     tg];
                    ah[im][1] = Ah[(mb + g + 8) * APAD + ks +     tg];
                    ah[im][2] = Ah[(mb + g    ) * APAD + ks + 4 + tg];
                    ah[im][3] = Ah[(mb + g + 8) * APAD + ks + 4 + tg];
                    if (SPLIT == 3) {
                        al_[im][0] = Al[(mb + g    ) * APAD + ks +     tg];
                        al_[im][1] = Al[(mb + g + 8) * APAD + ks +     tg];
                        al_[im][2] = Al[(mb + g    ) * APAD + ks + 4 + tg];
                        al_[im][3] = Al[(mb + g + 8) * APAD + ks + 4 + tg];
                    }
                }
                #pragma unroll
                for (int jn = 0; jn < 4; jn++) {
                    int nb = wn * 32 + jn * 8;
                    bh[jn][0] = Bh[(ks +     tg) * BPAD + nb + g];
                    bh[jn][1] = Bh[(ks + 4 + tg) * BPAD + nb + g];
                    if (SPLIT == 3) {
                        bl_[jn][0] = Bl[(ks +     tg) * BPAD + nb + g];
                        bl_[jn][1] = Bl[(ks + 4 + tg) * BPAD + nb + g];
                    }
                }
                #pragma unroll
                for (int im = 0; im < 2; im++)
                    #pragma unroll
                    for (int jn = 0; jn < 4; jn++) {
                        if (SPLIT == 3) {
                            MMA_TF32(acc[im][jn], ah[im], bl_[jn]);
                            MMA_TF32(acc[im][jn], al_[im], bh[jn]);
                        }
                        MMA_TF32(acc[im][jn], ah[im], bh[jn]);
                    }
            }
        }

        if (c + 1 < nch) {
            storeTiles(stage ^ 1);
            __syncthreads();
            stage ^= 1;
        }
    }

    // ---- epilogue
    #pragma unroll
    for (int im = 0; im < 2; im++) {
        #pragma unroll
        for (int jn = 0; jn < 4; jn++) {
            int r0 = row0 + wm * 32 + im * 16 + g;
            int c0 = col0 + wn * 32 + jn * 8 + 2 * tg;
            #pragma unroll
            for (int half = 0; half < 2; half++) {
                int gr = r0 + half * 8;
                if (gr >= Mr) continue;
                #pragma unroll
                for (int cc = 0; cc < 2; cc++) {
                    int gn = c0 + cc;
                    if (gn >= Nc) continue;
                    float v = acc[im][jn][half * 2 + cc] * alpha;
                    if (kslices == 1) {
                        if (bias) v += bias[gn];
                        if (Rb)   v += Rb[(long)gr * ldc + gn];
                        if (DOGELU) v = gelu_tanh(v);
                    }
                    Cb[(long)gr * ldc + gn] = v;
                }
            }
        }
    }
}

// ---------------- split-K reduce: out = sum(partials) + bias + res ----------------
__global__ void reduce_k(const float* __restrict__ part, long sstride, int ns,
                         const float* __restrict__ bias, const float* __restrict__ res,
                         float* __restrict__ out, long n, int ncols)
{
    long i = (long)blockIdx.x * 256 + threadIdx.x;
    if (i >= n) return;
    float s = 0.f;
    for (int k = 0; k < ns; k++) s += part[(long)k * sstride + i];
    if (bias) s += bias[(int)(i % ncols)];
    if (res)  s += res[i];
    out[i] = s;
}

// ---------------- layernorm over D=128 ----------------
__global__ void ln_k(const float* __restrict__ in, const float* __restrict__ g,
                     const float* __restrict__ b, float* __restrict__ out)
{
    long row = blockIdx.x;
    int t = threadIdx.x;
    float v = in[row * DMODEL + t];
    __shared__ float red[4];
    float s = v;
    #pragma unroll
    for (int o = 16; o > 0; o >>= 1) s += __shfl_xor_sync(0xffffffffu, s, o);
    if ((t & 31) == 0) red[t >> 5] = s;
    __syncthreads();
    float mu = (red[0] + red[1] + red[2] + red[3]) * (1.f / 128.f);
    float d = v - mu;
    __syncthreads();
    float s2 = d * d;
    #pragma unroll
    for (int o = 16; o > 0; o >>= 1) s2 += __shfl_xor_sync(0xffffffffu, s2, o);
    if ((t & 31) == 0) red[t >> 5] = s2;
    __syncthreads();
    float var = (red[0] + red[1] + red[2] + red[3]) * (1.f / 128.f);
    out[row * DMODEL + t] = d / sqrtf(var + LNEPS) * g[t] + b[t];
}

// ---------------- softmax over 196 ----------------
__global__ void softmax196_k(float* __restrict__ att)
{
    long row = blockIdx.x;
    int t = threadIdx.x;
    float* a = att + row * NTOK;
    float v = (t < NTOK) ? a[t] : -3.4e38f;
    __shared__ float red[8];
    float m = v;
    #pragma unroll
    for (int o = 16; o > 0; o >>= 1) m = fmaxf(m, __shfl_xor_sync(0xffffffffu, m, o));
    if ((t & 31) == 0) red[t >> 5] = m;
    __syncthreads();
    m = red[0];
    #pragma unroll
    for (int i = 1; i < 8; i++) m = fmaxf(m, red[i]);
    float e = (t < NTOK) ? expf(v - m) : 0.f;
    __syncthreads();
    float s = e;
    #pragma unroll
    for (int o = 16; o > 0; o >>= 1) s += __shfl_xor_sync(0xffffffffu, s, o);
    if ((t & 31) == 0) red[t >> 5] = s;
    __syncthreads();
    s = red[0];
    #pragma unroll
    for (int i = 1; i < 8; i++) s += red[i];
    if (t < NTOK) a[t] = e / s;
}

// ---------------- top-32: register-resident incremental argmax ----------------
__global__ void __launch_bounds__(256) topk_k(const float* __restrict__ msim,
                       float* __restrict__ mvals, int* __restrict__ midx)
{
    long row = blockIdx.x;
    int tid = threadIdx.x;
    int lane = tid & 31, wid = tid >> 5;
    const float* src = msim + row * MKEYS;

    float v[32];
    const float4* s4 = (const float4*)(src + tid * 32);
    #pragma unroll
    for (int i = 0; i < 8; i++) {
        float4 t = s4[i];
        v[i*4+0] = t.x; v[i*4+1] = t.y; v[i*4+2] = t.z; v[i*4+3] = t.w;
    }

    unsigned long long p = 0ull;
    #pragma unroll
    for (int i = 0; i < 32; i++) {
        unsigned u = __float_as_uint(v[i]);
        u = (u & 0x80000000u) ? ~u : (u | 0x80000000u);
        unsigned long long key = ((unsigned long long)u << 32) | (unsigned)(MKEYS - 1 - (tid * 32 + i));
        if (key > p) p = key;
    }

    __shared__ unsigned long long wmax[2][8];

    for (int it = 0; it < TOPK; it++) {
        unsigned long long q = p;
        #pragma unroll
        for (int o = 16; o > 0; o >>= 1) {
            unsigned long long other = __shfl_xor_sync(0xffffffffu, q, o);
            if (other > q) q = other;
        }
        if (lane == 0) wmax[it & 1][wid] = q;
        __syncthreads();
        unsigned long long best = wmax[it & 1][0];
        #pragma unroll
        for (int w = 1; w < 8; w++) {
            unsigned long long o2 = wmax[it & 1][w];
            if (o2 > best) best = o2;
        }
        int gidx = MKEYS - 1 - (int)(best & 0xffffffffu);
        if (tid == (gidx >> 5)) {
            int sub = gidx & 31;
            float bv = 0.f;
            #pragma unroll
            for (int i = 0; i < 32; i++)
                if (i == sub) { bv = v[i]; v[i] = -3.4e38f; }
            mvals[row * TOPK + it] = bv;
            midx [row * TOPK + it] = gidx;
            unsigned long long np = 0ull;
            #pragma unroll
            for (int i = 0; i < 32; i++) {
                unsigned u = __float_as_uint(v[i]);
                u = (u & 0x80000000u) ? ~u : (u | 0x80000000u);
                unsigned long long key = ((unsigned long long)u << 32) | (unsigned)(MKEYS - 1 - (tid * 32 + i));
                if (key > np) np = key;
            }
            p = np;
        }
    }
}

// ---------------- kNN combine ----------------
__global__ void knn_combine_k(const float* __restrict__ att,
                              const float* __restrict__ mvals, const int* __restrict__ midx,
                              const float* __restrict__ qkv, const float* __restrict__ knn_v,
                              float* __restrict__ out)
{
    long row = blockIdx.x;
    int b = (int)(row / NTOK);
    int tid = threadIdx.x;
    __shared__ float w[TOPK + NTOK];
    __shared__ int   sidx[TOPK];
    __shared__ float red[4];

    if (tid < TOPK) {
        w[tid]    = mvals[row * TOPK + tid];
        sidx[tid] = midx [row * TOPK + tid];
    }
    for (int m = tid; m < NTOK; m += 128) w[TOPK + m] = att[row * NTOK + m];
    __syncthreads();

    float l0 = w[tid];
    float l1 = (tid < (TOPK + NTOK - 128)) ? w[tid + 128] : -3.4e38f;
    float m = fmaxf(l0, l1);
    #pragma unroll
    for (int o = 16; o > 0; o >>= 1) m = fmaxf(m, __shfl_xor_sync(0xffffffffu, m, o));
    if ((tid & 31) == 0) red[tid >> 5] = m;
    __syncthreads();
    m = fmaxf(fmaxf(red[0], red[1]), fmaxf(red[2], red[3]));
    float e0 = expf(l0 - m);
    float e1 = (tid < (TOPK + NTOK - 128)) ? expf(l1 - m) : 0.f;
    float s = e0 + e1;
    __syncthreads();
    #pragma unroll
    for (int o = 16; o > 0; o >>= 1) s += __shfl_xor_sync(0xffffffffu, s, o);
    if ((tid & 31) == 0) red[tid >> 5] = s;
    __syncthreads();
    s = red[0] + red[1] + red[2] + red[3];
    float inv = 1.f / s;
    w[tid] = e0 * inv;
    if (tid < (TOPK + NTOK - 128)) w[tid + 128] = e1 * inv;
    __syncthreads();

    float acc = 0.f;
    const float* kv = knn_v + (long)b * MKEYS * DMODEL;
    #pragma unroll 4
    for (int j = 0; j < TOPK; j++)
        acc += w[j] * kv[(long)sidx[j] * DMODEL + tid];
    const float* vbase = qkv + ((long)b * NTOK) * 384 + 256;
    for (int mm = 0; mm < NTOK; mm++)
        acc += w[TOPK + mm] * vbase[(long)mm * 384 + tid];
    out[row * DMODEL + tid] = acc;
}

// ---------------- mean pool ----------------
__global__ void mean_k(const float* __restrict__ y, float* __restrict__ feats)
{
    int b = blockIdx.x, d = threadIdx.x;
    float s = 0.f;
    for (int n = 0; n < NTOK; n++) s += y[((long)b * NTOK + n) * DMODEL + d];
    feats[b * DMODEL + d] = s * (1.f / 196.f);
}

// ---------------- launch ----------------
extern "C" void kernel_launch(void* const* d_in, const int* in_sizes, int n_in,
                              void* d_out, int out_size)
{
    const float* x       = (const float*)d_in[0];
    const float* patch_w = (const float*)d_in[1];
    const float* patch_b = (const float*)d_in[2];
    const float* ln1_g   = (const float*)d_in[3];
    const float* ln1_b   = (const float*)d_in[4];
    const float* qkv_w   = (const float*)d_in[5];
    const float* qkv_b   = (const float*)d_in[6];
    const float* out_w   = (const float*)d_in[7];
    const float* out_b   = (const float*)d_in[8];
    const float* ln2_g   = (const float*)d_in[9];
    const float* ln2_b   = (const float*)d_in[10];
    const float* ff1_w   = (const float*)d_in[11];
    const float* ff1_b   = (const float*)d_in[12];
    const float* ff2_w   = (const float*)d_in[13];
    const float* ff2_b   = (const float*)d_in[14];
    const float* lnf_g   = (const float*)d_in[15];
    const float* lnf_b   = (const float*)d_in[16];
    const float* knn_k   = (const float*)d_in[17];
    const float* knn_v   = (const float*)d_in[18];
    const float* head_w  = (const float*)d_in[19];
    const float* head_b  = (const float*)d_in[20];
    float* out = (float*)d_out;

    void* tp;
    cudaGetSymbolAddress(&tp, g_p);    float* pP    = (float*)tp;
    cudaGetSymbolAddress(&tp, g_h);    float* pH    = (float*)tp;
    cudaGetSymbolAddress(&tp, g_y);    float* pY    = (float*)tp;
    cudaGetSymbolAddress(&tp, g_qkv);  float* pQKV  = (float*)tp;
    cudaGetSymbolAddress(&tp, g_att);  float* pATT  = (float*)tp;
    cudaGetSymbolAddress(&tp, g_msim); float* pMSIM = (float*)tp;
    cudaGetSymbolAddress(&tp, g_o);    float* pO    = (float*)tp;
    cudaGetSymbolAddress(&tp, g_ff);   float* pFF   = (float*)tp;
    cudaGetSymbolAddress(&tp, g_part); float* pPart = (float*)tp;
    cudaGetSymbolAddress(&tp, g_mv);   float* pMV   = (float*)tp;
    cudaGetSymbolAddress(&tp, g_mi);   int*   pMI   = (int*)tp;
    cudaGetSymbolAddress(&tp, g_feats);float* pFeat = (float*)tp;

    cudaFuncSetAttribute(mma3_k<false,false,3>, cudaFuncAttributeMaxDynamicSharedMemorySize, SMEM3);
    cudaFuncSetAttribute(mma3_k<true, false,3>, cudaFuncAttributeMaxDynamicSharedMemorySize, SMEM3);
    cudaFuncSetAttribute(mma3_k<false,true, 3>, cudaFuncAttributeMaxDynamicSharedMemorySize, SMEM3);
    cudaFuncSetAttribute(mma3_k<true, false,1>, cudaFuncAttributeMaxDynamicSharedMemorySize, SMEM1);

    const long sPart = (long)ROWS * DMODEL;
    const long nHD   = (long)ROWS * DMODEL;

    // patch embed: split-K 6 (768 = 6*128)
    patchify_k<<<(int)(((long)ROWS * PDIM + 255) / 256), 256>>>(x, pP);
    mma3_k<false,false,3><<<dim3(1, 98, 6), 256, SMEM3>>>(pP, patch_w, nullptr, nullptr, pPart,
        ROWS, DMODEL, PDIM, 0, PDIM, 0, DMODEL, 0, DMODEL, 1.f, 1, 6, sPart);
    reduce_k<<<(int)((nHD + 255) / 256), 256>>>(pPart, sPart, 6, patch_b, nullptr, pH, nHD, DMODEL);

    for (int i = 0; i < DEPTH; i++) {
        ln_k<<<ROWS, 128>>>(pH, ln1_g + i * DMODEL, ln1_b + i * DMODEL, pY);
        mma3_k<false,false,3><<<dim3(3, 98, 1), 256, SMEM3>>>(pY, qkv_w + (long)i * DMODEL * 3 * DMODEL,
            qkv_b + i * 3 * DMODEL, nullptr, pQKV,
            ROWS, 3 * DMODEL, DMODEL, 0, DMODEL, 0, 3 * DMODEL, 0, 3 * DMODEL, 1.f, 1, 1, 0);
        // sim = q @ k^T * scale  (batched TB)
        mma3_k<true,false,3><<<dim3(2, 4, BATCH), 256, SMEM3>>>(pQKV, pQKV + 128, nullptr, nullptr, pATT,
            NTOK, NTOK, DMODEL,
            (long)NTOK * 384, 384, (long)NTOK * 384, 384, (long)NTOK * NTOK, NTOK, SCALE, BATCH, 1, 0);

        if (i == KNN_LAYER) {
            mma3_k<true,false,1><<<dim3(64, 4, BATCH), 256, SMEM1>>>(pQKV, knn_k, nullptr, nullptr, pMSIM,
                NTOK, MKEYS, DMODEL,
                (long)NTOK * 384, 384, (long)MKEYS * DMODEL, DMODEL, (long)NTOK * MKEYS, MKEYS, SCALE, BATCH, 1, 0);
            topk_k<<<ROWS, 256>>>(pMSIM, pMV, pMI);
            knn_combine_k<<<ROWS, 128>>>(pATT, pMV, pMI, pQKV, knn_v, pO);
        } else {
            softmax196_k<<<ROWS, 256>>>(pATT);
            mma3_k<false,false,3><<<dim3(1, 4, BATCH), 256, SMEM3>>>(pATT, pQKV + 256, nullptr, nullptr, pO,
                NTOK, DMODEL, NTOK,
                (long)NTOK * NTOK, NTOK, (long)NTOK * 384, 384, (long)NTOK * DMODEL, DMODEL, 1.f, BATCH, 1, 0);
        }

        // h = h + o @ out_w + out_b
        mma3_k<false,false,3><<<dim3(1, 98, 1), 256, SMEM3>>>(pO, out_w + (long)i * DMODEL * DMODEL,
            out_b + i * DMODEL, pH, pH,
            ROWS, DMODEL, DMODEL, 0, DMODEL, 0, DMODEL, 0, DMODEL, 1.f, 1, 1, 0);

        ln_k<<<ROWS, 128>>>(pH, ln2_g + i * DMODEL, ln2_b + i * DMODEL, pY);
        // ff1 + gelu
        mma3_k<false,true,3><<<dim3(4, 98, 1), 256, SMEM3>>>(pY, ff1_w + (long)i * DMODEL * FFH,
            ff1_b + i * FFH, nullptr, pFF,
            ROWS, FFH, DMODEL, 0, DMODEL, 0, FFH, 0, FFH, 1.f, 1, 1, 0);
        // ff2: split-K 4 (512 = 4*128), then reduce adds bias + residual h
        mma3_k<false,false,3><<<dim3(1, 98, 4), 256, SMEM3>>>(pFF, ff2_w + (long)i * FFH * DMODEL,
            nullptr, nullptr, pPart,
            ROWS, DMODEL, FFH, 0, FFH, 0, DMODEL, 0, DMODEL, 1.f, 1, 4, sPart);
        reduce_k<<<(int)((nHD + 255) / 256), 256>>>(pPart, sPart, 4, ff2_b + i * DMODEL, pH, pH, nHD, DMODEL);
    }

    ln_k<<<ROWS, 128>>>(pH, lnf_g, lnf_b, pY);
    mean_k<<<BATCH, 128>>>(pY, pFeat);
    mma3_k<false,false,3><<<dim3(8, 1, 1), 256, SMEM3>>>(pFeat, head_w, head_b, nullptr, out,
        BATCH, NCLS, DMODEL, 0, DMODEL, 0, NCLS, 0, NCLS, 1.f, 1, 1, 0);
}

// round 8
// speedup vs baseline: 2.4490x; 1.1446x over previous
#include <cuda_runtime.h>
#include <cuda_bf16.h>
#include <math.h>

// ---------------- problem constants ----------------
#define BATCH   32
#define NTOK    196
#define DMODEL  128
#define ROWS    (BATCH*NTOK) // 6272
#define PDIM    768
#define DEPTH   7
#define KNN_LAYER 6
#define MKEYS   8192
#define TOPK    32
#define FFH     512
#define NCLS    1000
#define SCALE   0.08838834764831845f
#define LNEPS   1e-5f

// ---------------- device scratch ----------------
__device__ float g_p   [ (long)ROWS*PDIM ];
__device__ float g_h   [ (long)ROWS*DMODEL ];
__device__ float g_y   [ (long)ROWS*DMODEL ];
__device__ float g_qkv [ (long)ROWS*3*DMODEL ];
__device__ float g_att [ (long)BATCH*NTOK*NTOK ];
__device__ float g_msim[ (long)BATCH*NTOK*MKEYS ];
__device__ float g_o   [ (long)ROWS*DMODEL ];
__device__ float g_ff  [ (long)ROWS*FFH ];
__device__ float g_part[ (long)6*ROWS*DMODEL ];
__device__ float g_mv  [ (long)ROWS*TOPK ];
__device__ int   g_mi  [ (long)ROWS*TOPK ];
__device__ float g_feats[ BATCH*DMODEL ];

// ---------------- helpers ----------------
__device__ __forceinline__ float gelu_tanh(float v) {
    const float c = 0.7978845608028654f;
    float t = tanhf(c * (v + 0.044715f * v * v * v));
    return 0.5f * v * (1.f + t);
}
__device__ __forceinline__ void split_bf16(float v, unsigned short& h, unsigned short& l) {
    __nv_bfloat16 hb = __float2bfloat16_rn(v);
    h = __bfloat16_as_ushort(hb);
    l = __bfloat16_as_ushort(__float2bfloat16_rn(v - __bfloat162float(hb)));
}
#define MMA_BF16(ACC, A, B)                                                 \
    asm volatile(                                                           \
        "mma.sync.aligned.m16n8k16.row.col.f32.bf16.bf16.f32 "              \
        "{%0,%1,%2,%3}, {%4,%5,%6,%7}, {%8,%9}, {%0,%1,%2,%3};"             \
        : "+f"((ACC)[0]), "+f"((ACC)[1]), "+f"((ACC)[2]), "+f"((ACC)[3])    \
        : "r"((A)[0]), "r"((A)[1]), "r"((A)[2]), "r"((A)[3]),               \
          "r"((B)[0]), "r"((B)[1]))
#define LDSM4(R0,R1,R2,R3, ADDR)                                            \
    asm volatile("ldmatrix.sync.aligned.m8n8.x4.shared.b16 {%0,%1,%2,%3}, [%4];" \
        : "=r"(R0), "=r"(R1), "=r"(R2), "=r"(R3) : "r"(ADDR))
#define LDSM4T(R0,R1,R2,R3, ADDR)                                           \
    asm volatile("ldmatrix.sync.aligned.m8n8.x4.trans.shared.b16 {%0,%1,%2,%3}, [%4];" \
        : "=r"(R0), "=r"(R1), "=r"(R2), "=r"(R3) : "r"(ADDR))

// ---------------- patchify ----------------
__global__ void patchify_k(const float* __restrict__ x, float* __restrict__ p) {
    long e = (long)blockIdx.x * 256 + threadIdx.x;
    if (e >= (long)ROWS * PDIM) return;
    int c   = (int)(e % PDIM);
    long row = e / PDIM;
    int b = (int)(row / NTOK), n = (int)(row % NTOK);
    int i = n / 14, j = n % 14;
    int ch = c / 256, r = c % 256, pi = r / 16, pj = r % 16;
    p[e] = x[(((long)b*3 + ch)*224 + (i*16 + pi))*224 + (j*16 + pj)];
}

// ---------------- bf16 split-2 mma GEMM ----------------
// Block 64(M) x 128(N), K-chunk 32, 2-stage pipeline, ldmatrix fragments.
// Smem per stage (bytes): Ah@0 (5120), Al@5120, Bh@10240, Bl@20480. Stage=30720.
// A: row-major m x k, pitch 80B (40 bf16). B TB: n-major, pitch 80B. B NN: k-major, pitch 272B.
#define A_PITCH_B 80
#define BTB_PITCH_B 80
#define BNN_PITCH_B 272
#define AL_OFF 5120
#define BH_OFF 10240
#define BL_OFF 20480
#define STAGE_B 30720
#define SMEM2 (2*STAGE_B)

template<bool TB, bool DOGELU>
__global__ void __launch_bounds__(256, 2)
mmabf_k(const float* __restrict__ A, const float* __restrict__ Bm,
        const float* __restrict__ bias, const float* __restrict__ Res,
        float* __restrict__ C,
        int Mr, int Nc, int K,
        long sAb, int lda, long sBb, int ldb, long sCb, int ldc,
        float alpha, int nbatch, int kslices, long sPart)
{
    extern __shared__ char smem_c[];
    unsigned sbase = (unsigned)__cvta_generic_to_shared(smem_c);

    int bz = blockIdx.z;
    int batch = bz % nbatch;
    int ksl   = bz / nbatch;
    int Kslice = K / kslices;
    int Klo = ksl * Kslice;
    int Khi = (ksl == kslices - 1) ? K : Klo + Kslice;

    const float* Ab = A + (long)batch * sAb;
    const float* Bb = Bm + (long)batch * sBb;
    float*       Cb;
    const float* Rb;
    if (kslices > 1) {
        Cb = C + (long)ksl * sPart + (long)batch * sCb;
        Rb = nullptr;
    } else {
        Cb = C + (long)batch * sCb;
        Rb = Res ? (Res + (long)batch * sCb) : nullptr;
    }

    int row0 = blockIdx.y * 64;
    int col0 = blockIdx.x * 128;
    int tid = threadIdx.x;
    int lane = tid & 31, warp = tid >> 5;
    int wm = warp >> 2, wn = warp & 3;
    int g = lane >> 2, tg = lane & 3;

    int ar = tid >> 3, ak = (tid & 7) * 4;        // A: rows ar, ar+32; k ak..ak+3
    int bkNN = tid >> 5, bnNN = (tid & 31) * 4;   // B NN: k rows bkNN+8p; n bnNN..+3
    int bnTB = tid >> 3, bkTB = (tid & 7) * 4;    // B TB: n rows bnTB+32p; k bkTB..+3

    float4 pa[2], pb[4];

    auto loadA = [&](int k0) {
        #pragma unroll
        for (int p = 0; p < 2; p++) {
            int gr = row0 + ar + p * 32, gk = k0 + ak;
            float4 v = make_float4(0.f, 0.f, 0.f, 0.f);
            if (gr < Mr) {
                if (gk + 3 < Khi) v = *(const float4*)&Ab[(long)gr * lda + gk];
                else {
                    if (gk + 0 < Khi) v.x = Ab[(long)gr * lda + gk + 0];
                    if (gk + 1 < Khi) v.y = Ab[(long)gr * lda + gk + 1];
                    if (gk + 2 < Khi) v.z = Ab[(long)gr * lda + gk + 2];
                    if (gk + 3 < Khi) v.w = Ab[(long)gr * lda + gk + 3];
                }
            }
            pa[p] = v;
        }
    };
    auto loadB = [&](int k0) {
        if (TB) {
            #pragma unroll
            for (int p = 0; p < 4; p++) {
                int gn = col0 + bnTB + p * 32, gk = k0 + bkTB;
                float4 v = make_float4(0.f, 0.f, 0.f, 0.f);
                if (gn < Nc) {
                    if (gk + 3 < Khi) v = *(const float4*)&Bb[(long)gn * ldb + gk];
                    else {
                        if (gk + 0 < Khi) v.x = Bb[(long)gn * ldb + gk + 0];
                        if (gk + 1 < Khi) v.y = Bb[(long)gn * ldb + gk + 1];
                        if (gk + 2 < Khi) v.z = Bb[(long)gn * ldb + gk + 2];
                        if (gk + 3 < Khi) v.w = Bb[(long)gn * ldb + gk + 3];
                    }
                }
                pb[p] = v;
            }
        } else {
            #pragma unroll
            for (int p = 0; p < 4; p++) {
                int gk = k0 + bkNN + p * 8, gn = col0 + bnNN;
                float4 v = make_float4(0.f, 0.f, 0.f, 0.f);
                if (gk < Khi) {
                    if (gn + 3 < Nc) v = *(const float4*)&Bb[(long)gk * ldb + gn];
                    else {
                        if (gn + 0 < Nc) v.x = Bb[(long)gk * ldb + gn + 0];
                        if (gn + 1 < Nc) v.y = Bb[(long)gk * ldb + gn + 1];
                        if (gn + 2 < Nc) v.z = Bb[(long)gk * ldb + gn + 2];
                        if (gn + 3 < Nc) v.w = Bb[(long)gk * ldb + gn + 3];
                    }
                }
                pb[p] = v;
            }
        }
    };
    auto storeTiles = [&](int st) {
        char* sb = smem_c + st * STAGE_B;
        #pragma unroll
        for (int p = 0; p < 2; p++) {
            int r = ar + p * 32;
            float vv[4] = {pa[p].x, pa[p].y, pa[p].z, pa[p].w};
            unsigned short h[4], l[4];
            #pragma unroll
            for (int j = 0; j < 4; j++) split_bf16(vv[j], h[j], l[j]);
            uint2 ph = make_uint2(((unsigned)h[1] << 16) | h[0], ((unsigned)h[3] << 16) | h[2]);
            uint2 pl = make_uint2(((unsigned)l[1] << 16) | l[0], ((unsigned)l[3] << 16) | l[2]);
            *(uint2*)(sb + r * A_PITCH_B + ak * 2)          = ph;
            *(uint2*)(sb + AL_OFF + r * A_PITCH_B + ak * 2) = pl;
        }
        if (TB) {
            #pragma unroll
            for (int p = 0; p < 4; p++) {
                int n = bnTB + p * 32;
                float vv[4] = {pb[p].x, pb[p].y, pb[p].z, pb[p].w};
                unsigned short h[4], l[4];
                #pragma unroll
                for (int j = 0; j < 4; j++) split_bf16(vv[j], h[j], l[j]);
                uint2 ph = make_uint2(((unsigned)h[1] << 16) | h[0], ((unsigned)h[3] << 16) | h[2]);
                uint2 pl = make_uint2(((unsigned)l[1] << 16) | l[0], ((unsigned)l[3] << 16) | l[2]);
                *(uint2*)(sb + BH_OFF + n * BTB_PITCH_B + bkTB * 2) = ph;
                *(uint2*)(sb + BL_OFF + n * BTB_PITCH_B + bkTB * 2) = pl;
            }
        } else {
            #pragma unroll
            for (int p = 0; p < 4; p++) {
                int k = bkNN + p * 8;
                float vv[4] = {pb[p].x, pb[p].y, pb[p].z, pb[p].w};
                unsigned short h[4], l[4];
                #pragma unroll
                for (int j = 0; j < 4; j++) split_bf16(vv[j], h[j], l[j]);
                uint2 ph = make_uint2(((unsigned)h[1] << 16) | h[0], ((unsigned)h[3] << 16) | h[2]);
                uint2 pl = make_uint2(((unsigned)l[1] << 16) | l[0], ((unsigned)l[3] << 16) | l[2]);
                *(uint2*)(sb + BH_OFF + k * BNN_PITCH_B + bnNN * 2) = ph;
                *(uint2*)(sb + BL_OFF + k * BNN_PITCH_B + bnNN * 2) = pl;
            }
        }
    };

    float acc[2][4][4];
    #pragma unroll
    for (int im = 0; im < 2; im++)
        #pragma unroll
        for (int jn = 0; jn < 4; jn++)
            #pragma unroll
            for (int c = 0; c < 4; c++) acc[im][jn][c] = 0.f;

    int nch = (Khi - Klo + 31) / 32;
    int stage = 0;

    loadA(Klo); loadB(Klo);
    storeTiles(0);
    __syncthreads();

    for (int c = 0; c < nch; c++) {
        if (c + 1 < nch) { loadA(Klo + (c + 1) * 32); loadB(Klo + (c + 1) * 32); }

        unsigned stb = sbase + stage * STAGE_B;
        #pragma unroll
        for (int ks2 = 0; ks2 < 2; ks2++) {
            int ksb = ks2 * 32;   // byte offset along k within tile
            unsigned ah[2][4], al_[2][4];
            #pragma unroll
            for (int im = 0; im < 2; im++) {
                unsigned aaddr = stb
                    + (unsigned)((wm * 32 + im * 16 + (lane & 15)) * A_PITCH_B
                                 + ((lane >> 4) * 16) + ksb);
                LDSM4(ah[im][0], ah[im][1], ah[im][2], ah[im][3], aaddr);
                LDSM4(al_[im][0], al_[im][1], al_[im][2], al_[im][3], aaddr + AL_OFF);
            }
            unsigned bh[4][2], bl_[4][2];
            #pragma unroll
            for (int pr = 0; pr < 2; pr++) {
                int nb2 = wn * 32 + pr * 16;
                unsigned baddr;
                if (TB) {
                    baddr = stb + BH_OFF
                        + (unsigned)((nb2 + ((lane >> 4) << 3) + (lane & 7)) * BTB_PITCH_B
                                     + (((lane >> 3) & 1) * 16) + ksb);
                } else {
                    baddr = stb + BH_OFF
                        + (unsigned)((ks2 * 16 + ((lane >> 3) & 1) * 8 + (lane & 7)) * BNN_PITCH_B
                                     + (nb2 + (lane >> 4) * 8) * 2);
                }
                unsigned r0, r1, r2, r3;
                if (TB) { LDSM4(r0, r1, r2, r3, baddr); }
                else    { LDSM4T(r0, r1, r2, r3, baddr); }
                bh[2*pr][0] = r0; bh[2*pr][1] = r1; bh[2*pr+1][0] = r2; bh[2*pr+1][1] = r3;
                unsigned laddr = baddr + (BL_OFF - BH_OFF);
                if (TB) { LDSM4(r0, r1, r2, r3, laddr); }
                else    { LDSM4T(r0, r1, r2, r3, laddr); }
                bl_[2*pr][0] = r0; bl_[2*pr][1] = r1; bl_[2*pr+1][0] = r2; bl_[2*pr+1][1] = r3;
            }
            #pragma unroll
            for (int im = 0; im < 2; im++)
                #pragma unroll
                for (int jn = 0; jn < 4; jn++) {
                    MMA_BF16(acc[im][jn], ah[im], bl_[jn]);
                    MMA_BF16(acc[im][jn], al_[im], bh[jn]);
                    MMA_BF16(acc[im][jn], ah[im], bh[jn]);
                }
        }

        if (c + 1 < nch) {
            storeTiles(stage ^ 1);
            __syncthreads();
            stage ^= 1;
        }
    }

    // ---- epilogue (C fragment: rows g/g+8, cols 2tg/2tg+1 per jn tile)
    #pragma unroll
    for (int im = 0; im < 2; im++) {
        #pragma unroll
        for (int jn = 0; jn < 4; jn++) {
            int r0 = row0 + wm * 32 + im * 16 + g;
            int c0 = col0 + wn * 32 + jn * 8 + 2 * tg;
            #pragma unroll
            for (int half = 0; half < 2; half++) {
                int gr = r0 + half * 8;
                if (gr >= Mr) continue;
                #pragma unroll
                for (int cc = 0; cc < 2; cc++) {
                    int gn = c0 + cc;
                    if (gn >= Nc) continue;
                    float v = acc[im][jn][half * 2 + cc] * alpha;
                    if (kslices == 1) {
                        if (bias) v += bias[gn];
                        if (Rb)   v += Rb[(long)gr * ldc + gn];
                        if (DOGELU) v = gelu_tanh(v);
                    }
                    Cb[(long)gr * ldc + gn] = v;
                }
            }
        }
    }
}

// ---------------- split-K reduce ----------------
__global__ void reduce_k(const float* __restrict__ part, long sstride, int ns,
                         const float* __restrict__ bias, const float* __restrict__ res,
                         float* __restrict__ out, long n, int ncols)
{
    long i = (long)blockIdx.x * 256 + threadIdx.x;
    if (i >= n) return;
    float s = 0.f;
    for (int k = 0; k < ns; k++) s += part[(long)k * sstride + i];
    if (bias) s += bias[(int)(i % ncols)];
    if (res)  s += res[i];
    out[i] = s;
}

// ---------------- layernorm over D=128 ----------------
__global__ void ln_k(const float* __restrict__ in, const float* __restrict__ g,
                     const float* __restrict__ b, float* __restrict__ out)
{
    long row = blockIdx.x;
    int t = threadIdx.x;
    float v = in[row * DMODEL + t];
    __shared__ float red[4];
    float s = v;
    #pragma unroll
    for (int o = 16; o > 0; o >>= 1) s += __shfl_xor_sync(0xffffffffu, s, o);
    if ((t & 31) == 0) red[t >> 5] = s;
    __syncthreads();
    float mu = (red[0] + red[1] + red[2] + red[3]) * (1.f / 128.f);
    float d = v - mu;
    __syncthreads();
    float s2 = d * d;
    #pragma unroll
    for (int o = 16; o > 0; o >>= 1) s2 += __shfl_xor_sync(0xffffffffu, s2, o);
    if ((t & 31) == 0) red[t >> 5] = s2;
    __syncthreads();
    float var = (red[0] + red[1] + red[2] + red[3]) * (1.f / 128.f);
    out[row * DMODEL + t] = d / sqrtf(var + LNEPS) * g[t] + b[t];
}

// ---------------- softmax over 196 ----------------
__global__ void softmax196_k(float* __restrict__ att)
{
    long row = blockIdx.x;
    int t = threadIdx.x;
    float* a = att + row * NTOK;
    float v = (t < NTOK) ? a[t] : -3.4e38f;
    __shared__ float red[8];
    float m = v;
    #pragma unroll
    for (int o = 16; o > 0; o >>= 1) m = fmaxf(m, __shfl_xor_sync(0xffffffffu, m, o));
    if ((t & 31) == 0) red[t >> 5] = m;
    __syncthreads();
    m = red[0];
    #pragma unroll
    for (int i = 1; i < 8; i++) m = fmaxf(m, red[i]);
    float e = (t < NTOK) ? expf(v - m) : 0.f;
    __syncthreads();
    float s = e;
    #pragma unroll
    for (int o = 16; o > 0; o >>= 1) s += __shfl_xor_sync(0xffffffffu, s, o);
    if ((t & 31) == 0) red[t >> 5] = s;
    __syncthreads();
    s = red[0];
    #pragma unroll
    for (int i = 1; i < 8; i++) s += red[i];
    if (t < NTOK) a[t] = e / s;
}

// ---------------- top-32: register-resident incremental argmax ----------------
__global__ void __launch_bounds__(256) topk_k(const float* __restrict__ msim,
                       float* __restrict__ mvals, int* __restrict__ midx)
{
    long row = blockIdx.x;
    int tid = threadIdx.x;
    int lane = tid & 31, wid = tid >> 5;
    const float* src = msim + row * MKEYS;

    float v[32];
    const float4* s4 = (const float4*)(src + tid * 32);
    #pragma unroll
    for (int i = 0; i < 8; i++) {
        float4 t = s4[i];
        v[i*4+0] = t.x; v[i*4+1] = t.y; v[i*4+2] = t.z; v[i*4+3] = t.w;
    }

    unsigned long long p = 0ull;
    #pragma unroll
    for (int i = 0; i < 32; i++) {
        unsigned u = __float_as_uint(v[i]);
        u = (u & 0x80000000u) ? ~u : (u | 0x80000000u);
        unsigned long long key = ((unsigned long long)u << 32) | (unsigned)(MKEYS - 1 - (tid * 32 + i));
        if (key > p) p = key;
    }

    __shared__ unsigned long long wmax[2][8];

    for (int it = 0; it < TOPK; it++) {
        unsigned long long q = p;
        #pragma unroll
        for (int o = 16; o > 0; o >>= 1) {
            unsigned long long other = __shfl_xor_sync(0xffffffffu, q, o);
            if (other > q) q = other;
        }
        if (lane == 0) wmax[it & 1][wid] = q;
        __syncthreads();
        unsigned long long best = wmax[it & 1][0];
        #pragma unroll
        for (int w = 1; w < 8; w++) {
            unsigned long long o2 = wmax[it & 1][w];
            if (o2 > best) best = o2;
        }
        int gidx = MKEYS - 1 - (int)(best & 0xffffffffu);
        if (tid == (gidx >> 5)) {
            int sub = gidx & 31;
            float bv = 0.f;
            #pragma unroll
            for (int i = 0; i < 32; i++)
                if (i == sub) { bv = v[i]; v[i] = -3.4e38f; }
            mvals[row * TOPK + it] = bv;
            midx [row * TOPK + it] = gidx;
            unsigned long long np = 0ull;
            #pragma unroll
            for (int i = 0; i < 32; i++) {
                unsigned u = __float_as_uint(v[i]);
                u = (u & 0x80000000u) ? ~u : (u | 0x80000000u);
                unsigned long long key = ((unsigned long long)u << 32) | (unsigned)(MKEYS - 1 - (tid * 32 + i));
                if (key > np) np = key;
            }
            p = np;
        }
    }
}

// ---------------- kNN combine ----------------
__global__ void knn_combine_k(const float* __restrict__ att,
                              const float* __restrict__ mvals, const int* __restrict__ midx,
                              const float* __restrict__ qkv, const float* __restrict__ knn_v,
                              float* __restrict__ out)
{
    long row = blockIdx.x;
    int b = (int)(row / NTOK);
    int tid = threadIdx.x;
    __shared__ float w[TOPK + NTOK];
    __shared__ int   sidx[TOPK];
    __shared__ float red[4];

    if (tid < TOPK) {
        w[tid]    = mvals[row * TOPK + tid];
        sidx[tid] = midx [row * TOPK + tid];
    }
    for (int m = tid; m < NTOK; m += 128) w[TOPK + m] = att[row * NTOK + m];
    __syncthreads();

    float l0 = w[tid];
    float l1 = (tid < (TOPK + NTOK - 128)) ? w[tid + 128] : -3.4e38f;
    float m = fmaxf(l0, l1);
    #pragma unroll
    for (int o = 16; o > 0; o >>= 1) m = fmaxf(m, __shfl_xor_sync(0xffffffffu, m, o));
    if ((tid & 31) == 0) red[tid >> 5] = m;
    __syncthreads();
    m = fmaxf(fmaxf(red[0], red[1]), fmaxf(red[2], red[3]));
    float e0 = expf(l0 - m);
    float e1 = (tid < (TOPK + NTOK - 128)) ? expf(l1 - m) : 0.f;
    float s = e0 + e1;
    __syncthreads();
    #pragma unroll
    for (int o = 16; o > 0; o >>= 1) s += __shfl_xor_sync(0xffffffffu, s, o);
    if ((tid & 31) == 0) red[tid >> 5] = s;
    __syncthreads();
    s = red[0] + red[1] + red[2] + red[3];
    float inv = 1.f / s;
    w[tid] = e0 * inv;
    if (tid < (TOPK + NTOK - 128)) w[tid + 128] = e1 * inv;
    __syncthreads();

    float acc = 0.f;
    const float* kv = knn_v + (long)b * MKEYS * DMODEL;
    #pragma unroll 4
    for (int j = 0; j < TOPK; j++)
        acc += w[j] * kv[(long)sidx[j] * DMODEL + tid];
    const float* vbase = qkv + ((long)b * NTOK) * 384 + 256;
    for (int mm = 0; mm < NTOK; mm++)
        acc += w[TOPK + mm] * vbase[(long)mm * 384 + tid];
    out[row * DMODEL + tid] = acc;
}

// ---------------- mean pool ----------------
__global__ void mean_k(const float* __restrict__ y, float* __restrict__ feats)
{
    int b = blockIdx.x, d = threadIdx.x;
    float s = 0.f;
    for (int n = 0; n < NTOK; n++) s += y[((long)b * NTOK + n) * DMODEL + d];
    feats[b * DMODEL + d] = s * (1.f / 196.f);
}

// ---------------- launch ----------------
extern "C" void kernel_launch(void* const* d_in, const int* in_sizes, int n_in,
                              void* d_out, int out_size)
{
    const float* x       = (const float*)d_in[0];
    const float* patch_w = (const float*)d_in[1];
    const float* patch_b = (const float*)d_in[2];
    const float* ln1_g   = (const float*)d_in[3];
    const float* ln1_b   = (const float*)d_in[4];
    const float* qkv_w   = (const float*)d_in[5];
    const float* qkv_b   = (const float*)d_in[6];
    const float* out_w   = (const float*)d_in[7];
    const float* out_b   = (const float*)d_in[8];
    const float* ln2_g   = (const float*)d_in[9];
    const float* ln2_b   = (const float*)d_in[10];
    const float* ff1_w   = (const float*)d_in[11];
    const float* ff1_b   = (const float*)d_in[12];
    const float* ff2_w   = (const float*)d_in[13];
    const float* ff2_b   = (const float*)d_in[14];
    const float* lnf_g   = (const float*)d_in[15];
    const float* lnf_b   = (const float*)d_in[16];
    const float* knn_k   = (const float*)d_in[17];
    const float* knn_v   = (const float*)d_in[18];
    const float* head_w  = (const float*)d_in[19];
    const float* head_b  = (const float*)d_in[20];
    float* out = (float*)d_out;

    void* tp;
    cudaGetSymbolAddress(&tp, g_p);    float* pP    = (float*)tp;
    cudaGetSymbolAddress(&tp, g_h);    float* pH    = (float*)tp;
    cudaGetSymbolAddress(&tp, g_y);    float* pY    = (float*)tp;
    cudaGetSymbolAddress(&tp, g_qkv);  float* pQKV  = (float*)tp;
    cudaGetSymbolAddress(&tp, g_att);  float* pATT  = (float*)tp;
    cudaGetSymbolAddress(&tp, g_msim); float* pMSIM = (float*)tp;
    cudaGetSymbolAddress(&tp, g_o);    float* pO    = (float*)tp;
    cudaGetSymbolAddress(&tp, g_ff);   float* pFF   = (float*)tp;
    cudaGetSymbolAddress(&tp, g_part); float* pPart = (float*)tp;
    cudaGetSymbolAddress(&tp, g_mv);   float* pMV   = (float*)tp;
    cudaGetSymbolAddress(&tp, g_mi);   int*   pMI   = (int*)tp;
    cudaGetSymbolAddress(&tp, g_feats);float* pFeat = (float*)tp;

    cudaFuncSetAttribute(mmabf_k<false,false>, cudaFuncAttributeMaxDynamicSharedMemorySize, SMEM2);
    cudaFuncSetAttribute(mmabf_k<true, false>, cudaFuncAttributeMaxDynamicSharedMemorySize, SMEM2);
    cudaFuncSetAttribute(mmabf_k<false,true >, cudaFuncAttributeMaxDynamicSharedMemorySize, SMEM2);

    const long sPart = (long)ROWS * DMODEL;
    const long nHD   = (long)ROWS * DMODEL;

    // patch embed: split-K 6 (768 = 6*128)
    patchify_k<<<(int)(((long)ROWS * PDIM + 255) / 256), 256>>>(x, pP);
    mmabf_k<false,false><<<dim3(1, 98, 6), 256, SMEM2>>>(pP, patch_w, nullptr, nullptr, pPart,
        ROWS, DMODEL, PDIM, 0, PDIM, 0, DMODEL, 0, DMODEL, 1.f, 1, 6, sPart);
    reduce_k<<<(int)((nHD + 255) / 256), 256>>>(pPart, sPart, 6, patch_b, nullptr, pH, nHD, DMODEL);

    for (int i = 0; i < DEPTH; i++) {
        ln_k<<<ROWS, 128>>>(pH, ln1_g + i * DMODEL, ln1_b + i * DMODEL, pY);
        mmabf_k<false,false><<<dim3(3, 98, 1), 256, SMEM2>>>(pY, qkv_w + (long)i * DMODEL * 3 * DMODEL,
            qkv_b + i * 3 * DMODEL, nullptr, pQKV,
            ROWS, 3 * DMODEL, DMODEL, 0, DMODEL, 0, 3 * DMODEL, 0, 3 * DMODEL, 1.f, 1, 1, 0);
        // sim = q @ k^T * scale  (batched TB)
        mmabf_k<true,false><<<dim3(2, 4, BATCH), 256, SMEM2>>>(pQKV, pQKV + 128, nullptr, nullptr, pATT,
            NTOK, NTOK, DMODEL,
            (long)NTOK * 384, 384, (long)NTOK * 384, 384, (long)NTOK * NTOK, NTOK, SCALE, BATCH, 1, 0);

        if (i == KNN_LAYER) {
            mmabf_k<true,false><<<dim3(64, 4, BATCH), 256, SMEM2>>>(pQKV, knn_k, nullptr, nullptr, pMSIM,
                NTOK, MKEYS, DMODEL,
                (long)NTOK * 384, 384, (long)MKEYS * DMODEL, DMODEL, (long)NTOK * MKEYS, MKEYS, SCALE, BATCH, 1, 0);
            topk_k<<<ROWS, 256>>>(pMSIM, pMV, pMI);
            knn_combine_k<<<ROWS, 128>>>(pATT, pMV, pMI, pQKV, knn_v, pO);
        } else {
            softmax196_k<<<ROWS, 256>>>(pATT);
            mmabf_k<false,false><<<dim3(1, 4, BATCH), 256, SMEM2>>>(pATT, pQKV + 256, nullptr, nullptr, pO,
                NTOK, DMODEL, NTOK,
                (long)NTOK * NTOK, NTOK, (long)NTOK * 384, 384, (long)NTOK * DMODEL, DMODEL, 1.f, BATCH, 1, 0);
        }

        // h = h + o @ out_w + out_b
        mmabf_k<false,false><<<dim3(1, 98, 1), 256, SMEM2>>>(pO, out_w + (long)i * DMODEL * DMODEL,
            out_b + i * DMODEL, pH, pH,
            ROWS, DMODEL, DMODEL, 0, DMODEL, 0, DMODEL, 0, DMODEL, 1.f, 1, 1, 0);

        ln_k<<<ROWS, 128>>>(pH, ln2_g + i * DMODEL, ln2_b + i * DMODEL, pY);
        // ff1 + gelu
        mmabf_k<false,true><<<dim3(4, 98, 1), 256, SMEM2>>>(pY, ff1_w + (long)i * DMODEL * FFH,
            ff1_b + i * FFH, nullptr, pFF,
            ROWS, FFH, DMODEL, 0, DMODEL, 0, FFH, 0, FFH, 1.f, 1, 1, 0);
        // ff2: split-K 4 (512 = 4*128), reduce adds bias + residual h
        mmabf_k<false,false><<<dim3(1, 98, 4), 256, SMEM2>>>(pFF, ff2_w + (long)i * FFH * DMODEL,
            nullptr, nullptr, pPart,
            ROWS, DMODEL, FFH, 0, FFH, 0, DMODEL, 0, DMODEL, 1.f, 1, 4, sPart);
        reduce_k<<<(int)((nHD + 255) / 256), 256>>>(pPart, sPart, 4, ff2_b + i * DMODEL, pH, pH, nHD, DMODEL);
    }

    ln_k<<<ROWS, 128>>>(pH, lnf_g, lnf_b, pY);
    mean_k<<<BATCH, 128>>>(pY, pFeat);
    mmabf_k<false,false><<<dim3(8, 1, 1), 256, SMEM2>>>(pFeat, head_w, head_b, nullptr, out,
        BATCH, NCLS, DMODEL, 0, DMODEL, 0, NCLS, 0, NCLS, 1.f, 1, 1, 0);
}

// round 9
// speedup vs baseline: 2.5272x; 1.0319x over previous
#include <cuda_runtime.h>
#include <cuda_bf16.h>
#include <math.h>

// ---------------- problem constants ----------------
#define BATCH   32
#define NTOK    196
#define DMODEL  128
#define ROWS    (BATCH*NTOK) // 6272
#define PDIM    768
#define DEPTH   7
#define KNN_LAYER 6
#define MKEYS   8192
#define TOPK    32
#define FFH     512
#define NCLS    1000
#define SCALE   0.08838834764831845f
#define LNEPS   1e-5f

// ---------------- device scratch ----------------
__device__ float g_p   [ (long)ROWS*PDIM ];
__device__ float g_h   [ (long)ROWS*DMODEL ];
__device__ float g_qkv [ (long)ROWS*3*DMODEL ];
__device__ float g_att [ (long)BATCH*NTOK*NTOK ];
__device__ float g_msim[ (long)BATCH*NTOK*MKEYS ];
__device__ float g_o   [ (long)ROWS*DMODEL ];
__device__ float g_ff  [ (long)ROWS*FFH ];
__device__ float g_part[ (long)6*ROWS*DMODEL ];
__device__ float g_mv  [ (long)ROWS*TOPK ];
__device__ int   g_mi  [ (long)ROWS*TOPK ];
__device__ float g_feats[ BATCH*DMODEL ];
__device__ float g_mu  [ ROWS ];
__device__ float g_rs  [ ROWS ];

// ---------------- helpers ----------------
__device__ __forceinline__ float gelu_tanh(float v) {
    const float c = 0.7978845608028654f;
    float t = tanhf(c * (v + 0.044715f * v * v * v));
    return 0.5f * v * (1.f + t);
}
__device__ __forceinline__ void split_bf16(float v, unsigned short& h, unsigned short& l) {
    __nv_bfloat16 hb = __float2bfloat16_rn(v);
    h = __bfloat16_as_ushort(hb);
    l = __bfloat16_as_ushort(__float2bfloat16_rn(v - __bfloat162float(hb)));
}
#define MMA_BF16(ACC, A, B)                                                 \
    asm volatile(                                                           \
        "mma.sync.aligned.m16n8k16.row.col.f32.bf16.bf16.f32 "              \
        "{%0,%1,%2,%3}, {%4,%5,%6,%7}, {%8,%9}, {%0,%1,%2,%3};"             \
        : "+f"((ACC)[0]), "+f"((ACC)[1]), "+f"((ACC)[2]), "+f"((ACC)[3])    \
        : "r"((A)[0]), "r"((A)[1]), "r"((A)[2]), "r"((A)[3]),               \
          "r"((B)[0]), "r"((B)[1]))
#define LDSM4(R0,R1,R2,R3, ADDR)                                            \
    asm volatile("ldmatrix.sync.aligned.m8n8.x4.shared.b16 {%0,%1,%2,%3}, [%4];" \
        : "=r"(R0), "=r"(R1), "=r"(R2), "=r"(R3) : "r"(ADDR))
#define LDSM4T(R0,R1,R2,R3, ADDR)                                           \
    asm volatile("ldmatrix.sync.aligned.m8n8.x4.trans.shared.b16 {%0,%1,%2,%3}, [%4];" \
        : "=r"(R0), "=r"(R1), "=r"(R2), "=r"(R3) : "r"(ADDR))

// ---------------- patchify ----------------
__global__ void patchify_k(const float* __restrict__ x, float* __restrict__ p) {
    long e = (long)blockIdx.x * 256 + threadIdx.x;
    if (e >= (long)ROWS * PDIM) return;
    int c   = (int)(e % PDIM);
    long row = e / PDIM;
    int b = (int)(row / NTOK), n = (int)(row % NTOK);
    int i = n / 14, j = n % 14;
    int ch = c / 256, r = c % 256, pi = r / 16, pj = r % 16;
    p[e] = x[(((long)b*3 + ch)*224 + (i*16 + pi))*224 + (j*16 + pj)];
}

// ---------------- bf16 split-2 mma GEMM ----------------
// Block 64(M) x 128(N), K-chunk 32, 2-stage pipeline, ldmatrix fragments.
// LNA: apply layernorm (muA/rsA/lngA/lnbA) to A rows during load.
// STATS: (requires gridDim.x==1, Nc==128, full rows) epilogue emits row mean/rstd.
#define A_PITCH_B 80
#define BTB_PITCH_B 80
#define BNN_PITCH_B 272
#define AL_OFF 5120
#define BH_OFF 10240
#define BL_OFF 20480
#define STAGE_B 30720
#define SMEM2 (2*STAGE_B)

template<bool TB, bool DOGELU, bool LNA, bool STATS>
__global__ void __launch_bounds__(256, 2)
mmabf_k(const float* __restrict__ A, const float* __restrict__ Bm,
        const float* __restrict__ bias, const float* __restrict__ Res,
        float* __restrict__ C,
        int Mr, int Nc, int K,
        long sAb, int lda, long sBb, int ldb, long sCb, int ldc,
        float alpha, int nbatch, int kslices, long sPart,
        const float* __restrict__ muA, const float* __restrict__ rsA,
        const float* __restrict__ lngA, const float* __restrict__ lnbA,
        float* __restrict__ muO, float* __restrict__ rsO)
{
    extern __shared__ char smem_c[];
    unsigned sbase = (unsigned)__cvta_generic_to_shared(smem_c);

    int bz = blockIdx.z;
    int batch = bz % nbatch;
    int ksl   = bz / nbatch;
    int Kslice = K / kslices;
    int Klo = ksl * Kslice;
    int Khi = (ksl == kslices - 1) ? K : Klo + Kslice;

    const float* Ab = A + (long)batch * sAb;
    const float* Bb = Bm + (long)batch * sBb;
    float*       Cb;
    const float* Rb;
    if (kslices > 1) {
        Cb = C + (long)ksl * sPart + (long)batch * sCb;
        Rb = nullptr;
    } else {
        Cb = C + (long)batch * sCb;
        Rb = Res ? (Res + (long)batch * sCb) : nullptr;
    }

    int row0 = blockIdx.y * 64;
    int col0 = blockIdx.x * 128;
    int tid = threadIdx.x;
    int lane = tid & 31, warp = tid >> 5;
    int wm = warp >> 2, wn = warp & 3;
    int g = lane >> 2, tg = lane & 3;

    int ar = tid >> 3, ak = (tid & 7) * 4;
    int bkNN = tid >> 5, bnNN = (tid & 31) * 4;
    int bnTB = tid >> 3, bkTB = (tid & 7) * 4;

    float4 pa[2], pb[4];

    auto loadA = [&](int k0) {
        #pragma unroll
        for (int p = 0; p < 2; p++) {
            int gr = row0 + ar + p * 32, gk = k0 + ak;
            float4 v = make_float4(0.f, 0.f, 0.f, 0.f);
            if (gr < Mr) {
                if (gk + 3 < Khi) {
                    v = *(const float4*)&Ab[(long)gr * lda + gk];
                    if (LNA) {
                        float mu = __ldg(&muA[gr]);
                        float rs = __ldg(&rsA[gr]);
                        float4 gg = *(const float4*)&lngA[gk];
                        float4 bb = *(const float4*)&lnbA[gk];
                        v.x = (v.x - mu) * rs * gg.x + bb.x;
                        v.y = (v.y - mu) * rs * gg.y + bb.y;
                        v.z = (v.z - mu) * rs * gg.z + bb.z;
                        v.w = (v.w - mu) * rs * gg.w + bb.w;
                    }
                } else {
                    if (gk + 0 < Khi) v.x = Ab[(long)gr * lda + gk + 0];
                    if (gk + 1 < Khi) v.y = Ab[(long)gr * lda + gk + 1];
                    if (gk + 2 < Khi) v.z = Ab[(long)gr * lda + gk + 2];
                    if (gk + 3 < Khi) v.w = Ab[(long)gr * lda + gk + 3];
                }
            }
            pa[p] = v;
        }
    };
    auto loadB = [&](int k0) {
        if (TB) {
            #pragma unroll
            for (int p = 0; p < 4; p++) {
                int gn = col0 + bnTB + p * 32, gk = k0 + bkTB;
                float4 v = make_float4(0.f, 0.f, 0.f, 0.f);
                if (gn < Nc) {
                    if (gk + 3 < Khi) v = *(const float4*)&Bb[(long)gn * ldb + gk];
                    else {
                        if (gk + 0 < Khi) v.x = Bb[(long)gn * ldb + gk + 0];
                        if (gk + 1 < Khi) v.y = Bb[(long)gn * ldb + gk + 1];
                        if (gk + 2 < Khi) v.z = Bb[(long)gn * ldb + gk + 2];
                        if (gk + 3 < Khi) v.w = Bb[(long)gn * ldb + gk + 3];
                    }
                }
                pb[p] = v;
            }
        } else {
            #pragma unroll
            for (int p = 0; p < 4; p++) {
                int gk = k0 + bkNN + p * 8, gn = col0 + bnNN;
                float4 v = make_float4(0.f, 0.f, 0.f, 0.f);
                if (gk < Khi) {
                    if (gn + 3 < Nc) v = *(const float4*)&Bb[(long)gk * ldb + gn];
                    else {
                        if (gn + 0 < Nc) v.x = Bb[(long)gk * ldb + gn + 0];
                        if (gn + 1 < Nc) v.y = Bb[(long)gk * ldb + gn + 1];
                        if (gn + 2 < Nc) v.z = Bb[(long)gk * ldb + gn + 2];
                        if (gn + 3 < Nc) v.w = Bb[(long)gk * ldb + gn + 3];
                    }
                }
                pb[p] = v;
            }
        }
    };
    auto storeTiles = [&](int st) {
        char* sb = smem_c + st * STAGE_B;
        #pragma unroll
        for (int p = 0; p < 2; p++) {
            int r = ar + p * 32;
            float vv[4] = {pa[p].x, pa[p].y, pa[p].z, pa[p].w};
            unsigned short h[4], l[4];
            #pragma unroll
            for (int j = 0; j < 4; j++) split_bf16(vv[j], h[j], l[j]);
            uint2 ph = make_uint2(((unsigned)h[1] << 16) | h[0], ((unsigned)h[3] << 16) | h[2]);
            uint2 pl = make_uint2(((unsigned)l[1] << 16) | l[0], ((unsigned)l[3] << 16) | l[2]);
            *(uint2*)(sb + r * A_PITCH_B + ak * 2)          = ph;
            *(uint2*)(sb + AL_OFF + r * A_PITCH_B + ak * 2) = pl;
        }
        if (TB) {
            #pragma unroll
            for (int p = 0; p < 4; p++) {
                int n = bnTB + p * 32;
                float vv[4] = {pb[p].x, pb[p].y, pb[p].z, pb[p].w};
                unsigned short h[4], l[4];
                #pragma unroll
                for (int j = 0; j < 4; j++) split_bf16(vv[j], h[j], l[j]);
                uint2 ph = make_uint2(((unsigned)h[1] << 16) | h[0], ((unsigned)h[3] << 16) | h[2]);
                uint2 pl = make_uint2(((unsigned)l[1] << 16) | l[0], ((unsigned)l[3] << 16) | l[2]);
                *(uint2*)(sb + BH_OFF + n * BTB_PITCH_B + bkTB * 2) = ph;
                *(uint2*)(sb + BL_OFF + n * BTB_PITCH_B + bkTB * 2) = pl;
            }
        } else {
            #pragma unroll
            for (int p = 0; p < 4; p++) {
                int k = bkNN + p * 8;
                float vv[4] = {pb[p].x, pb[p].y, pb[p].z, pb[p].w};
                unsigned short h[4], l[4];
                #pragma unroll
                for (int j = 0; j < 4; j++) split_bf16(vv[j], h[j], l[j]);
                uint2 ph = make_uint2(((unsigned)h[1] << 16) | h[0], ((unsigned)h[3] << 16) | h[2]);
                uint2 pl = make_uint2(((unsigned)l[1] << 16) | l[0], ((unsigned)l[3] << 16) | l[2]);
                *(uint2*)(sb + BH_OFF + k * BNN_PITCH_B + bnNN * 2) = ph;
                *(uint2*)(sb + BL_OFF + k * BNN_PITCH_B + bnNN * 2) = pl;
            }
        }
    };

    float acc[2][4][4];
    #pragma unroll
    for (int im = 0; im < 2; im++)
        #pragma unroll
        for (int jn = 0; jn < 4; jn++)
            #pragma unroll
            for (int c = 0; c < 4; c++) acc[im][jn][c] = 0.f;

    int nch = (Khi - Klo + 31) / 32;
    int stage = 0;

    loadA(Klo); loadB(Klo);
    storeTiles(0);
    __syncthreads();

    for (int c = 0; c < nch; c++) {
        if (c + 1 < nch) { loadA(Klo + (c + 1) * 32); loadB(Klo + (c + 1) * 32); }

        unsigned stb = sbase + stage * STAGE_B;
        #pragma unroll
        for (int ks2 = 0; ks2 < 2; ks2++) {
            int ksb = ks2 * 32;
            unsigned ah[2][4], al_[2][4];
            #pragma unroll
            for (int im = 0; im < 2; im++) {
                unsigned aaddr = stb
                    + (unsigned)((wm * 32 + im * 16 + (lane & 15)) * A_PITCH_B
                                 + ((lane >> 4) * 16) + ksb);
                LDSM4(ah[im][0], ah[im][1], ah[im][2], ah[im][3], aaddr);
                LDSM4(al_[im][0], al_[im][1], al_[im][2], al_[im][3], aaddr + AL_OFF);
            }
            unsigned bh[4][2], bl_[4][2];
            #pragma unroll
            for (int pr = 0; pr < 2; pr++) {
                int nb2 = wn * 32 + pr * 16;
                unsigned baddr;
                if (TB) {
                    baddr = stb + BH_OFF
                        + (unsigned)((nb2 + ((lane >> 4) << 3) + (lane & 7)) * BTB_PITCH_B
                                     + (((lane >> 3) & 1) * 16) + ksb);
                } else {
                    baddr = stb + BH_OFF
                        + (unsigned)((ks2 * 16 + ((lane >> 3) & 1) * 8 + (lane & 7)) * BNN_PITCH_B
                                     + (nb2 + (lane >> 4) * 8) * 2);
                }
                unsigned r0, r1, r2, r3;
                if (TB) { LDSM4(r0, r1, r2, r3, baddr); }
                else    { LDSM4T(r0, r1, r2, r3, baddr); }
                bh[2*pr][0] = r0; bh[2*pr][1] = r1; bh[2*pr+1][0] = r2; bh[2*pr+1][1] = r3;
                unsigned laddr = baddr + (BL_OFF - BH_OFF);
                if (TB) { LDSM4(r0, r1, r2, r3, laddr); }
                else    { LDSM4T(r0, r1, r2, r3, laddr); }
                bl_[2*pr][0] = r0; bl_[2*pr][1] = r1; bl_[2*pr+1][0] = r2; bl_[2*pr+1][1] = r3;
            }
            #pragma unroll
            for (int im = 0; im < 2; im++)
                #pragma unroll
                for (int jn = 0; jn < 4; jn++) {
                    MMA_BF16(acc[im][jn], ah[im], bl_[jn]);
                    MMA_BF16(acc[im][jn], al_[im], bh[jn]);
                    MMA_BF16(acc[im][jn], ah[im], bh[jn]);
                }
        }

        if (c + 1 < nch) {
            storeTiles(stage ^ 1);
            __syncthreads();
            stage ^= 1;
        }
    }

    // ---- epilogue
    float st1[2][2], st2[2][2];
    if (STATS) {
        #pragma unroll
        for (int im = 0; im < 2; im++)
            #pragma unroll
            for (int hh = 0; hh < 2; hh++) { st1[im][hh] = 0.f; st2[im][hh] = 0.f; }
    }
    #pragma unroll
    for (int im = 0; im < 2; im++) {
        #pragma unroll
        for (int jn = 0; jn < 4; jn++) {
            int r0 = row0 + wm * 32 + im * 16 + g;
            int c0 = col0 + wn * 32 + jn * 8 + 2 * tg;
            #pragma unroll
            for (int half = 0; half < 2; half++) {
                int gr = r0 + half * 8;
                if (gr >= Mr) continue;
                #pragma unroll
                for (int cc = 0; cc < 2; cc++) {
                    int gn = c0 + cc;
                    if (gn >= Nc) continue;
                    float v = acc[im][jn][half * 2 + cc] * alpha;
                    if (kslices == 1) {
                        if (bias) v += bias[gn];
                        if (Rb)   v += Rb[(long)gr * ldc + gn];
                        if (DOGELU) v = gelu_tanh(v);
                    }
                    if (STATS) { st1[im][half] += v; st2[im][half] += v * v; }
                    Cb[(long)gr * ldc + gn] = v;
                }
            }
        }
    }
    if (STATS) {
        __syncthreads();   // done with mainloop smem
        float* s1 = (float*)smem_c;        // [4][64]
        float* s2 = s1 + 256;
        #pragma unroll
        for (int im = 0; im < 2; im++)
            #pragma unroll
            for (int hh = 0; hh < 2; hh++) {
                float x1 = st1[im][hh], x2 = st2[im][hh];
                x1 += __shfl_xor_sync(0xffffffffu, x1, 1);
                x1 += __shfl_xor_sync(0xffffffffu, x1, 2);
                x2 += __shfl_xor_sync(0xffffffffu, x2, 1);
                x2 += __shfl_xor_sync(0xffffffffu, x2, 2);
                if (tg == 0) {
                    int lr = wm * 32 + im * 16 + g + hh * 8;
                    s1[wn * 64 + lr] = x1;
                    s2[wn * 64 + lr] = x2;
                }
            }
        __syncthreads();
        if (tid < 64) {
            float t1 = s1[tid] + s1[64 + tid] + s1[128 + tid] + s1[192 + tid];
            float t2 = s2[tid] + s2[64 + tid] + s2[128 + tid] + s2[192 + tid];
            float mu = t1 * (1.f / 128.f);
            float var = t2 * (1.f / 128.f) - mu * mu;
            muO[row0 + tid] = mu;
            rsO[row0 + tid] = rsqrtf(var + LNEPS);
        }
    }
}

// ---------------- split-K reduce + LN stats (one row per block) ----------------
__global__ void reduce_stats_k(const float* __restrict__ part, long sstride, int ns,
                               const float* __restrict__ bias, const float* __restrict__ res,
                               float* __restrict__ out,
                               float* __restrict__ mu, float* __restrict__ rstd)
{
    long row = blockIdx.x;
    int d = threadIdx.x;   // 128
    long idx = row * DMODEL + d;
    float s = 0.f;
    for (int k = 0; k < ns; k++) s += part[(long)k * sstride + idx];
    s += bias[d];
    if (res) s += res[idx];
    out[idx] = s;
    __shared__ float r1[4], r2[4];
    float v1 = s, v2 = s * s;
    #pragma unroll
    for (int o = 16; o > 0; o >>= 1) {
        v1 += __shfl_xor_sync(0xffffffffu, v1, o);
        v2 += __shfl_xor_sync(0xffffffffu, v2, o);
    }
    if ((d & 31) == 0) { r1[d >> 5] = v1; r2[d >> 5] = v2; }
    __syncthreads();
    if (d == 0) {
        float t1 = r1[0] + r1[1] + r1[2] + r1[3];
        float t2 = r2[0] + r2[1] + r2[2] + r2[3];
        float m = t1 * (1.f / 128.f);
        float var = t2 * (1.f / 128.f) - m * m;
        mu[row] = m;
        rstd[row] = rsqrtf(var + LNEPS);
    }
}

// ---------------- final LN + mean pool fused ----------------
__global__ void feats_k(const float* __restrict__ h, const float* __restrict__ mu,
                        const float* __restrict__ rstd,
                        const float* __restrict__ g, const float* __restrict__ b,
                        float* __restrict__ feats)
{
    int bb = blockIdx.x, d = threadIdx.x;
    float gd = g[d], bd = b[d];
    float s = 0.f;
    for (int n = 0; n < NTOK; n++) {
        long row = (long)bb * NTOK + n;
        s += (h[row * DMODEL + d] - mu[row]) * rstd[row] * gd + bd;
    }
    feats[bb * DMODEL + d] = s * (1.f / 196.f);
}

// ---------------- softmax over 196 ----------------
__global__ void softmax196_k(float* __restrict__ att)
{
    long row = blockIdx.x;
    int t = threadIdx.x;
    float* a = att + row * NTOK;
    float v = (t < NTOK) ? a[t] : -3.4e38f;
    __shared__ float red[8];
    float m = v;
    #pragma unroll
    for (int o = 16; o > 0; o >>= 1) m = fmaxf(m, __shfl_xor_sync(0xffffffffu, m, o));
    if ((t & 31) == 0) red[t >> 5] = m;
    __syncthreads();
    m = red[0];
    #pragma unroll
    for (int i = 1; i < 8; i++) m = fmaxf(m, red[i]);
    float e = (t < NTOK) ? expf(v - m) : 0.f;
    __syncthreads();
    float s = e;
    #pragma unroll
    for (int o = 16; o > 0; o >>= 1) s += __shfl_xor_sync(0xffffffffu, s, o);
    if ((t & 31) == 0) red[t >> 5] = s;
    __syncthreads();
    s = red[0];
    #pragma unroll
    for (int i = 1; i < 8; i++) s += red[i];
    if (t < NTOK) a[t] = e / s;
}

// ---------------- top-32: register-resident incremental argmax ----------------
__global__ void __launch_bounds__(256) topk_k(const float* __restrict__ msim,
                       float* __restrict__ mvals, int* __restrict__ midx)
{
    long row = blockIdx.x;
    int tid = threadIdx.x;
    int lane = tid & 31, wid = tid >> 5;
    const float* src = msim + row * MKEYS;

    float v[32];
    const float4* s4 = (const float4*)(src + tid * 32);
    #pragma unroll
    for (int i = 0; i < 8; i++) {
        float4 t = s4[i];
        v[i*4+0] = t.x; v[i*4+1] = t.y; v[i*4+2] = t.z; v[i*4+3] = t.w;
    }

    unsigned long long p = 0ull;
    #pragma unroll
    for (int i = 0; i < 32; i++) {
        unsigned u = __float_as_uint(v[i]);
        u = (u & 0x80000000u) ? ~u : (u | 0x80000000u);
        unsigned long long key = ((unsigned long long)u << 32) | (unsigned)(MKEYS - 1 - (tid * 32 + i));
        if (key > p) p = key;
    }

    __shared__ unsigned long long wmax[2][8];

    for (int it = 0; it < TOPK; it++) {
        unsigned long long q = p;
        #pragma unroll
        for (int o = 16; o > 0; o >>= 1) {
            unsigned long long other = __shfl_xor_sync(0xffffffffu, q, o);
            if (other > q) q = other;
        }
        if (lane == 0) wmax[it & 1][wid] = q;
        __syncthreads();
        unsigned long long best = wmax[it & 1][0];
        #pragma unroll
        for (int w = 1; w < 8; w++) {
            unsigned long long o2 = wmax[it & 1][w];
            if (o2 > best) best = o2;
        }
        int gidx = MKEYS - 1 - (int)(best & 0xffffffffu);
        if (tid == (gidx >> 5)) {
            int sub = gidx & 31;
            float bv = 0.f;
            #pragma unroll
            for (int i = 0; i < 32; i++)
                if (i == sub) { bv = v[i]; v[i] = -3.4e38f; }
            mvals[row * TOPK + it] = bv;
            midx [row * TOPK + it] = gidx;
            unsigned long long np = 0ull;
            #pragma unroll
            for (int i = 0; i < 32; i++) {
                unsigned u = __float_as_uint(v[i]);
                u = (u & 0x80000000u) ? ~u : (u | 0x80000000u);
                unsigned long long key = ((unsigned long long)u << 32) | (unsigned)(MKEYS - 1 - (tid * 32 + i));
                if (key > np) np = key;
            }
            p = np;
        }
    }
}

// ---------------- kNN combine ----------------
__global__ void knn_combine_k(const float* __restrict__ att,
                              const float* __restrict__ mvals, const int* __restrict__ midx,
                              const float* __restrict__ qkv, const float* __restrict__ knn_v,
                              float* __restrict__ out)
{
    long row = blockIdx.x;
    int b = (int)(row / NTOK);
    int tid = threadIdx.x;
    __shared__ float w[TOPK + NTOK];
    __shared__ int   sidx[TOPK];
    __shared__ float red[4];

    if (tid < TOPK) {
        w[tid]    = mvals[row * TOPK + tid];
        sidx[tid] = midx [row * TOPK + tid];
    }
    for (int m = tid; m < NTOK; m += 128) w[TOPK + m] = att[row * NTOK + m];
    __syncthreads();

    float l0 = w[tid];
    float l1 = (tid < (TOPK + NTOK - 128)) ? w[tid + 128] : -3.4e38f;
    float m = fmaxf(l0, l1);
    #pragma unroll
    for (int o = 16; o > 0; o >>= 1) m = fmaxf(m, __shfl_xor_sync(0xffffffffu, m, o));
    if ((tid & 31) == 0) red[tid >> 5] = m;
    __syncthreads();
    m = fmaxf(fmaxf(red[0], red[1]), fmaxf(red[2], red[3]));
    float e0 = expf(l0 - m);
    float e1 = (tid < (TOPK + NTOK - 128)) ? expf(l1 - m) : 0.f;
    float s = e0 + e1;
    __syncthreads();
    #pragma unroll
    for (int o = 16; o > 0; o >>= 1) s += __shfl_xor_sync(0xffffffffu, s, o);
    if ((tid & 31) == 0) red[tid >> 5] = s;
    __syncthreads();
    s = red[0] + red[1] + red[2] + red[3];
    float inv = 1.f / s;
    w[tid] = e0 * inv;
    if (tid < (TOPK + NTOK - 128)) w[tid + 128] = e1 * inv;
    __syncthreads();

    float acc = 0.f;
    const float* kv = knn_v + (long)b * MKEYS * DMODEL;
    #pragma unroll 4
    for (int j = 0; j < TOPK; j++)
        acc += w[j] * kv[(long)sidx[j] * DMODEL + tid];
    const float* vbase = qkv + ((long)b * NTOK) * 384 + 256;
    for (int mm = 0; mm < NTOK; mm++)
        acc += w[TOPK + mm] * vbase[(long)mm * 384 + tid];
    out[row * DMODEL + tid] = acc;
}

// ---------------- launch ----------------
extern "C" void kernel_launch(void* const* d_in, const int* in_sizes, int n_in,
                              void* d_out, int out_size)
{
    const float* x       = (const float*)d_in[0];
    const float* patch_w = (const float*)d_in[1];
    const float* patch_b = (const float*)d_in[2];
    const float* ln1_g   = (const float*)d_in[3];
    const float* ln1_b   = (const float*)d_in[4];
    const float* qkv_w   = (const float*)d_in[5];
    const float* qkv_b   = (const float*)d_in[6];
    const float* out_w   = (const float*)d_in[7];
    const float* out_b   = (const float*)d_in[8];
    const float* ln2_g   = (const float*)d_in[9];
    const float* ln2_b   = (const float*)d_in[10];
    const float* ff1_w   = (const float*)d_in[11];
    const float* ff1_b   = (const float*)d_in[12];
    const float* ff2_w   = (const float*)d_in[13];
    const float* ff2_b   = (const float*)d_in[14];
    const float* lnf_g   = (const float*)d_in[15];
    const float* lnf_b   = (const float*)d_in[16];
    const float* knn_k   = (const float*)d_in[17];
    const float* knn_v   = (const float*)d_in[18];
    const float* head_w  = (const float*)d_in[19];
    const float* head_b  = (const float*)d_in[20];
    float* out = (float*)d_out;

    void* tp;
    cudaGetSymbolAddress(&tp, g_p);    float* pP    = (float*)tp;
    cudaGetSymbolAddress(&tp, g_h);    float* pH    = (float*)tp;
    cudaGetSymbolAddress(&tp, g_qkv);  float* pQKV  = (float*)tp;
    cudaGetSymbolAddress(&tp, g_att);  float* pATT  = (float*)tp;
    cudaGetSymbolAddress(&tp, g_msim); float* pMSIM = (float*)tp;
    cudaGetSymbolAddress(&tp, g_o);    float* pO    = (float*)tp;
    cudaGetSymbolAddress(&tp, g_ff);   float* pFF   = (float*)tp;
    cudaGetSymbolAddress(&tp, g_part); float* pPart = (float*)tp;
    cudaGetSymbolAddress(&tp, g_mv);   float* pMV   = (float*)tp;
    cudaGetSymbolAddress(&tp, g_mi);   int*   pMI   = (int*)tp;
    cudaGetSymbolAddress(&tp, g_feats);float* pFeat = (float*)tp;
    cudaGetSymbolAddress(&tp, g_mu);   float* pMu   = (float*)tp;
    cudaGetSymbolAddress(&tp, g_rs);   float* pRs   = (float*)tp;

    cudaFuncSetAttribute(mmabf_k<false,false,false,false>, cudaFuncAttributeMaxDynamicSharedMemorySize, SMEM2);
    cudaFuncSetAttribute(mmabf_k<true, false,false,false>, cudaFuncAttributeMaxDynamicSharedMemorySize, SMEM2);
    cudaFuncSetAttribute(mmabf_k<false,false,true ,false>, cudaFuncAttributeMaxDynamicSharedMemorySize, SMEM2);
    cudaFuncSetAttribute(mmabf_k<false,true ,true ,false>, cudaFuncAttributeMaxDynamicSharedMemorySize, SMEM2);
    cudaFuncSetAttribute(mmabf_k<false,false,false,true >, cudaFuncAttributeMaxDynamicSharedMemorySize, SMEM2);

    const long sPart = (long)ROWS * DMODEL;

    // patch embed: split-K 6 -> reduce + ln1 stats
    patchify_k<<<(int)(((long)ROWS * PDIM + 255) / 256), 256>>>(x, pP);
    mmabf_k<false,false,false,false><<<dim3(1, 98, 6), 256, SMEM2>>>(pP, patch_w, nullptr, nullptr, pPart,
        ROWS, DMODEL, PDIM, 0, PDIM, 0, DMODEL, 0, DMODEL, 1.f, 1, 6, sPart,
        nullptr, nullptr, nullptr, nullptr, nullptr, nullptr);
    reduce_stats_k<<<ROWS, 128>>>(pPart, sPart, 6, patch_b, nullptr, pH, pMu, pRs);

    for (int i = 0; i < DEPTH; i++) {
        // qkv with inline ln1
        mmabf_k<false,false,true,false><<<dim3(3, 98, 1), 256, SMEM2>>>(pH, qkv_w + (long)i * DMODEL * 3 * DMODEL,
            qkv_b + i * 3 * DMODEL, nullptr, pQKV,
            ROWS, 3 * DMODEL, DMODEL, 0, DMODEL, 0, 3 * DMODEL, 0, 3 * DMODEL, 1.f, 1, 1, 0,
            pMu, pRs, ln1_g + i * DMODEL, ln1_b + i * DMODEL, nullptr, nullptr);
        // sim = q @ k^T * scale
        mmabf_k<true,false,false,false><<<dim3(2, 4, BATCH), 256, SMEM2>>>(pQKV, pQKV + 128, nullptr, nullptr, pATT,
            NTOK, NTOK, DMODEL,
            (long)NTOK * 384, 384, (long)NTOK * 384, 384, (long)NTOK * NTOK, NTOK, SCALE, BATCH, 1, 0,
            nullptr, nullptr, nullptr, nullptr, nullptr, nullptr);

        if (i == KNN_LAYER) {
            mmabf_k<true,false,false,false><<<dim3(64, 4, BATCH), 256, SMEM2>>>(pQKV, knn_k, nullptr, nullptr, pMSIM,
                NTOK, MKEYS, DMODEL,
                (long)NTOK * 384, 384, (long)MKEYS * DMODEL, DMODEL, (long)NTOK * MKEYS, MKEYS, SCALE, BATCH, 1, 0,
                nullptr, nullptr, nullptr, nullptr, nullptr, nullptr);
            topk_k<<<ROWS, 256>>>(pMSIM, pMV, pMI);
            knn_combine_k<<<ROWS, 128>>>(pATT, pMV, pMI, pQKV, knn_v, pO);
        } else {
            softmax196_k<<<ROWS, 256>>>(pATT);
            mmabf_k<false,false,false,false><<<dim3(1, 4, BATCH), 256, SMEM2>>>(pATT, pQKV + 256, nullptr, nullptr, pO,
                NTOK, DMODEL, NTOK,
                (long)NTOK * NTOK, NTOK, (long)NTOK * 384, 384, (long)NTOK * DMODEL, DMODEL, 1.f, BATCH, 1, 0,
                nullptr, nullptr, nullptr, nullptr, nullptr, nullptr);
        }

        // h = h + o @ out_w + out_b ; epilogue emits ln2 stats
        mmabf_k<false,false,false,true><<<dim3(1, 98, 1), 256, SMEM2>>>(pO, out_w + (long)i * DMODEL * DMODEL,
            out_b + i * DMODEL, pH, pH,
            ROWS, DMODEL, DMODEL, 0, DMODEL, 0, DMODEL, 0, DMODEL, 1.f, 1, 1, 0,
            nullptr, nullptr, nullptr, nullptr, pMu, pRs);

        // ff1 + gelu with inline ln2
        mmabf_k<false,true,true,false><<<dim3(4, 98, 1), 256, SMEM2>>>(pH, ff1_w + (long)i * DMODEL * FFH,
            ff1_b + i * FFH, nullptr, pFF,
            ROWS, FFH, DMODEL, 0, DMODEL, 0, FFH, 0, FFH, 1.f, 1, 1, 0,
            pMu, pRs, ln2_g + i * DMODEL, ln2_b + i * DMODEL, nullptr, nullptr);
        // ff2: split-K 4, reduce adds bias + residual h, emits next ln1 stats
        mmabf_k<false,false,false,false><<<dim3(1, 98, 4), 256, SMEM2>>>(pFF, ff2_w + (long)i * FFH * DMODEL,
            nullptr, nullptr, pPart,
            ROWS, DMODEL, FFH, 0, FFH, 0, DMODEL, 0, DMODEL, 1.f, 1, 4, sPart,
            nullptr, nullptr, nullptr, nullptr, nullptr, nullptr);
        reduce_stats_k<<<ROWS, 128>>>(pPart, sPart, 4, ff2_b + i * DMODEL, pH, pH, pMu, pRs);
    }

    // final LN (stats from last reduce_stats) + mean pool, then head
    feats_k<<<BATCH, 128>>>(pH, pMu, pRs, lnf_g, lnf_b, pFeat);
    mmabf_k<false,false,false,false><<<dim3(8, 1, 1), 256, SMEM2>>>(pFeat, head_w, head_b, nullptr, out,
        BATCH, NCLS, DMODEL, 0, DMODEL, 0, NCLS, 0, NCLS, 1.f, 1, 1, 0,
        nullptr, nullptr, nullptr, nullptr, nullptr, nullptr);
}